// round 7
// baseline (speedup 1.0000x reference)
#include <cuda_runtime.h>
#include <cuda_fp16.h>
#include <math.h>

#define Bb 16
#define Nn 512
#define Hh 768
#define Gg 8
#define Dd 96
#define Ll 16

// ---------------- scratch: separate fp16 hi/lo planes ----------------------
__device__ __half g_xh[(size_t)8192 * 768];
__device__ __half g_xl[(size_t)8192 * 768];
__device__ __half g_wqh[768 * 768];
__device__ __half g_wkh[768 * 768];
__device__ __half g_wvh[768 * 1536];
__device__ __half g_wvl[768 * 1536];
__device__ __half g_woh[1536 * 768];
__device__ __half g_wol[1536 * 768];
__device__ __half g_Qh[(size_t)128 * 512 * 96];
__device__ __half g_Ql[(size_t)128 * 512 * 96];
__device__ __half g_Kh[(size_t)128 * 512 * 96];
__device__ __half g_Kl[(size_t)128 * 512 * 96];
__device__ __half g_Vh[(size_t)256 * 512 * 96];
__device__ __half g_Vl[(size_t)256 * 512 * 96];
__device__ float  g_S [(size_t)128 * 512 * 512];
__device__ __half g_Ah[(size_t)256 * 512 * 512];
__device__ __half g_Oh[(size_t)8192 * 1536];
__device__ __half g_Ol[(size_t)8192 * 1536];

// ---------------- helpers --------------------------------------------------
__device__ __forceinline__ unsigned sptr(const void* p) {
    return (unsigned)__cvta_generic_to_shared(p);
}
__device__ __forceinline__ void cpa16(unsigned s, const void* g) {
    asm volatile("cp.async.cg.shared.global [%0], [%1], 16;" :: "r"(s), "l"(g));
}
__device__ __forceinline__ void cpcommit() {
    asm volatile("cp.async.commit_group;");
}
template<int W> __device__ __forceinline__ void cpwait() {
    asm volatile("cp.async.wait_group %0;" :: "n"(W));
}
__device__ __forceinline__ void ldsm4(unsigned f[4], unsigned a) {
    asm volatile("ldmatrix.sync.aligned.m8n8.x4.shared.b16 {%0,%1,%2,%3}, [%4];"
                 : "=r"(f[0]), "=r"(f[1]), "=r"(f[2]), "=r"(f[3]) : "r"(a));
}
__device__ __forceinline__ void ldsm4t(unsigned& r0, unsigned& r1, unsigned& r2,
                                       unsigned& r3, unsigned a) {
    asm volatile("ldmatrix.sync.aligned.m8n8.x4.trans.shared.b16 {%0,%1,%2,%3}, [%4];"
                 : "=r"(r0), "=r"(r1), "=r"(r2), "=r"(r3) : "r"(a));
}
__device__ __forceinline__ void ldsm2t(unsigned& r0, unsigned& r1, unsigned a) {
    asm volatile("ldmatrix.sync.aligned.m8n8.x2.trans.shared.b16 {%0,%1}, [%2];"
                 : "=r"(r0), "=r"(r1) : "r"(a));
}
__device__ __forceinline__ void mmaf16(float c[4], const unsigned a[4],
                                       unsigned b0, unsigned b1) {
    asm volatile(
        "mma.sync.aligned.m16n8k16.row.col.f32.f16.f16.f32 "
        "{%0,%1,%2,%3}, {%4,%5,%6,%7}, {%8,%9}, {%0,%1,%2,%3};"
        : "+f"(c[0]), "+f"(c[1]), "+f"(c[2]), "+f"(c[3])
        : "r"(a[0]), "r"(a[1]), "r"(a[2]), "r"(a[3]), "r"(b0), "r"(b1));
}
__device__ __forceinline__ void hsplit(float v, __half& h, __half& l) {
    h = __float2half_rn(v);
    l = __float2half_rn(v - __half2float(h));
}

// ---------------- split inputs ---------------------------------------------
__global__ void __launch_bounds__(256) split2k(const float4* __restrict__ in,
                                               __half* __restrict__ oh,
                                               __half* __restrict__ ol, int n4) {
    int i = blockIdx.x * 256 + threadIdx.x;
    if (i >= n4) return;
    float4 v = in[i];
    __half h0, h1, h2, h3, l0, l1, l2, l3;
    hsplit(v.x, h0, l0); hsplit(v.y, h1, l1);
    hsplit(v.z, h2, l2); hsplit(v.w, h3, l3);
    ((__half2*)oh)[i * 2]     = __halves2half2(h0, h1);
    ((__half2*)oh)[i * 2 + 1] = __halves2half2(h2, h3);
    ((__half2*)ol)[i * 2]     = __halves2half2(l0, l1);
    ((__half2*)ol)[i * 2 + 1] = __halves2half2(l2, l3);
}
__global__ void __launch_bounds__(256) split1k(const float4* __restrict__ in,
                                               __half* __restrict__ oh, int n4) {
    int i = blockIdx.x * 256 + threadIdx.x;
    if (i >= n4) return;
    float4 v = in[i];
    ((__half2*)oh)[i * 2]     = __halves2half2(__float2half_rn(v.x), __float2half_rn(v.y));
    ((__half2*)oh)[i * 2 + 1] = __halves2half2(__float2half_rn(v.z), __float2half_rn(v.w));
}

// ---------------------------------------------------------------------------
// Generic C = A[MxK] @ B[KxN]. BM=128 BN=128 BK=32, 3-stage cp.async, 256 thr.
// TERMS==1: hi planes only, 1 mma; TERMS==3: dual planes, 3 mma.
// HEADS>0: split-store permuted into [b][head][n][96]; F32OUT: fp32 rowmajor.
// ---------------------------------------------------------------------------
#define ASTR 10240          // 128 rows * 80B  (40-half padded rows)
#define BSTR 8704           // 32 rows * 272B  (136-half padded rows)

template<int TERMS, int HEADS, bool BIAS, bool F32OUT>
__global__ void __launch_bounds__(256) gemm16(
    const __half* __restrict__ Agh, const __half* __restrict__ Agl,
    const __half* __restrict__ Bgh, const __half* __restrict__ Bgl,
    const float* __restrict__ bias,
    __half* __restrict__ outH, __half* __restrict__ outL,
    float* __restrict__ outF, int K, int N)
{
    extern __shared__ char smem[];
    char* p = smem;
    __half* sAh = (__half*)p; p += 3 * ASTR;
    __half* sAl = nullptr;
    if (TERMS == 3) { sAl = (__half*)p; p += 3 * ASTR; }
    __half* sBh = (__half*)p; p += 3 * BSTR;
    __half* sBl = nullptr;
    if (TERMS == 3) { sBl = (__half*)p; }

    const int tid = threadIdx.x;
    const int lane = tid & 31, warp = tid >> 5;
    const int wm = warp >> 2, wn = warp & 3;
    const int gid = lane >> 2, tig = lane & 3;
    const int m0 = blockIdx.y * 128, n0 = blockIdx.x * 128;

    const int aR = tid >> 1, aC = (tid & 1) * 16;
    const int bR = tid >> 3, bC = (tid & 7) * 16;

    const unsigned sAhb = sptr(sAh), sBhb = sptr(sBh);
    const unsigned sAlb = TERMS == 3 ? sptr(sAl) : 0;
    const unsigned sBlb = TERMS == 3 ? sptr(sBl) : 0;

    auto issue = [&](int kt, int s) {
        const int k0 = kt << 5;
        const __half* ga = Agh + (size_t)(m0 + aR) * K + k0 + aC;
        unsigned sa = sAhb + s * ASTR + aR * 80 + aC * 2;
        cpa16(sa, ga); cpa16(sa + 16, ga + 8);
        const __half* gb = Bgh + (size_t)(k0 + bR) * N + n0 + bC;
        unsigned sb = sBhb + s * BSTR + bR * 272 + bC * 2;
        cpa16(sb, gb); cpa16(sb + 16, gb + 8);
        if (TERMS == 3) {
            const __half* ga2 = Agl + (size_t)(m0 + aR) * K + k0 + aC;
            unsigned sa2 = sAlb + s * ASTR + aR * 80 + aC * 2;
            cpa16(sa2, ga2); cpa16(sa2 + 16, ga2 + 8);
            const __half* gb2 = Bgl + (size_t)(k0 + bR) * N + n0 + bC;
            unsigned sb2 = sBlb + s * BSTR + bR * 272 + bC * 2;
            cpa16(sb2, gb2); cpa16(sb2 + 16, gb2 + 8);
        }
        cpcommit();
    };

    float c[4][4][4];
#pragma unroll
    for (int i = 0; i < 4; i++)
#pragma unroll
        for (int j = 0; j < 4; j++)
#pragma unroll
            for (int q = 0; q < 4; q++) c[i][j][q] = 0.f;

    const unsigned aOff = (wm * 64 + (lane & 15)) * 80 + (lane >> 4) * 16;
    const unsigned bOff = (lane & 15) * 272 + (wn * 32 + (lane >> 4) * 8) * 2;

    issue(0, 0); issue(1, 1);
    const int KT = K >> 5;

    for (int kt = 0; kt < KT; kt++) {
        cpwait<1>();
        __syncthreads();
        const int s = kt % 3;
        const unsigned aB = sAhb + s * ASTR + aOff;
        const unsigned bB = sBhb + s * BSTR + bOff;
        const unsigned aB2 = TERMS == 3 ? sAlb + s * ASTR + aOff : 0;
        const unsigned bB2 = TERMS == 3 ? sBlb + s * BSTR + bOff : 0;

#pragma unroll
        for (int k16 = 0; k16 < 2; k16++) {
            unsigned ah[4][4], al[4][4], bh[4][2], bl[4][2], t0, t1, t2, t3;
#pragma unroll
            for (int mf = 0; mf < 4; mf++) {
                ldsm4(ah[mf], aB + mf * 1280 + k16 * 32);
                if (TERMS == 3) ldsm4(al[mf], aB2 + mf * 1280 + k16 * 32);
            }
#pragma unroll
            for (int nf2 = 0; nf2 < 2; nf2++) {
                ldsm4t(t0, t1, t2, t3, bB + k16 * 4352 + nf2 * 32);
                bh[nf2 * 2][0] = t0; bh[nf2 * 2][1] = t1;
                bh[nf2 * 2 + 1][0] = t2; bh[nf2 * 2 + 1][1] = t3;
                if (TERMS == 3) {
                    ldsm4t(t0, t1, t2, t3, bB2 + k16 * 4352 + nf2 * 32);
                    bl[nf2 * 2][0] = t0; bl[nf2 * 2][1] = t1;
                    bl[nf2 * 2 + 1][0] = t2; bl[nf2 * 2 + 1][1] = t3;
                }
            }
#pragma unroll
            for (int mf = 0; mf < 4; mf++)
#pragma unroll
                for (int nf = 0; nf < 4; nf++) {
                    mmaf16(c[mf][nf], ah[mf], bh[nf][0], bh[nf][1]);
                    if (TERMS == 3) {
                        mmaf16(c[mf][nf], ah[mf], bl[nf][0], bl[nf][1]);
                        mmaf16(c[mf][nf], al[mf], bh[nf][0], bh[nf][1]);
                    }
                }
        }
        const int kn = kt + 2;
        if (kn < KT) issue(kn, kn % 3); else cpcommit();
    }

#pragma unroll
    for (int mf = 0; mf < 4; mf++)
#pragma unroll
        for (int q2 = 0; q2 < 2; q2++) {
            const int row = m0 + wm * 64 + mf * 16 + gid + q2 * 8;
            const int b = row >> 9, n = row & 511;
#pragma unroll
            for (int nf = 0; nf < 4; nf++) {
                const int col = n0 + wn * 32 + nf * 8 + tig * 2;
                float v0 = c[mf][nf][q2 * 2 + 0];
                float v1 = c[mf][nf][q2 * 2 + 1];
                if (BIAS) { v0 += bias[col]; v1 += bias[col + 1]; }
                if (F32OUT) {
                    *(float2*)(outF + (size_t)row * N + col) = make_float2(v0, v1);
                } else {
                    const int h = col / 96, d = col - h * 96;
                    const size_t idx = (((size_t)(b * HEADS + h)) * 512 + n) * 96 + d;
                    __half h0, h1, l0, l1;
                    hsplit(v0, h0, l0); hsplit(v1, h1, l1);
                    *(__half2*)(outH + idx) = __halves2half2(h0, h1);
                    *(__half2*)(outL + idx) = __halves2half2(l0, l1);
                }
            }
        }
}

// ---------------------------------------------------------------------------
// Scores: S[bg,n,m] = Q.K^T + sigma^2*eps.  Both operands [row][96] K-major,
// 3-term fp16 split.  BM=BN=128, BK=32, KT=3, 3 stages.
// ---------------------------------------------------------------------------
__global__ void __launch_bounds__(256) scores16(
    const float* __restrict__ eps, const float* __restrict__ sigma)
{
    extern __shared__ char smem[];
    char* p = smem;
    __half* sQh = (__half*)p; p += 3 * ASTR;
    __half* sQl = (__half*)p; p += 3 * ASTR;
    __half* sKh = (__half*)p; p += 3 * ASTR;
    __half* sKl = (__half*)p;

    const int tid = threadIdx.x;
    const int lane = tid & 31, warp = tid >> 5;
    const int wm = warp >> 2, wn = warp & 3;
    const int gid = lane >> 2, tig = lane & 3;
    const int bg = blockIdx.z;
    const int sn0 = blockIdx.y * 128, sm0 = blockIdx.x * 128;

    const __half* Qhp = g_Qh + (size_t)bg * Nn * Dd;
    const __half* Qlp = g_Ql + (size_t)bg * Nn * Dd;
    const __half* Khp = g_Kh + (size_t)bg * Nn * Dd;
    const __half* Klp = g_Kl + (size_t)bg * Nn * Dd;

    const int aR = tid >> 1, aC = (tid & 1) * 16;
    const unsigned bQh = sptr(sQh), bQl = sptr(sQl);
    const unsigned bKh = sptr(sKh), bKl = sptr(sKl);

    auto issue = [&](int kt, int s) {
        const int k0 = kt << 5;
        unsigned so = s * ASTR + aR * 80 + aC * 2;
        size_t go = (size_t)aR * 96 + k0 + aC;
        cpa16(bQh + so, Qhp + (size_t)sn0 * 96 + go);
        cpa16(bQh + so + 16, Qhp + (size_t)sn0 * 96 + go + 8);
        cpa16(bQl + so, Qlp + (size_t)sn0 * 96 + go);
        cpa16(bQl + so + 16, Qlp + (size_t)sn0 * 96 + go + 8);
        cpa16(bKh + so, Khp + (size_t)sm0 * 96 + go);
        cpa16(bKh + so + 16, Khp + (size_t)sm0 * 96 + go + 8);
        cpa16(bKl + so, Klp + (size_t)sm0 * 96 + go);
        cpa16(bKl + so + 16, Klp + (size_t)sm0 * 96 + go + 8);
        cpcommit();
    };

    float c[4][4][4];
#pragma unroll
    for (int i = 0; i < 4; i++)
#pragma unroll
        for (int j = 0; j < 4; j++)
#pragma unroll
            for (int q = 0; q < 4; q++) c[i][j][q] = 0.f;

    const unsigned aOff = (wm * 64 + (lane & 15)) * 80 + (lane >> 4) * 16;
    const unsigned kOff = (wn * 32 + (lane & 15)) * 80 + (lane >> 4) * 16;

    issue(0, 0); issue(1, 1);

    for (int kt = 0; kt < 3; kt++) {
        cpwait<1>();
        __syncthreads();
        const int s = kt;
        const unsigned aH = bQh + s * ASTR + aOff, aL = bQl + s * ASTR + aOff;
        const unsigned kH = bKh + s * ASTR + kOff, kL = bKl + s * ASTR + kOff;

#pragma unroll
        for (int k16 = 0; k16 < 2; k16++) {
            unsigned ah[4][4], al[4][4], f[4], bh[4][2], bl[4][2];
#pragma unroll
            for (int mf = 0; mf < 4; mf++) {
                ldsm4(ah[mf], aH + mf * 1280 + k16 * 32);
                ldsm4(al[mf], aL + mf * 1280 + k16 * 32);
            }
#pragma unroll
            for (int nf2 = 0; nf2 < 2; nf2++) {
                ldsm4(f, kH + nf2 * 1280 + k16 * 32);
                bh[nf2 * 2][0] = f[0]; bh[nf2 * 2][1] = f[2];
                bh[nf2 * 2 + 1][0] = f[1]; bh[nf2 * 2 + 1][1] = f[3];
                ldsm4(f, kL + nf2 * 1280 + k16 * 32);
                bl[nf2 * 2][0] = f[0]; bl[nf2 * 2][1] = f[2];
                bl[nf2 * 2 + 1][0] = f[1]; bl[nf2 * 2 + 1][1] = f[3];
            }
#pragma unroll
            for (int mf = 0; mf < 4; mf++)
#pragma unroll
                for (int nf = 0; nf < 4; nf++) {
                    mmaf16(c[mf][nf], ah[mf], bh[nf][0], bh[nf][1]);
                    mmaf16(c[mf][nf], ah[mf], bl[nf][0], bl[nf][1]);
                    mmaf16(c[mf][nf], al[mf], bh[nf][0], bh[nf][1]);
                }
        }
        const int kn = kt + 2;
        if (kn < 3) issue(kn, kn); else cpcommit();
    }

    float s2 = sigma[bg & 7];
    s2 = s2 * s2;
#pragma unroll
    for (int mf = 0; mf < 4; mf++)
#pragma unroll
        for (int q2 = 0; q2 < 2; q2++) {
            const int n = sn0 + wm * 64 + mf * 16 + gid + q2 * 8;
#pragma unroll
            for (int nf = 0; nf < 4; nf++) {
                const int m = sm0 + wn * 32 + nf * 8 + tig * 2;
                const size_t idx = ((size_t)bg * Nn + n) * Nn + m;
                float2 ev = *(const float2*)(eps + idx);
                *(float2*)(g_S + idx) = make_float2(
                    c[mf][nf][q2 * 2 + 0] + s2 * ev.x,
                    c[mf][nf][q2 * 2 + 1] + s2 * ev.y);
            }
        }
}

// ---------------------------------------------------------------------------
// Mix + mish + softmax.  A written as single fp16.
// ---------------------------------------------------------------------------
__global__ void __launch_bounds__(512) mix_softmax_kernel(
    const float* __restrict__ encoding_bias, const float* __restrict__ p)
{
    int bn = blockIdx.x;
    int b = bn >> 9, n = bn & 511;
    int tid = threadIdx.x;
    int lane = tid & 31, warp = tid >> 5;

    __shared__ float ps[128];
    __shared__ float red[16][17];
    __shared__ float rmax[16];
    __shared__ float rsum[16];

    if (tid < 128) ps[tid] = p[tid];
    __syncthreads();

    float s[8];
#pragma unroll
    for (int g = 0; g < 8; g++)
        s[g] = g_S[(((size_t)(b * 8 + g)) * 512 + n) * 512 + tid];
    float bias = encoding_bias[((size_t)bn) * 512 + tid];
    const float scale = 0.03608439182435161f;

    float vals[16];
#pragma unroll
    for (int l = 0; l < 16; l++) {
        float t = 0.f;
#pragma unroll
        for (int g = 0; g < 8; g++) t = fmaf(s[g], ps[g * 16 + l], t);
        float e = __expf(fminf(t, 15.f));
        float num = e * (e + 2.f);
        float mish = t * (num / (num + 2.f));
        vals[l] = mish * scale + bias;
    }

#pragma unroll
    for (int l = 0; l < 16; l++) {
        float v = vals[l];
#pragma unroll
        for (int o = 16; o > 0; o >>= 1)
            v = fmaxf(v, __shfl_xor_sync(0xffffffffu, v, o));
        if (lane == 0) red[l][warp] = v;
    }
    __syncthreads();
    {
        float v = (lane < 16) ? red[warp][lane] : -3.0e38f;
#pragma unroll
        for (int o = 8; o > 0; o >>= 1)
            v = fmaxf(v, __shfl_xor_sync(0xffffffffu, v, o));
        if (lane == 0) rmax[warp] = v;
    }
    __syncthreads();

#pragma unroll
    for (int l = 0; l < 16; l++) {
        vals[l] = __expf(vals[l] - rmax[l]);
        float v = vals[l];
#pragma unroll
        for (int o = 16; o > 0; o >>= 1)
            v += __shfl_xor_sync(0xffffffffu, v, o);
        if (lane == 0) red[l][warp] = v;
    }
    __syncthreads();
    {
        float v = (lane < 16) ? red[warp][lane] : 0.f;
#pragma unroll
        for (int o = 8; o > 0; o >>= 1)
            v += __shfl_xor_sync(0xffffffffu, v, o);
        if (lane == 0) rsum[warp] = v;
    }
    __syncthreads();

#pragma unroll
    for (int l = 0; l < 16; l++)
        g_Ah[(((size_t)(b * 16 + l)) * 512 + n) * 512 + tid] =
            __float2half_rn(vals[l] / rsum[l]);
}

// ---------------------------------------------------------------------------
// O = A @ V per (b,l).  A single fp16 [bl][n][m], V dual [bl][m][d].
// BM=128, BN=96, BK=32, KT=16, 2-term.  Warp tile 64x24.
// ---------------------------------------------------------------------------
#define VSTR 6656          // 32 rows * 208B (104-half padded rows)

__global__ void __launch_bounds__(256) outv16()
{
    extern __shared__ char smem[];
    char* p = smem;
    __half* sA = (__half*)p;  p += 3 * ASTR;
    __half* sVh = (__half*)p; p += 3 * VSTR;
    __half* sVl = (__half*)p;

    const int tid = threadIdx.x;
    const int lane = tid & 31, warp = tid >> 5;
    const int wm = warp >> 2, wn = warp & 3;
    const int gid = lane >> 2, tig = lane & 3;
    const int bl = blockIdx.y;
    const int n0 = blockIdx.x * 128;

    const __half* Ap = g_Ah + (size_t)bl * Nn * Nn;
    const __half* Vhp = g_Vh + (size_t)bl * Nn * Dd;
    const __half* Vlp = g_Vl + (size_t)bl * Nn * Dd;

    const int aR = tid >> 1, aC = (tid & 1) * 16;
    const int vR = tid / 6, vC = (tid % 6) * 16;
    const bool vAct = tid < 192;

    const unsigned bA = sptr(sA), bVh = sptr(sVh), bVl = sptr(sVl);

    auto issue = [&](int kt, int s) {
        const int k0 = kt << 5;
        unsigned sa = bA + s * ASTR + aR * 80 + aC * 2;
        const __half* ga = Ap + (size_t)(n0 + aR) * 512 + k0 + aC;
        cpa16(sa, ga); cpa16(sa + 16, ga + 8);
        if (vAct) {
            unsigned sv = s * VSTR + vR * 208 + vC * 2;
            const __half* gv = Vhp + (size_t)(k0 + vR) * 96 + vC;
            cpa16(bVh + sv, gv); cpa16(bVh + sv + 16, gv + 8);
            const __half* gv2 = Vlp + (size_t)(k0 + vR) * 96 + vC;
            cpa16(bVl + sv, gv2); cpa16(bVl + sv + 16, gv2 + 8);
        }
        cpcommit();
    };

    float c[4][3][4];
#pragma unroll
    for (int i = 0; i < 4; i++)
#pragma unroll
        for (int j = 0; j < 3; j++)
#pragma unroll
            for (int q = 0; q < 4; q++) c[i][j][q] = 0.f;

    const unsigned aOff = (wm * 64 + (lane & 15)) * 80 + (lane >> 4) * 16;
    const unsigned vOff = (lane & 15) * 208 + (wn * 24 + (lane >> 4) * 8) * 2;
    const unsigned vOff2 = (lane & 15) * 208 + (wn * 24 + 16) * 2;

    issue(0, 0); issue(1, 1);

    for (int kt = 0; kt < 16; kt++) {
        cpwait<1>();
        __syncthreads();
        const int s = kt % 3;
        const unsigned aB = bA + s * ASTR + aOff;
        const unsigned vH = bVh + s * VSTR, vL = bVl + s * VSTR;

#pragma unroll
        for (int k16 = 0; k16 < 2; k16++) {
            unsigned ah[4][4], bh[3][2], blr[3][2], t0, t1, t2, t3;
#pragma unroll
            for (int mf = 0; mf < 4; mf++)
                ldsm4(ah[mf], aB + mf * 1280 + k16 * 32);
            ldsm4t(t0, t1, t2, t3, vH + vOff + k16 * 3328);
            bh[0][0] = t0; bh[0][1] = t1; bh[1][0] = t2; bh[1][1] = t3;
            ldsm2t(t0, t1, vH + vOff2 + k16 * 3328);
            bh[2][0] = t0; bh[2][1] = t1;
            ldsm4t(t0, t1, t2, t3, vL + vOff + k16 * 3328);
            blr[0][0] = t0; blr[0][1] = t1; blr[1][0] = t2; blr[1][1] = t3;
            ldsm2t(t0, t1, vL + vOff2 + k16 * 3328);
            blr[2][0] = t0; blr[2][1] = t1;

#pragma unroll
            for (int mf = 0; mf < 4; mf++)
#pragma unroll
                for (int nf = 0; nf < 3; nf++) {
                    mmaf16(c[mf][nf], ah[mf], bh[nf][0], bh[nf][1]);
                    mmaf16(c[mf][nf], ah[mf], blr[nf][0], blr[nf][1]);
                }
        }
        const int kn = kt + 2;
        if (kn < 16) issue(kn, kn % 3); else cpcommit();
    }

    const int b = bl >> 4, l = bl & 15;
#pragma unroll
    for (int mf = 0; mf < 4; mf++)
#pragma unroll
        for (int q2 = 0; q2 < 2; q2++) {
            const int n = n0 + wm * 64 + mf * 16 + gid + q2 * 8;
#pragma unroll
            for (int nf = 0; nf < 3; nf++) {
                const int d = wn * 24 + nf * 8 + tig * 2;
                const size_t idx = ((size_t)(b * 512 + n)) * 1536 + l * 96 + d;
                __half h0, h1, l0, l1;
                hsplit(c[mf][nf][q2 * 2 + 0], h0, l0);
                hsplit(c[mf][nf][q2 * 2 + 1], h1, l1);
                *(__half2*)(g_Oh + idx) = __halves2half2(h0, h1);
                *(__half2*)(g_Ol + idx) = __halves2half2(l0, l1);
            }
        }
}

// ---------------------------------------------------------------------------
extern "C" void kernel_launch(void* const* d_in, const int* in_sizes, int n_in,
                              void* d_out, int out_size)
{
    const float* x     = (const float*)d_in[0];
    const float* ebias = (const float*)d_in[1];
    const float* eps   = (const float*)d_in[2];
    const float* Wq    = (const float*)d_in[3];
    const float* Wk    = (const float*)d_in[4];
    const float* Wv    = (const float*)d_in[5];
    const float* bv    = (const float*)d_in[6];
    const float* sigma = (const float*)d_in[7];
    const float* p     = (const float*)d_in[8];
    const float* Wout  = (const float*)d_in[9];
    float* out = (float*)d_out;

    __half *xh, *xl, *wqh, *wkh, *wvh, *wvl, *woh, *wol;
    __half *qh, *ql, *kh, *kl, *vh, *vl, *oh, *ol;
    cudaGetSymbolAddress((void**)&xh,  g_xh);
    cudaGetSymbolAddress((void**)&xl,  g_xl);
    cudaGetSymbolAddress((void**)&wqh, g_wqh);
    cudaGetSymbolAddress((void**)&wkh, g_wkh);
    cudaGetSymbolAddress((void**)&wvh, g_wvh);
    cudaGetSymbolAddress((void**)&wvl, g_wvl);
    cudaGetSymbolAddress((void**)&woh, g_woh);
    cudaGetSymbolAddress((void**)&wol, g_wol);
    cudaGetSymbolAddress((void**)&qh,  g_Qh);
    cudaGetSymbolAddress((void**)&ql,  g_Ql);
    cudaGetSymbolAddress((void**)&kh,  g_Kh);
    cudaGetSymbolAddress((void**)&kl,  g_Kl);
    cudaGetSymbolAddress((void**)&vh,  g_Vh);
    cudaGetSymbolAddress((void**)&vl,  g_Vl);
    cudaGetSymbolAddress((void**)&oh,  g_Oh);
    cudaGetSymbolAddress((void**)&ol,  g_Ol);

    const int SM1 = 3 * ASTR + 3 * BSTR;                 // 56832
    const int SM3 = 6 * ASTR + 6 * BSTR;                 // 113664
    const int SMS = 12 * ASTR;                           // 122880
    const int SMO = 3 * ASTR + 6 * VSTR;                 // 70656

    cudaFuncSetAttribute(gemm16<1, 8,  false, false>,
        cudaFuncAttributeMaxDynamicSharedMemorySize, SM1);
    cudaFuncSetAttribute(gemm16<3, 16, true,  false>,
        cudaFuncAttributeMaxDynamicSharedMemorySize, SM3);
    cudaFuncSetAttribute(gemm16<3, 0,  false, true>,
        cudaFuncAttributeMaxDynamicSharedMemorySize, SM3);
    cudaFuncSetAttribute(scores16,
        cudaFuncAttributeMaxDynamicSharedMemorySize, SMS);
    cudaFuncSetAttribute(outv16,
        cudaFuncAttributeMaxDynamicSharedMemorySize, SMO);

    // splits
    split2k<<<6144, 256>>>((const float4*)x, xh, xl, 1572864);
    split1k<<<576,  256>>>((const float4*)Wq, wqh, 147456);
    split1k<<<576,  256>>>((const float4*)Wk, wkh, 147456);
    split2k<<<1152, 256>>>((const float4*)Wv, wvh, wvl, 294912);
    split2k<<<1152, 256>>>((const float4*)Wout, woh, wol, 294912);

    // Q/K projections: single-plane fp16, split-stored outputs
    gemm16<1, 8, false, false><<<dim3(6, 64), 256, SM1>>>(
        xh, nullptr, wqh, nullptr, nullptr, qh, ql, nullptr, 768, 768);
    gemm16<1, 8, false, false><<<dim3(6, 64), 256, SM1>>>(
        xh, nullptr, wkh, nullptr, nullptr, kh, kl, nullptr, 768, 768);
    // V projection: 3-term
    gemm16<3, 16, true, false><<<dim3(12, 64), 256, SM3>>>(
        xh, xl, wvh, wvl, bv, vh, vl, nullptr, 768, 1536);

    // scores + sigma^2*eps (3-term on split Q/K)
    scores16<<<dim3(4, 4, 128), 256, SMS>>>(eps, sigma);

    // mix + mish + softmax -> A (fp16)
    mix_softmax_kernel<<<Bb * Nn, 512>>>(ebias, p);

    // O = A @ V (2-term)
    outv16<<<dim3(4, 256), 256, SMO>>>();

    // output projection: 3-term, fp32 out
    gemm16<3, 0, false, true><<<dim3(6, 64), 256, SM3>>>(
        oh, ol, woh, wol, nullptr, nullptr, nullptr, out, 1536, 768);
}

// round 9
// speedup vs baseline: 1.3357x; 1.3357x over previous
#include <cuda_runtime.h>
#include <cuda_fp16.h>
#include <math.h>

#define Bb 16
#define Nn 512
#define Dd 96

// ---------------- scratch -------------------------------------------------
__device__ __half g_xh [(size_t)8192 * 768];
__device__ __half g_wqh[768 * 768];
__device__ __half g_wkh[768 * 768];
__device__ __half g_wvh[(size_t)768 * 1536];
__device__ __half g_wvl[(size_t)768 * 1536];
__device__ __half g_woh[(size_t)1536 * 768];
__device__ __half g_wol[(size_t)1536 * 768];
__device__ __half g_Qh[(size_t)128 * 512 * 96];
__device__ __half g_Kh[(size_t)128 * 512 * 96];
__device__ __half g_Kl[(size_t)128 * 512 * 96];
__device__ __half g_Vh[(size_t)256 * 512 * 96];
__device__ __half g_Vl[(size_t)256 * 512 * 96];
__device__ float  g_S [(size_t)128 * 512 * 512];
__device__ __half g_Ah[(size_t)256 * 512 * 512];
__device__ __half g_Oh[(size_t)8192 * 1536];

// ---------------- helpers --------------------------------------------------
__device__ __forceinline__ unsigned sptr(const void* p) {
    return (unsigned)__cvta_generic_to_shared(p);
}
__device__ __forceinline__ void cpa16(unsigned s, const void* g) {
    asm volatile("cp.async.cg.shared.global [%0], [%1], 16;" :: "r"(s), "l"(g));
}
__device__ __forceinline__ void cpcommit() {
    asm volatile("cp.async.commit_group;");
}
template<int W> __device__ __forceinline__ void cpwait() {
    asm volatile("cp.async.wait_group %0;" :: "n"(W));
}
__device__ __forceinline__ void ldsm4(unsigned f[4], unsigned a) {
    asm volatile("ldmatrix.sync.aligned.m8n8.x4.shared.b16 {%0,%1,%2,%3}, [%4];"
                 : "=r"(f[0]), "=r"(f[1]), "=r"(f[2]), "=r"(f[3]) : "r"(a));
}
__device__ __forceinline__ void ldsm4t(unsigned& r0, unsigned& r1, unsigned& r2,
                                       unsigned& r3, unsigned a) {
    asm volatile("ldmatrix.sync.aligned.m8n8.x4.trans.shared.b16 {%0,%1,%2,%3}, [%4];"
                 : "=r"(r0), "=r"(r1), "=r"(r2), "=r"(r3) : "r"(a));
}
__device__ __forceinline__ void ldsm2t(unsigned& r0, unsigned& r1, unsigned a) {
    asm volatile("ldmatrix.sync.aligned.m8n8.x2.trans.shared.b16 {%0,%1}, [%2];"
                 : "=r"(r0), "=r"(r1) : "r"(a));
}
__device__ __forceinline__ void mmaf16(float c[4], const unsigned a[4],
                                       unsigned b0, unsigned b1) {
    asm volatile(
        "mma.sync.aligned.m16n8k16.row.col.f32.f16.f16.f32 "
        "{%0,%1,%2,%3}, {%4,%5,%6,%7}, {%8,%9}, {%0,%1,%2,%3};"
        : "+f"(c[0]), "+f"(c[1]), "+f"(c[2]), "+f"(c[3])
        : "r"(a[0]), "r"(a[1]), "r"(a[2]), "r"(a[3]), "r"(b0), "r"(b1));
}
__device__ __forceinline__ void hsplit(float v, __half& h, __half& l) {
    h = __float2half_rn(v);
    l = __float2half_rn(v - __half2float(h));
}

// ---------------- split inputs ---------------------------------------------
__global__ void __launch_bounds__(256) split2k(const float4* __restrict__ in,
                                               __half* __restrict__ oh,
                                               __half* __restrict__ ol, int n4) {
    int i = blockIdx.x * 256 + threadIdx.x;
    if (i >= n4) return;
    float4 v = in[i];
    __half h0, h1, h2, h3, l0, l1, l2, l3;
    hsplit(v.x, h0, l0); hsplit(v.y, h1, l1);
    hsplit(v.z, h2, l2); hsplit(v.w, h3, l3);
    ((__half2*)oh)[i * 2]     = __halves2half2(h0, h1);
    ((__half2*)oh)[i * 2 + 1] = __halves2half2(h2, h3);
    ((__half2*)ol)[i * 2]     = __halves2half2(l0, l1);
    ((__half2*)ol)[i * 2 + 1] = __halves2half2(l2, l3);
}
__global__ void __launch_bounds__(256) split1k(const float4* __restrict__ in,
                                               __half* __restrict__ oh, int n4) {
    int i = blockIdx.x * 256 + threadIdx.x;
    if (i >= n4) return;
    float4 v = in[i];
    ((__half2*)oh)[i * 2]     = __halves2half2(__float2half_rn(v.x), __float2half_rn(v.y));
    ((__half2*)oh)[i * 2 + 1] = __halves2half2(__float2half_rn(v.z), __float2half_rn(v.w));
}

// ---------------------------------------------------------------------------
// C = A[MxK] @ B[KxN]. BM=128 BN=128 BK=32, 3-stage cp.async, 256 thr.
// A single fp16 plane. TERMS==2: B dual planes (2 mma); TERMS==1: B single.
// HEADS>0: permuted store [b][head][n][96] (outL!=null => split); F32OUT: fp32.
// ---------------------------------------------------------------------------
#define ASTR 10240          // 128 rows * 80B
#define BSTR 8704           // 32 rows * 272B

template<int TERMS, int HEADS, bool BIAS, bool F32OUT>
__global__ void __launch_bounds__(256, 2) gemm16(
    const __half* __restrict__ Agh,
    const __half* __restrict__ Bgh, const __half* __restrict__ Bgl,
    const float* __restrict__ bias,
    __half* __restrict__ outH, __half* __restrict__ outL,
    float* __restrict__ outF, int K, int N)
{
    extern __shared__ char smem[];
    char* p = smem;
    __half* sA = (__half*)p;  p += 3 * ASTR;
    __half* sBh = (__half*)p; p += 3 * BSTR;
    __half* sBl = (TERMS == 2) ? (__half*)p : nullptr;

    const int tid = threadIdx.x;
    const int lane = tid & 31, warp = tid >> 5;
    const int wm = warp >> 2, wn = warp & 3;
    const int gid = lane >> 2, tig = lane & 3;
    const int m0 = blockIdx.y * 128, n0 = blockIdx.x * 128;

    const int aR = tid >> 1, aC = (tid & 1) * 16;
    const int bR = tid >> 3, bC = (tid & 7) * 16;

    const unsigned sAb = sptr(sA), sBhb = sptr(sBh);
    const unsigned sBlb = (TERMS == 2) ? sptr(sBl) : 0;

    auto issue = [&](int kt, int s) {
        const int k0 = kt << 5;
        const __half* ga = Agh + (size_t)(m0 + aR) * K + k0 + aC;
        unsigned sa = sAb + s * ASTR + aR * 80 + aC * 2;
        cpa16(sa, ga); cpa16(sa + 16, ga + 8);
        const __half* gb = Bgh + (size_t)(k0 + bR) * N + n0 + bC;
        unsigned sb = sBhb + s * BSTR + bR * 272 + bC * 2;
        cpa16(sb, gb); cpa16(sb + 16, gb + 8);
        if (TERMS == 2) {
            const __half* gb2 = Bgl + (size_t)(k0 + bR) * N + n0 + bC;
            unsigned sb2 = sBlb + s * BSTR + bR * 272 + bC * 2;
            cpa16(sb2, gb2); cpa16(sb2 + 16, gb2 + 8);
        }
        cpcommit();
    };

    float c[4][4][4];
#pragma unroll
    for (int i = 0; i < 4; i++)
#pragma unroll
        for (int j = 0; j < 4; j++)
#pragma unroll
            for (int q = 0; q < 4; q++) c[i][j][q] = 0.f;

    const unsigned aOff = (wm * 64 + (lane & 15)) * 80 + (lane >> 4) * 16;
    const unsigned bOff = (lane & 15) * 272 + (wn * 32 + (lane >> 4) * 8) * 2;

    issue(0, 0); issue(1, 1);
    const int KT = K >> 5;

    for (int kt = 0; kt < KT; kt++) {
        cpwait<1>();
        __syncthreads();
        const int s = kt % 3;
        const unsigned aB = sAb + s * ASTR + aOff;
        const unsigned bB = sBhb + s * BSTR + bOff;
        const unsigned bB2 = (TERMS == 2) ? sBlb + s * BSTR + bOff : 0;

#pragma unroll
        for (int k16 = 0; k16 < 2; k16++) {
            unsigned ah[4][4], bh[4][2], bl[4][2], t0, t1, t2, t3;
#pragma unroll
            for (int mf = 0; mf < 4; mf++)
                ldsm4(ah[mf], aB + mf * 1280 + k16 * 32);
#pragma unroll
            for (int nf2 = 0; nf2 < 2; nf2++) {
                ldsm4t(t0, t1, t2, t3, bB + k16 * 4352 + nf2 * 32);
                bh[nf2 * 2][0] = t0; bh[nf2 * 2][1] = t1;
                bh[nf2 * 2 + 1][0] = t2; bh[nf2 * 2 + 1][1] = t3;
                if (TERMS == 2) {
                    ldsm4t(t0, t1, t2, t3, bB2 + k16 * 4352 + nf2 * 32);
                    bl[nf2 * 2][0] = t0; bl[nf2 * 2][1] = t1;
                    bl[nf2 * 2 + 1][0] = t2; bl[nf2 * 2 + 1][1] = t3;
                }
            }
#pragma unroll
            for (int mf = 0; mf < 4; mf++)
#pragma unroll
                for (int nf = 0; nf < 4; nf++) {
                    mmaf16(c[mf][nf], ah[mf], bh[nf][0], bh[nf][1]);
                    if (TERMS == 2)
                        mmaf16(c[mf][nf], ah[mf], bl[nf][0], bl[nf][1]);
                }
        }
        const int kn = kt + 2;
        if (kn < KT) issue(kn, kn % 3); else cpcommit();
    }

#pragma unroll
    for (int mf = 0; mf < 4; mf++)
#pragma unroll
        for (int q2 = 0; q2 < 2; q2++) {
            const int row = m0 + wm * 64 + mf * 16 + gid + q2 * 8;
            const int b = row >> 9, n = row & 511;
#pragma unroll
            for (int nf = 0; nf < 4; nf++) {
                const int col = n0 + wn * 32 + nf * 8 + tig * 2;
                float v0 = c[mf][nf][q2 * 2 + 0];
                float v1 = c[mf][nf][q2 * 2 + 1];
                if (BIAS) { v0 += bias[col]; v1 += bias[col + 1]; }
                if (F32OUT) {
                    *(float2*)(outF + (size_t)row * N + col) = make_float2(v0, v1);
                } else {
                    const int h = col / 96, d = col - h * 96;
                    const size_t idx = (((size_t)(b * HEADS + h)) * 512 + n) * 96 + d;
                    if (outL) {
                        __half h0, h1, l0, l1;
                        hsplit(v0, h0, l0); hsplit(v1, h1, l1);
                        *(__half2*)(outH + idx) = __halves2half2(h0, h1);
                        *(__half2*)(outL + idx) = __halves2half2(l0, l1);
                    } else {
                        *(__half2*)(outH + idx) =
                            __halves2half2(__float2half_rn(v0), __float2half_rn(v1));
                    }
                }
            }
        }
}

// ---------------------------------------------------------------------------
// Scores: S = Q.K^T + sigma^2*eps.  Q single plane, K dual (2-term).
// BM=BN=128, BK=32, KT=3.
// ---------------------------------------------------------------------------
__global__ void __launch_bounds__(256, 2) scores16(
    const float* __restrict__ eps, const float* __restrict__ sigma)
{
    extern __shared__ char smem[];
    char* p = smem;
    __half* sQ  = (__half*)p; p += 3 * ASTR;
    __half* sKh = (__half*)p; p += 3 * ASTR;
    __half* sKl = (__half*)p;

    const int tid = threadIdx.x;
    const int lane = tid & 31, warp = tid >> 5;
    const int wm = warp >> 2, wn = warp & 3;
    const int gid = lane >> 2, tig = lane & 3;
    const int bg = blockIdx.z;
    const int sn0 = blockIdx.y * 128, sm0 = blockIdx.x * 128;

    const __half* Qp  = g_Qh + (size_t)bg * Nn * Dd;
    const __half* Khp = g_Kh + (size_t)bg * Nn * Dd;
    const __half* Klp = g_Kl + (size_t)bg * Nn * Dd;

    const int aR = tid >> 1, aC = (tid & 1) * 16;
    const unsigned bQ = sptr(sQ), bKh = sptr(sKh), bKl = sptr(sKl);

    auto issue = [&](int kt, int s) {
        const int k0 = kt << 5;
        unsigned so = s * ASTR + aR * 80 + aC * 2;
        size_t go = (size_t)aR * 96 + k0 + aC;
        cpa16(bQ + so, Qp + (size_t)sn0 * 96 + go);
        cpa16(bQ + so + 16, Qp + (size_t)sn0 * 96 + go + 8);
        cpa16(bKh + so, Khp + (size_t)sm0 * 96 + go);
        cpa16(bKh + so + 16, Khp + (size_t)sm0 * 96 + go + 8);
        cpa16(bKl + so, Klp + (size_t)sm0 * 96 + go);
        cpa16(bKl + so + 16, Klp + (size_t)sm0 * 96 + go + 8);
        cpcommit();
    };

    float c[4][4][4];
#pragma unroll
    for (int i = 0; i < 4; i++)
#pragma unroll
        for (int j = 0; j < 4; j++)
#pragma unroll
            for (int q = 0; q < 4; q++) c[i][j][q] = 0.f;

    const unsigned aOff = (wm * 64 + (lane & 15)) * 80 + (lane >> 4) * 16;
    const unsigned kOff = (wn * 32 + (lane & 15)) * 80 + (lane >> 4) * 16;

    issue(0, 0); issue(1, 1);

    for (int kt = 0; kt < 3; kt++) {
        cpwait<1>();
        __syncthreads();
        const unsigned aB = bQ + kt * ASTR + aOff;
        const unsigned kH = bKh + kt * ASTR + kOff;
        const unsigned kL = bKl + kt * ASTR + kOff;

#pragma unroll
        for (int k16 = 0; k16 < 2; k16++) {
            unsigned ah[4][4], f[4], bh[4][2], bl[4][2];
#pragma unroll
            for (int mf = 0; mf < 4; mf++)
                ldsm4(ah[mf], aB + mf * 1280 + k16 * 32);
#pragma unroll
            for (int nf2 = 0; nf2 < 2; nf2++) {
                ldsm4(f, kH + nf2 * 1280 + k16 * 32);
                bh[nf2 * 2][0] = f[0]; bh[nf2 * 2][1] = f[2];
                bh[nf2 * 2 + 1][0] = f[1]; bh[nf2 * 2 + 1][1] = f[3];
                ldsm4(f, kL + nf2 * 1280 + k16 * 32);
                bl[nf2 * 2][0] = f[0]; bl[nf2 * 2][1] = f[2];
                bl[nf2 * 2 + 1][0] = f[1]; bl[nf2 * 2 + 1][1] = f[3];
            }
#pragma unroll
            for (int mf = 0; mf < 4; mf++)
#pragma unroll
                for (int nf = 0; nf < 4; nf++) {
                    mmaf16(c[mf][nf], ah[mf], bh[nf][0], bh[nf][1]);
                    mmaf16(c[mf][nf], ah[mf], bl[nf][0], bl[nf][1]);
                }
        }
        const int kn = kt + 2;
        if (kn < 3) issue(kn, kn); else cpcommit();
    }

    float s2 = sigma[bg & 7];
    s2 = s2 * s2;
#pragma unroll
    for (int mf = 0; mf < 4; mf++)
#pragma unroll
        for (int q2 = 0; q2 < 2; q2++) {
            const int n = sn0 + wm * 64 + mf * 16 + gid + q2 * 8;
#pragma unroll
            for (int nf = 0; nf < 4; nf++) {
                const int m = sm0 + wn * 32 + nf * 8 + tig * 2;
                const size_t idx = ((size_t)bg * Nn + n) * Nn + m;
                float2 ev = *(const float2*)(eps + idx);
                *(float2*)(g_S + idx) = make_float2(
                    c[mf][nf][q2 * 2 + 0] + s2 * ev.x,
                    c[mf][nf][q2 * 2 + 1] + s2 * ev.y);
            }
        }
}

// ---------------------------------------------------------------------------
// Mix + mish + softmax -> A single fp16.
// ---------------------------------------------------------------------------
__global__ void __launch_bounds__(512) mix_softmax_kernel(
    const float* __restrict__ encoding_bias, const float* __restrict__ p)
{
    int bn = blockIdx.x;
    int b = bn >> 9, n = bn & 511;
    int tid = threadIdx.x;
    int lane = tid & 31, warp = tid >> 5;

    __shared__ float ps[128];
    __shared__ float red[16][17];
    __shared__ float rmax[16];
    __shared__ float rsum[16];

    if (tid < 128) ps[tid] = p[tid];
    __syncthreads();

    float s[8];
#pragma unroll
    for (int g = 0; g < 8; g++)
        s[g] = g_S[(((size_t)(b * 8 + g)) * 512 + n) * 512 + tid];
    float bias = encoding_bias[((size_t)bn) * 512 + tid];
    const float scale = 0.03608439182435161f;

    float vals[16];
#pragma unroll
    for (int l = 0; l < 16; l++) {
        float t = 0.f;
#pragma unroll
        for (int g = 0; g < 8; g++) t = fmaf(s[g], ps[g * 16 + l], t);
        float e = __expf(fminf(t, 15.f));
        float num = e * (e + 2.f);
        vals[l] = t * (num / (num + 2.f)) * scale + bias;
    }

#pragma unroll
    for (int l = 0; l < 16; l++) {
        float v = vals[l];
#pragma unroll
        for (int o = 16; o > 0; o >>= 1)
            v = fmaxf(v, __shfl_xor_sync(0xffffffffu, v, o));
        if (lane == 0) red[l][warp] = v;
    }
    __syncthreads();
    {
        float v = (lane < 16) ? red[warp][lane] : -3.0e38f;
#pragma unroll
        for (int o = 8; o > 0; o >>= 1)
            v = fmaxf(v, __shfl_xor_sync(0xffffffffu, v, o));
        if (lane == 0) rmax[warp] = v;
    }
    __syncthreads();
#pragma unroll
    for (int l = 0; l < 16; l++) {
        vals[l] = __expf(vals[l] - rmax[l]);
        float v = vals[l];
#pragma unroll
        for (int o = 16; o > 0; o >>= 1)
            v += __shfl_xor_sync(0xffffffffu, v, o);
        if (lane == 0) red[l][warp] = v;
    }
    __syncthreads();
    {
        float v = (lane < 16) ? red[warp][lane] : 0.f;
#pragma unroll
        for (int o = 8; o > 0; o >>= 1)
            v += __shfl_xor_sync(0xffffffffu, v, o);
        if (lane == 0) rsum[warp] = v;
    }
    __syncthreads();
#pragma unroll
    for (int l = 0; l < 16; l++)
        g_Ah[(((size_t)(b * 16 + l)) * 512 + n) * 512 + tid] =
            __float2half_rn(vals[l] / rsum[l]);
}

// ---------------------------------------------------------------------------
// O = A @ V per (b,l).  A single fp16, V dual (2-term).  O stored single fp16.
// BM=128, BN=96, BK=32, KT=16.
// ---------------------------------------------------------------------------
#define VSTR 6656          // 32 rows * 208B

__global__ void __launch_bounds__(256, 2) outv16()
{
    extern __shared__ char smem[];
    char* p = smem;
    __half* sA = (__half*)p;  p += 3 * ASTR;
    __half* sVh = (__half*)p; p += 3 * VSTR;
    __half* sVl = (__half*)p;

    const int tid = threadIdx.x;
    const int lane = tid & 31, warp = tid >> 5;
    const int wm = warp >> 2, wn = warp & 3;
    const int gid = lane >> 2, tig = lane & 3;
    const int bl = blockIdx.y;
    const int n0 = blockIdx.x * 128;

    const __half* Ap = g_Ah + (size_t)bl * Nn * Nn;
    const __half* Vhp = g_Vh + (size_t)bl * Nn * Dd;
    const __half* Vlp = g_Vl + (size_t)bl * Nn * Dd;

    const int aR = tid >> 1, aC = (tid & 1) * 16;
    const int vR = tid / 6, vC = (tid % 6) * 16;
    const bool vAct = tid < 192;

    const unsigned bA = sptr(sA), bVh = sptr(sVh), bVl = sptr(sVl);

    auto issue = [&](int kt, int s) {
        const int k0 = kt << 5;
        unsigned sa = bA + s * ASTR + aR * 80 + aC * 2;
        const __half* ga = Ap + (size_t)(n0 + aR) * 512 + k0 + aC;
        cpa16(sa, ga); cpa16(sa + 16, ga + 8);
        if (vAct) {
            unsigned sv = s * VSTR + vR * 208 + vC * 2;
            const __half* gv = Vhp + (size_t)(k0 + vR) * 96 + vC;
            cpa16(bVh + sv, gv); cpa16(bVh + sv + 16, gv + 8);
            const __half* gv2 = Vlp + (size_t)(k0 + vR) * 96 + vC;
            cpa16(bVl + sv, gv2); cpa16(bVl + sv + 16, gv2 + 8);
        }
        cpcommit();
    };

    float c[4][3][4];
#pragma unroll
    for (int i = 0; i < 4; i++)
#pragma unroll
        for (int j = 0; j < 3; j++)
#pragma unroll
            for (int q = 0; q < 4; q++) c[i][j][q] = 0.f;

    const unsigned aOff = (wm * 64 + (lane & 15)) * 80 + (lane >> 4) * 16;
    const unsigned vOff = (lane & 15) * 208 + (wn * 24 + (lane >> 4) * 8) * 2;
    const unsigned vOff2 = (lane & 15) * 208 + (wn * 24 + 16) * 2;

    issue(0, 0); issue(1, 1);

    for (int kt = 0; kt < 16; kt++) {
        cpwait<1>();
        __syncthreads();
        const int s = kt % 3;
        const unsigned aB = bA + s * ASTR + aOff;
        const unsigned vH = bVh + s * VSTR, vL = bVl + s * VSTR;

#pragma unroll
        for (int k16 = 0; k16 < 2; k16++) {
            unsigned ah[4][4], bh[3][2], blr[3][2], t0, t1, t2, t3;
#pragma unroll
            for (int mf = 0; mf < 4; mf++)
                ldsm4(ah[mf], aB + mf * 1280 + k16 * 32);
            ldsm4t(t0, t1, t2, t3, vH + vOff + k16 * 3328);
            bh[0][0] = t0; bh[0][1] = t1; bh[1][0] = t2; bh[1][1] = t3;
            ldsm2t(t0, t1, vH + vOff2 + k16 * 3328);
            bh[2][0] = t0; bh[2][1] = t1;
            ldsm4t(t0, t1, t2, t3, vL + vOff + k16 * 3328);
            blr[0][0] = t0; blr[0][1] = t1; blr[1][0] = t2; blr[1][1] = t3;
            ldsm2t(t0, t1, vL + vOff2 + k16 * 3328);
            blr[2][0] = t0; blr[2][1] = t1;

#pragma unroll
            for (int mf = 0; mf < 4; mf++)
#pragma unroll
                for (int nf = 0; nf < 3; nf++) {
                    mmaf16(c[mf][nf], ah[mf], bh[nf][0], bh[nf][1]);
                    mmaf16(c[mf][nf], ah[mf], blr[nf][0], blr[nf][1]);
                }
        }
        const int kn = kt + 2;
        if (kn < 16) issue(kn, kn % 3); else cpcommit();
    }

    const int b = bl >> 4, l = bl & 15;
#pragma unroll
    for (int mf = 0; mf < 4; mf++)
#pragma unroll
        for (int q2 = 0; q2 < 2; q2++) {
            const int n = n0 + wm * 64 + mf * 16 + gid + q2 * 8;
#pragma unroll
            for (int nf = 0; nf < 3; nf++) {
                const int d = wn * 24 + nf * 8 + tig * 2;
                const size_t idx = ((size_t)(b * 512 + n)) * 1536 + l * 96 + d;
                *(__half2*)(g_Oh + idx) =
                    __halves2half2(__float2half_rn(c[mf][nf][q2 * 2 + 0]),
                                   __float2half_rn(c[mf][nf][q2 * 2 + 1]));
            }
        }
}

// ---------------------------------------------------------------------------
extern "C" void kernel_launch(void* const* d_in, const int* in_sizes, int n_in,
                              void* d_out, int out_size)
{
    const float* x     = (const float*)d_in[0];
    const float* ebias = (const float*)d_in[1];
    const float* eps   = (const float*)d_in[2];
    const float* Wq    = (const float*)d_in[3];
    const float* Wk    = (const float*)d_in[4];
    const float* Wv    = (const float*)d_in[5];
    const float* bv    = (const float*)d_in[6];
    const float* sigma = (const float*)d_in[7];
    const float* p     = (const float*)d_in[8];
    const float* Wout  = (const float*)d_in[9];
    float* out = (float*)d_out;

    __half *xh, *wqh, *wkh, *wvh, *wvl, *woh, *wol;
    __half *qh, *kh, *kl, *vh, *vl, *ah, *oh;
    cudaGetSymbolAddress((void**)&xh,  g_xh);
    cudaGetSymbolAddress((void**)&wqh, g_wqh);
    cudaGetSymbolAddress((void**)&wkh, g_wkh);
    cudaGetSymbolAddress((void**)&wvh, g_wvh);
    cudaGetSymbolAddress((void**)&wvl, g_wvl);
    cudaGetSymbolAddress((void**)&woh, g_woh);
    cudaGetSymbolAddress((void**)&wol, g_wol);
    cudaGetSymbolAddress((void**)&qh,  g_Qh);
    cudaGetSymbolAddress((void**)&kh,  g_Kh);
    cudaGetSymbolAddress((void**)&kl,  g_Kl);
    cudaGetSymbolAddress((void**)&vh,  g_Vh);
    cudaGetSymbolAddress((void**)&vl,  g_Vl);
    cudaGetSymbolAddress((void**)&ah,  g_Ah);
    cudaGetSymbolAddress((void**)&oh,  g_Oh);

    const int SM_1 = 3 * ASTR + 3 * BSTR;   // 56832
    const int SM_2 = 3 * ASTR + 6 * BSTR;   // 82944
    const int SM_S = 9 * ASTR;              // 92160
    const int SM_O = 3 * ASTR + 6 * VSTR;   // 70656

    cudaFuncSetAttribute(gemm16<1, 8,  false, false>,
        cudaFuncAttributeMaxDynamicSharedMemorySize, SM_1);
    cudaFuncSetAttribute(gemm16<2, 16, true,  false>,
        cudaFuncAttributeMaxDynamicSharedMemorySize, SM_2);
    cudaFuncSetAttribute(gemm16<2, 0,  false, true>,
        cudaFuncAttributeMaxDynamicSharedMemorySize, SM_2);
    cudaFuncSetAttribute(scores16,
        cudaFuncAttributeMaxDynamicSharedMemorySize, SM_S);
    cudaFuncSetAttribute(outv16,
        cudaFuncAttributeMaxDynamicSharedMemorySize, SM_O);

    // splits (x: hi plane only — lo plane unused everywhere now)
    split1k<<<6144, 256>>>((const float4*)x, xh, 1572864);
    split1k<<<576,  256>>>((const float4*)Wq, wqh, 147456);
    split1k<<<576,  256>>>((const float4*)Wk, wkh, 147456);
    split2k<<<1152, 256>>>((const float4*)Wv, wvh, wvl, 294912);
    split2k<<<1152, 256>>>((const float4*)Wout, woh, wol, 294912);

    // Q proj: 1-term, single store.  K proj: 1-term, split store.
    gemm16<1, 8, false, false><<<dim3(6, 64), 256, SM_1>>>(
        xh, wqh, nullptr, nullptr, qh, nullptr, nullptr, 768, 768);
    gemm16<1, 8, false, false><<<dim3(6, 64), 256, SM_1>>>(
        xh, wkh, nullptr, nullptr, kh, kl, nullptr, 768, 768);
    // V proj: 2-term (xh . (wvh+wvl)) + bias, split store
    gemm16<2, 16, true, false><<<dim3(12, 64), 256, SM_2>>>(
        xh, wvh, wvl, bv, vh, vl, nullptr, 768, 1536);

    // scores: 2-term (qh . (kh+kl)) + sigma^2*eps
    scores16<<<dim3(4, 4, 128), 256, SM_S>>>(eps, sigma);

    // mix + mish + softmax -> A fp16
    mix_softmax_kernel<<<Bb * Nn, 512>>>(ebias, p);

    // O = A @ V (2-term), single store
    outv16<<<dim3(4, 256), 256, SM_O>>>();

    // out proj: 2-term (Oh . (woh+wol)) -> fp32 d_out
    gemm16<2, 0, false, true><<<dim3(6, 64), 256, SM_2>>>(
        oh, woh, wol, nullptr, nullptr, nullptr, out, 1536, 768);
}

// round 10
// speedup vs baseline: 1.4832x; 1.1105x over previous
#include <cuda_runtime.h>
#include <cuda_fp16.h>
#include <math.h>

#define Bb 16
#define Nn 512
#define Dd 96

// ---------------- scratch -------------------------------------------------
__device__ __half g_xh [(size_t)8192 * 768];
__device__ __half g_wqk[(size_t)768 * 1536];     // [k][ Wq(768) | Wk(768) ]
__device__ __half g_wvh[(size_t)768 * 1536];
__device__ __half g_woh[(size_t)1536 * 768];
__device__ __half g_wol[(size_t)1536 * 768];
__device__ __half g_Qh[(size_t)128 * 512 * 96];
__device__ __half g_Kh[(size_t)128 * 512 * 96];
__device__ __half g_Kl[(size_t)128 * 512 * 96];
__device__ __half g_Vh[(size_t)256 * 512 * 96];
__device__ __half g_S [(size_t)128 * 512 * 512];  // fp16 scores
__device__ __half g_Ah[(size_t)256 * 512 * 512];
__device__ __half g_Oh[(size_t)8192 * 1536];

// ---------------- helpers --------------------------------------------------
__device__ __forceinline__ unsigned sptr(const void* p) {
    return (unsigned)__cvta_generic_to_shared(p);
}
__device__ __forceinline__ void cpa16(unsigned s, const void* g) {
    asm volatile("cp.async.cg.shared.global [%0], [%1], 16;" :: "r"(s), "l"(g));
}
__device__ __forceinline__ void cpcommit() {
    asm volatile("cp.async.commit_group;");
}
template<int W> __device__ __forceinline__ void cpwait() {
    asm volatile("cp.async.wait_group %0;" :: "n"(W));
}
__device__ __forceinline__ void ldsm4(unsigned f[4], unsigned a) {
    asm volatile("ldmatrix.sync.aligned.m8n8.x4.shared.b16 {%0,%1,%2,%3}, [%4];"
                 : "=r"(f[0]), "=r"(f[1]), "=r"(f[2]), "=r"(f[3]) : "r"(a));
}
__device__ __forceinline__ void ldsm4t(unsigned& r0, unsigned& r1, unsigned& r2,
                                       unsigned& r3, unsigned a) {
    asm volatile("ldmatrix.sync.aligned.m8n8.x4.trans.shared.b16 {%0,%1,%2,%3}, [%4];"
                 : "=r"(r0), "=r"(r1), "=r"(r2), "=r"(r3) : "r"(a));
}
__device__ __forceinline__ void ldsm2t(unsigned& r0, unsigned& r1, unsigned a) {
    asm volatile("ldmatrix.sync.aligned.m8n8.x2.trans.shared.b16 {%0,%1}, [%2];"
                 : "=r"(r0), "=r"(r1) : "r"(a));
}
__device__ __forceinline__ void mmaf16(float c[4], const unsigned a[4],
                                       unsigned b0, unsigned b1) {
    asm volatile(
        "mma.sync.aligned.m16n8k16.row.col.f32.f16.f16.f32 "
        "{%0,%1,%2,%3}, {%4,%5,%6,%7}, {%8,%9}, {%0,%1,%2,%3};"
        : "+f"(c[0]), "+f"(c[1]), "+f"(c[2]), "+f"(c[3])
        : "r"(a[0]), "r"(a[1]), "r"(a[2]), "r"(a[3]), "r"(b0), "r"(b1));
}
__device__ __forceinline__ void hsplit(float v, __half& h, __half& l) {
    h = __float2half_rn(v);
    l = __float2half_rn(v - __half2float(h));
}

// ---------------- split inputs ---------------------------------------------
__global__ void __launch_bounds__(256) split2k(const float4* __restrict__ in,
                                               __half* __restrict__ oh,
                                               __half* __restrict__ ol, int n4) {
    int i = blockIdx.x * 256 + threadIdx.x;
    if (i >= n4) return;
    float4 v = in[i];
    __half h0, h1, h2, h3, l0, l1, l2, l3;
    hsplit(v.x, h0, l0); hsplit(v.y, h1, l1);
    hsplit(v.z, h2, l2); hsplit(v.w, h3, l3);
    ((__half2*)oh)[i * 2]     = __halves2half2(h0, h1);
    ((__half2*)oh)[i * 2 + 1] = __halves2half2(h2, h3);
    ((__half2*)ol)[i * 2]     = __halves2half2(l0, l1);
    ((__half2*)ol)[i * 2 + 1] = __halves2half2(l2, l3);
}
__global__ void __launch_bounds__(256) split1k(const float4* __restrict__ in,
                                               __half* __restrict__ oh, int n4) {
    int i = blockIdx.x * 256 + threadIdx.x;
    if (i >= n4) return;
    float4 v = in[i];
    ((__half2*)oh)[i * 2]     = __halves2half2(__float2half_rn(v.x), __float2half_rn(v.y));
    ((__half2*)oh)[i * 2 + 1] = __halves2half2(__float2half_rn(v.z), __float2half_rn(v.w));
}
// concat [Wq | Wk] columns into g_wqk[768][1536], fp16
__global__ void __launch_bounds__(256) splitQK(const float4* __restrict__ Wq,
                                               const float4* __restrict__ Wk,
                                               __half* __restrict__ o) {
    int i = blockIdx.x * 256 + threadIdx.x;   // 147456 float4 per matrix
    if (i >= 147456) return;
    int row = i / 192, col = (i % 192) * 4;
    float4 a = Wq[i];
    __half2* d = (__half2*)(o + (size_t)row * 1536 + col);
    d[0] = __halves2half2(__float2half_rn(a.x), __float2half_rn(a.y));
    d[1] = __halves2half2(__float2half_rn(a.z), __float2half_rn(a.w));
    float4 b = Wk[i];
    __half2* d2 = (__half2*)(o + (size_t)row * 1536 + 768 + col);
    d2[0] = __halves2half2(__float2half_rn(b.x), __float2half_rn(b.y));
    d2[1] = __halves2half2(__float2half_rn(b.z), __float2half_rn(b.w));
}

// ---------------------------------------------------------------------------
// C = A[MxK] @ B[KxN]. BM=128 BN=128 BK=32, 3-stage cp.async, 256 thr, 2 CTA/SM.
// TERMS==2: B dual planes (2 mma); TERMS==1: single.
// MODE 0: fp32 rowmajor (outF)
// MODE 1: QK combined: head h<8 -> single store o0(Q); h>=8 -> split o1/o2 (K)
// MODE 2: V: 16 heads, single store o0 (+bias)
// ---------------------------------------------------------------------------
#define ASTR 10240          // 128 rows * 80B
#define BSTR 8704           // 32 rows * 272B

template<int TERMS, int MODE, bool BIAS>
__global__ void __launch_bounds__(256, 2) gemm16(
    const __half* __restrict__ Agh,
    const __half* __restrict__ Bgh, const __half* __restrict__ Bgl,
    const float* __restrict__ bias,
    __half* __restrict__ o0, __half* __restrict__ o1, __half* __restrict__ o2,
    float* __restrict__ outF, int K, int N)
{
    extern __shared__ char smem[];
    char* p = smem;
    __half* sA = (__half*)p;  p += 3 * ASTR;
    __half* sBh = (__half*)p; p += 3 * BSTR;
    __half* sBl = (TERMS == 2) ? (__half*)p : nullptr;

    const int tid = threadIdx.x;
    const int lane = tid & 31, warp = tid >> 5;
    const int wm = warp >> 2, wn = warp & 3;
    const int gid = lane >> 2, tig = lane & 3;
    const int m0 = blockIdx.y * 128, n0 = blockIdx.x * 128;

    const int aR = tid >> 1, aC = (tid & 1) * 16;
    const int bR = tid >> 3, bC = (tid & 7) * 16;

    const unsigned sAb = sptr(sA), sBhb = sptr(sBh);
    const unsigned sBlb = (TERMS == 2) ? sptr(sBl) : 0;

    auto issue = [&](int kt, int s) {
        const int k0 = kt << 5;
        const __half* ga = Agh + (size_t)(m0 + aR) * K + k0 + aC;
        unsigned sa = sAb + s * ASTR + aR * 80 + aC * 2;
        cpa16(sa, ga); cpa16(sa + 16, ga + 8);
        const __half* gb = Bgh + (size_t)(k0 + bR) * N + n0 + bC;
        unsigned sb = sBhb + s * BSTR + bR * 272 + bC * 2;
        cpa16(sb, gb); cpa16(sb + 16, gb + 8);
        if (TERMS == 2) {
            const __half* gb2 = Bgl + (size_t)(k0 + bR) * N + n0 + bC;
            unsigned sb2 = sBlb + s * BSTR + bR * 272 + bC * 2;
            cpa16(sb2, gb2); cpa16(sb2 + 16, gb2 + 8);
        }
        cpcommit();
    };

    float c[4][4][4];
#pragma unroll
    for (int i = 0; i < 4; i++)
#pragma unroll
        for (int j = 0; j < 4; j++)
#pragma unroll
            for (int q = 0; q < 4; q++) c[i][j][q] = 0.f;

    const unsigned aOff = (wm * 64 + (lane & 15)) * 80 + (lane >> 4) * 16;
    const unsigned bOff = (lane & 15) * 272 + (wn * 32 + (lane >> 4) * 8) * 2;

    issue(0, 0); issue(1, 1);
    const int KT = K >> 5;

    for (int kt = 0; kt < KT; kt++) {
        cpwait<1>();
        __syncthreads();
        const int s = kt % 3;
        const unsigned aB = sAb + s * ASTR + aOff;
        const unsigned bB = sBhb + s * BSTR + bOff;
        const unsigned bB2 = (TERMS == 2) ? sBlb + s * BSTR + bOff : 0;

#pragma unroll
        for (int k16 = 0; k16 < 2; k16++) {
            unsigned ah[4][4], bh[4][2], bl[4][2], t0, t1, t2, t3;
#pragma unroll
            for (int mf = 0; mf < 4; mf++)
                ldsm4(ah[mf], aB + mf * 1280 + k16 * 32);
#pragma unroll
            for (int nf2 = 0; nf2 < 2; nf2++) {
                ldsm4t(t0, t1, t2, t3, bB + k16 * 4352 + nf2 * 32);
                bh[nf2 * 2][0] = t0; bh[nf2 * 2][1] = t1;
                bh[nf2 * 2 + 1][0] = t2; bh[nf2 * 2 + 1][1] = t3;
                if (TERMS == 2) {
                    ldsm4t(t0, t1, t2, t3, bB2 + k16 * 4352 + nf2 * 32);
                    bl[nf2 * 2][0] = t0; bl[nf2 * 2][1] = t1;
                    bl[nf2 * 2 + 1][0] = t2; bl[nf2 * 2 + 1][1] = t3;
                }
            }
#pragma unroll
            for (int mf = 0; mf < 4; mf++)
#pragma unroll
                for (int nf = 0; nf < 4; nf++) {
                    mmaf16(c[mf][nf], ah[mf], bh[nf][0], bh[nf][1]);
                    if (TERMS == 2)
                        mmaf16(c[mf][nf], ah[mf], bl[nf][0], bl[nf][1]);
                }
        }
        const int kn = kt + 2;
        if (kn < KT) issue(kn, kn % 3); else cpcommit();
    }

#pragma unroll
    for (int mf = 0; mf < 4; mf++)
#pragma unroll
        for (int q2 = 0; q2 < 2; q2++) {
            const int row = m0 + wm * 64 + mf * 16 + gid + q2 * 8;
            const int b = row >> 9, n = row & 511;
#pragma unroll
            for (int nf = 0; nf < 4; nf++) {
                const int col = n0 + wn * 32 + nf * 8 + tig * 2;
                float v0 = c[mf][nf][q2 * 2 + 0];
                float v1 = c[mf][nf][q2 * 2 + 1];
                if (BIAS) { v0 += bias[col]; v1 += bias[col + 1]; }
                if (MODE == 0) {
                    *(float2*)(outF + (size_t)row * N + col) = make_float2(v0, v1);
                } else if (MODE == 1) {
                    const int h = col / 96, d = col - h * 96;
                    if (h < 8) {
                        const size_t idx = (((size_t)(b * 8 + h)) * 512 + n) * 96 + d;
                        *(__half2*)(o0 + idx) =
                            __halves2half2(__float2half_rn(v0), __float2half_rn(v1));
                    } else {
                        const size_t idx = (((size_t)(b * 8 + h - 8)) * 512 + n) * 96 + d;
                        __half h0, h1, l0, l1;
                        hsplit(v0, h0, l0); hsplit(v1, h1, l1);
                        *(__half2*)(o1 + idx) = __halves2half2(h0, h1);
                        *(__half2*)(o2 + idx) = __halves2half2(l0, l1);
                    }
                } else {
                    const int h = col / 96, d = col - h * 96;
                    const size_t idx = (((size_t)(b * 16 + h)) * 512 + n) * 96 + d;
                    *(__half2*)(o0 + idx) =
                        __halves2half2(__float2half_rn(v0), __float2half_rn(v1));
                }
            }
        }
}

// ---------------------------------------------------------------------------
// Scores: S = Q.K^T + sigma^2*eps (fp16 store).  Q single, K dual (2-term).
// ---------------------------------------------------------------------------
__global__ void __launch_bounds__(256, 2) scores16(
    const float* __restrict__ eps, const float* __restrict__ sigma)
{
    extern __shared__ char smem[];
    char* p = smem;
    __half* sQ  = (__half*)p; p += 3 * ASTR;
    __half* sKh = (__half*)p; p += 3 * ASTR;
    __half* sKl = (__half*)p;

    const int tid = threadIdx.x;
    const int lane = tid & 31, warp = tid >> 5;
    const int wm = warp >> 2, wn = warp & 3;
    const int gid = lane >> 2, tig = lane & 3;
    const int bg = blockIdx.z;
    const int sn0 = blockIdx.y * 128, sm0 = blockIdx.x * 128;

    const __half* Qp  = g_Qh + (size_t)bg * Nn * Dd;
    const __half* Khp = g_Kh + (size_t)bg * Nn * Dd;
    const __half* Klp = g_Kl + (size_t)bg * Nn * Dd;

    const int aR = tid >> 1, aC = (tid & 1) * 16;
    const unsigned bQ = sptr(sQ), bKh = sptr(sKh), bKl = sptr(sKl);

    auto issue = [&](int kt, int s) {
        const int k0 = kt << 5;
        unsigned so = s * ASTR + aR * 80 + aC * 2;
        size_t go = (size_t)aR * 96 + k0 + aC;
        cpa16(bQ + so, Qp + (size_t)sn0 * 96 + go);
        cpa16(bQ + so + 16, Qp + (size_t)sn0 * 96 + go + 8);
        cpa16(bKh + so, Khp + (size_t)sm0 * 96 + go);
        cpa16(bKh + so + 16, Khp + (size_t)sm0 * 96 + go + 8);
        cpa16(bKl + so, Klp + (size_t)sm0 * 96 + go);
        cpa16(bKl + so + 16, Klp + (size_t)sm0 * 96 + go + 8);
        cpcommit();
    };

    float c[4][4][4];
#pragma unroll
    for (int i = 0; i < 4; i++)
#pragma unroll
        for (int j = 0; j < 4; j++)
#pragma unroll
            for (int q = 0; q < 4; q++) c[i][j][q] = 0.f;

    const unsigned aOff = (wm * 64 + (lane & 15)) * 80 + (lane >> 4) * 16;
    const unsigned kOff = (wn * 32 + (lane & 15)) * 80 + (lane >> 4) * 16;

    issue(0, 0); issue(1, 1);

    for (int kt = 0; kt < 3; kt++) {
        cpwait<1>();
        __syncthreads();
        const unsigned aB = bQ + kt * ASTR + aOff;
        const unsigned kH = bKh + kt * ASTR + kOff;
        const unsigned kL = bKl + kt * ASTR + kOff;

#pragma unroll
        for (int k16 = 0; k16 < 2; k16++) {
            unsigned ah[4][4], f[4], bh[4][2], bl[4][2];
#pragma unroll
            for (int mf = 0; mf < 4; mf++)
                ldsm4(ah[mf], aB + mf * 1280 + k16 * 32);
#pragma unroll
            for (int nf2 = 0; nf2 < 2; nf2++) {
                ldsm4(f, kH + nf2 * 1280 + k16 * 32);
                bh[nf2 * 2][0] = f[0]; bh[nf2 * 2][1] = f[2];
                bh[nf2 * 2 + 1][0] = f[1]; bh[nf2 * 2 + 1][1] = f[3];
                ldsm4(f, kL + nf2 * 1280 + k16 * 32);
                bl[nf2 * 2][0] = f[0]; bl[nf2 * 2][1] = f[2];
                bl[nf2 * 2 + 1][0] = f[1]; bl[nf2 * 2 + 1][1] = f[3];
            }
#pragma unroll
            for (int mf = 0; mf < 4; mf++)
#pragma unroll
                for (int nf = 0; nf < 4; nf++) {
                    mmaf16(c[mf][nf], ah[mf], bh[nf][0], bh[nf][1]);
                    mmaf16(c[mf][nf], ah[mf], bl[nf][0], bl[nf][1]);
                }
        }
        const int kn = kt + 2;
        if (kn < 3) issue(kn, kn); else cpcommit();
    }

    float s2 = sigma[bg & 7];
    s2 = s2 * s2;
#pragma unroll
    for (int mf = 0; mf < 4; mf++)
#pragma unroll
        for (int q2 = 0; q2 < 2; q2++) {
            const int n = sn0 + wm * 64 + mf * 16 + gid + q2 * 8;
#pragma unroll
            for (int nf = 0; nf < 4; nf++) {
                const int m = sm0 + wn * 32 + nf * 8 + tig * 2;
                const size_t idx = ((size_t)bg * Nn + n) * Nn + m;
                float2 ev = *(const float2*)(eps + idx);
                *(__half2*)(g_S + idx) = __halves2half2(
                    __float2half_rn(c[mf][nf][q2 * 2 + 0] + s2 * ev.x),
                    __float2half_rn(c[mf][nf][q2 * 2 + 1] + s2 * ev.y));
            }
        }
}

// ---------------------------------------------------------------------------
// Mix + mish + softmax -> A single fp16.  S read as fp16.
// ---------------------------------------------------------------------------
__global__ void __launch_bounds__(512) mix_softmax_kernel(
    const float* __restrict__ encoding_bias, const float* __restrict__ p)
{
    int bn = blockIdx.x;
    int b = bn >> 9, n = bn & 511;
    int tid = threadIdx.x;
    int lane = tid & 31, warp = tid >> 5;

    __shared__ float ps[128];
    __shared__ float red[16][17];
    __shared__ float rmax[16];
    __shared__ float rsum[16];

    if (tid < 128) ps[tid] = p[tid];
    __syncthreads();

    float s[8];
#pragma unroll
    for (int g = 0; g < 8; g++)
        s[g] = __half2float(g_S[(((size_t)(b * 8 + g)) * 512 + n) * 512 + tid]);
    float bias = encoding_bias[((size_t)bn) * 512 + tid];
    const float scale = 0.03608439182435161f;

    float vals[16];
#pragma unroll
    for (int l = 0; l < 16; l++) {
        float t = 0.f;
#pragma unroll
        for (int g = 0; g < 8; g++) t = fmaf(s[g], ps[g * 16 + l], t);
        float e = __expf(fminf(t, 15.f));
        float num = e * (e + 2.f);
        vals[l] = t * (num / (num + 2.f)) * scale + bias;
    }

#pragma unroll
    for (int l = 0; l < 16; l++) {
        float v = vals[l];
#pragma unroll
        for (int o = 16; o > 0; o >>= 1)
            v = fmaxf(v, __shfl_xor_sync(0xffffffffu, v, o));
        if (lane == 0) red[l][warp] = v;
    }
    __syncthreads();
    {
        float v = (lane < 16) ? red[warp][lane] : -3.0e38f;
#pragma unroll
        for (int o = 8; o > 0; o >>= 1)
            v = fmaxf(v, __shfl_xor_sync(0xffffffffu, v, o));
        if (lane == 0) rmax[warp] = v;
    }
    __syncthreads();
#pragma unroll
    for (int l = 0; l < 16; l++) {
        vals[l] = __expf(vals[l] - rmax[l]);
        float v = vals[l];
#pragma unroll
        for (int o = 16; o > 0; o >>= 1)
            v += __shfl_xor_sync(0xffffffffu, v, o);
        if (lane == 0) red[l][warp] = v;
    }
    __syncthreads();
    {
        float v = (lane < 16) ? red[warp][lane] : 0.f;
#pragma unroll
        for (int o = 8; o > 0; o >>= 1)
            v += __shfl_xor_sync(0xffffffffu, v, o);
        if (lane == 0) rsum[warp] = v;
    }
    __syncthreads();
#pragma unroll
    for (int l = 0; l < 16; l++)
        g_Ah[(((size_t)(b * 16 + l)) * 512 + n) * 512 + tid] =
            __float2half_rn(vals[l] / rsum[l]);
}

// ---------------------------------------------------------------------------
// O = A @ V per (b,l).  A fp16, V fp16 (1-term).  O fp16.
// BM=128, BN=96, BK=32, KT=16.
// ---------------------------------------------------------------------------
#define VSTR 6656          // 32 rows * 208B

__global__ void __launch_bounds__(256, 2) outv16()
{
    extern __shared__ char smem[];
    char* p = smem;
    __half* sA = (__half*)p;  p += 3 * ASTR;
    __half* sVh = (__half*)p;

    const int tid = threadIdx.x;
    const int lane = tid & 31, warp = tid >> 5;
    const int wm = warp >> 2, wn = warp & 3;
    const int gid = lane >> 2, tig = lane & 3;
    const int bl = blockIdx.y;
    const int n0 = blockIdx.x * 128;

    const __half* Ap = g_Ah + (size_t)bl * Nn * Nn;
    const __half* Vhp = g_Vh + (size_t)bl * Nn * Dd;

    const int aR = tid >> 1, aC = (tid & 1) * 16;
    const int vR = tid / 6, vC = (tid % 6) * 16;
    const bool vAct = tid < 192;

    const unsigned bA = sptr(sA), bVh = sptr(sVh);

    auto issue = [&](int kt, int s) {
        const int k0 = kt << 5;
        unsigned sa = bA + s * ASTR + aR * 80 + aC * 2;
        const __half* ga = Ap + (size_t)(n0 + aR) * 512 + k0 + aC;
        cpa16(sa, ga); cpa16(sa + 16, ga + 8);
        if (vAct) {
            unsigned sv = bVh + s * VSTR + vR * 208 + vC * 2;
            const __half* gv = Vhp + (size_t)(k0 + vR) * 96 + vC;
            cpa16(sv, gv); cpa16(sv + 16, gv + 8);
        }
        cpcommit();
    };

    float c[4][3][4];
#pragma unroll
    for (int i = 0; i < 4; i++)
#pragma unroll
        for (int j = 0; j < 3; j++)
#pragma unroll
            for (int q = 0; q < 4; q++) c[i][j][q] = 0.f;

    const unsigned aOff = (wm * 64 + (lane & 15)) * 80 + (lane >> 4) * 16;
    const unsigned vOff = (lane & 15) * 208 + (wn * 24 + (lane >> 4) * 8) * 2;
    const unsigned vOff2 = (lane & 15) * 208 + (wn * 24 + 16) * 2;

    issue(0, 0); issue(1, 1);

    for (int kt = 0; kt < 16; kt++) {
        cpwait<1>();
        __syncthreads();
        const int s = kt % 3;
        const unsigned aB = bA + s * ASTR + aOff;
        const unsigned vH = bVh + s * VSTR;

#pragma unroll
        for (int k16 = 0; k16 < 2; k16++) {
            unsigned ah[4][4], bh[3][2], t0, t1, t2, t3;
#pragma unroll
            for (int mf = 0; mf < 4; mf++)
                ldsm4(ah[mf], aB + mf * 1280 + k16 * 32);
            ldsm4t(t0, t1, t2, t3, vH + vOff + k16 * 3328);
            bh[0][0] = t0; bh[0][1] = t1; bh[1][0] = t2; bh[1][1] = t3;
            ldsm2t(t0, t1, vH + vOff2 + k16 * 3328);
            bh[2][0] = t0; bh[2][1] = t1;

#pragma unroll
            for (int mf = 0; mf < 4; mf++)
#pragma unroll
                for (int nf = 0; nf < 3; nf++)
                    mmaf16(c[mf][nf], ah[mf], bh[nf][0], bh[nf][1]);
        }
        const int kn = kt + 2;
        if (kn < 16) issue(kn, kn % 3); else cpcommit();
    }

    const int b = bl >> 4, l = bl & 15;
#pragma unroll
    for (int mf = 0; mf < 4; mf++)
#pragma unroll
        for (int q2 = 0; q2 < 2; q2++) {
            const int n = n0 + wm * 64 + mf * 16 + gid + q2 * 8;
#pragma unroll
            for (int nf = 0; nf < 3; nf++) {
                const int d = wn * 24 + nf * 8 + tig * 2;
                const size_t idx = ((size_t)(b * 512 + n)) * 1536 + l * 96 + d;
                *(__half2*)(g_Oh + idx) =
                    __halves2half2(__float2half_rn(c[mf][nf][q2 * 2 + 0]),
                                   __float2half_rn(c[mf][nf][q2 * 2 + 1]));
            }
        }
}

// ---------------------------------------------------------------------------
extern "C" void kernel_launch(void* const* d_in, const int* in_sizes, int n_in,
                              void* d_out, int out_size)
{
    const float* x     = (const float*)d_in[0];
    const float* ebias = (const float*)d_in[1];
    const float* eps   = (const float*)d_in[2];
    const float* Wq    = (const float*)d_in[3];
    const float* Wk    = (const float*)d_in[4];
    const float* Wv    = (const float*)d_in[5];
    const float* bv    = (const float*)d_in[6];
    const float* sigma = (const float*)d_in[7];
    const float* p     = (const float*)d_in[8];
    const float* Wout  = (const float*)d_in[9];
    float* out = (float*)d_out;

    __half *xh, *wqk, *wvh, *woh, *wol;
    __half *qh, *kh, *kl, *vh, *oh;
    cudaGetSymbolAddress((void**)&xh,  g_xh);
    cudaGetSymbolAddress((void**)&wqk, g_wqk);
    cudaGetSymbolAddress((void**)&wvh, g_wvh);
    cudaGetSymbolAddress((void**)&woh, g_woh);
    cudaGetSymbolAddress((void**)&wol, g_wol);
    cudaGetSymbolAddress((void**)&qh,  g_Qh);
    cudaGetSymbolAddress((void**)&kh,  g_Kh);
    cudaGetSymbolAddress((void**)&kl,  g_Kl);
    cudaGetSymbolAddress((void**)&vh,  g_Vh);
    cudaGetSymbolAddress((void**)&oh,  g_Oh);

    const int SM_1 = 3 * ASTR + 3 * BSTR;   // 56832
    const int SM_2 = 3 * ASTR + 6 * BSTR;   // 82944
    const int SM_S = 9 * ASTR;              // 92160
    const int SM_O = 3 * ASTR + 3 * VSTR;   // 50688

    cudaFuncSetAttribute(gemm16<1, 1, false>,
        cudaFuncAttributeMaxDynamicSharedMemorySize, SM_1);
    cudaFuncSetAttribute(gemm16<1, 2, true>,
        cudaFuncAttributeMaxDynamicSharedMemorySize, SM_1);
    cudaFuncSetAttribute(gemm16<2, 0, false>,
        cudaFuncAttributeMaxDynamicSharedMemorySize, SM_2);
    cudaFuncSetAttribute(scores16,
        cudaFuncAttributeMaxDynamicSharedMemorySize, SM_S);
    cudaFuncSetAttribute(outv16,
        cudaFuncAttributeMaxDynamicSharedMemorySize, SM_O);

    // splits
    split1k<<<6144, 256>>>((const float4*)x, xh, 1572864);
    splitQK<<<576, 256>>>((const float4*)Wq, (const float4*)Wk, wqk);
    split1k<<<1152, 256>>>((const float4*)Wv, wvh, 294912);
    split2k<<<1152, 256>>>((const float4*)Wout, woh, wol, 294912);

    // Q+K projection merged: 1-term, N=1536 (Q single / K split stores)
    gemm16<1, 1, false><<<dim3(12, 64), 256, SM_1>>>(
        xh, wqk, nullptr, nullptr, qh, kh, kl, nullptr, 768, 1536);
    // V proj: 1-term + bias, single store
    gemm16<1, 2, true><<<dim3(12, 64), 256, SM_1>>>(
        xh, wvh, nullptr, bv, vh, nullptr, nullptr, nullptr, 768, 1536);

    // scores: 2-term (qh . (kh+kl)) + sigma^2*eps -> fp16 S
    scores16<<<dim3(4, 4, 128), 256, SM_S>>>(eps, sigma);

    // mix + mish + softmax -> A fp16
    mix_softmax_kernel<<<Bb * Nn, 512>>>(ebias, p);

    // O = A @ V (1-term), fp16 store
    outv16<<<dim3(4, 256), 256, SM_O>>>();

    // out proj: 2-term (Oh . (woh+wol)) -> fp32 d_out
    gemm16<2, 0, false><<<dim3(6, 64), 256, SM_2>>>(
        oh, woh, wol, nullptr, nullptr, nullptr, nullptr, out, 1536, 768);
}

// round 11
// speedup vs baseline: 1.5870x; 1.0700x over previous
#include <cuda_runtime.h>
#include <cuda_fp16.h>
#include <math.h>

#define Bb 16
#define Nn 512
#define Dd 96

// ---------------- scratch -------------------------------------------------
__device__ __half g_xh  [(size_t)8192 * 768];
__device__ __half g_wqkv[(size_t)768 * 3072];    // [k][ Wq | Wk | Wv ]
__device__ __half g_woh [(size_t)1536 * 768];
__device__ __half g_Qh[(size_t)128 * 512 * 96];
__device__ __half g_Kh[(size_t)128 * 512 * 96];
__device__ __half g_Kl[(size_t)128 * 512 * 96];
__device__ __half g_Vh[(size_t)256 * 512 * 96];
__device__ __half g_S [(size_t)128 * 512 * 512];
__device__ __half g_Ah[(size_t)256 * 512 * 512];
__device__ __half g_Oh[(size_t)8192 * 1536];

// ---------------- helpers --------------------------------------------------
__device__ __forceinline__ unsigned sptr(const void* p) {
    return (unsigned)__cvta_generic_to_shared(p);
}
__device__ __forceinline__ void cpa16(unsigned s, const void* g) {
    asm volatile("cp.async.cg.shared.global [%0], [%1], 16;" :: "r"(s), "l"(g));
}
__device__ __forceinline__ void cpcommit() {
    asm volatile("cp.async.commit_group;");
}
template<int W> __device__ __forceinline__ void cpwait() {
    asm volatile("cp.async.wait_group %0;" :: "n"(W));
}
__device__ __forceinline__ void ldsm4(unsigned f[4], unsigned a) {
    asm volatile("ldmatrix.sync.aligned.m8n8.x4.shared.b16 {%0,%1,%2,%3}, [%4];"
                 : "=r"(f[0]), "=r"(f[1]), "=r"(f[2]), "=r"(f[3]) : "r"(a));
}
__device__ __forceinline__ void ldsm4t(unsigned& r0, unsigned& r1, unsigned& r2,
                                       unsigned& r3, unsigned a) {
    asm volatile("ldmatrix.sync.aligned.m8n8.x4.trans.shared.b16 {%0,%1,%2,%3}, [%4];"
                 : "=r"(r0), "=r"(r1), "=r"(r2), "=r"(r3) : "r"(a));
}
__device__ __forceinline__ void ldsm2t(unsigned& r0, unsigned& r1, unsigned a) {
    asm volatile("ldmatrix.sync.aligned.m8n8.x2.trans.shared.b16 {%0,%1}, [%2];"
                 : "=r"(r0), "=r"(r1) : "r"(a));
}
__device__ __forceinline__ void mmaf16(float c[4], const unsigned a[4],
                                       unsigned b0, unsigned b1) {
    asm volatile(
        "mma.sync.aligned.m16n8k16.row.col.f32.f16.f16.f32 "
        "{%0,%1,%2,%3}, {%4,%5,%6,%7}, {%8,%9}, {%0,%1,%2,%3};"
        : "+f"(c[0]), "+f"(c[1]), "+f"(c[2]), "+f"(c[3])
        : "r"(a[0]), "r"(a[1]), "r"(a[2]), "r"(a[3]), "r"(b0), "r"(b1));
}
__device__ __forceinline__ void hsplit(float v, __half& h, __half& l) {
    h = __float2half_rn(v);
    l = __float2half_rn(v - __half2float(h));
}

// ---------------- split inputs ---------------------------------------------
__global__ void __launch_bounds__(256) split1k(const float4* __restrict__ in,
                                               __half* __restrict__ oh, int n4) {
    int i = blockIdx.x * 256 + threadIdx.x;
    if (i >= n4) return;
    float4 v = in[i];
    ((__half2*)oh)[i * 2]     = __halves2half2(__float2half_rn(v.x), __float2half_rn(v.y));
    ((__half2*)oh)[i * 2 + 1] = __halves2half2(__float2half_rn(v.z), __float2half_rn(v.w));
}
// Wq,Wk -> g_wqkv cols [0,1536), row stride 3072
__global__ void __launch_bounds__(256) splitQK(const float4* __restrict__ Wq,
                                               const float4* __restrict__ Wk,
                                               __half* __restrict__ o) {
    int i = blockIdx.x * 256 + threadIdx.x;   // 147456 float4 each
    if (i >= 147456) return;
    int row = i / 192, col = (i % 192) * 4;
    float4 a = Wq[i];
    __half2* d = (__half2*)(o + (size_t)row * 3072 + col);
    d[0] = __halves2half2(__float2half_rn(a.x), __float2half_rn(a.y));
    d[1] = __halves2half2(__float2half_rn(a.z), __float2half_rn(a.w));
    float4 b = Wk[i];
    __half2* d2 = (__half2*)(o + (size_t)row * 3072 + 768 + col);
    d2[0] = __halves2half2(__float2half_rn(b.x), __float2half_rn(b.y));
    d2[1] = __halves2half2(__float2half_rn(b.z), __float2half_rn(b.w));
}
// Wv -> g_wqkv cols [1536,3072)
__global__ void __launch_bounds__(256) splitV(const float4* __restrict__ Wv,
                                              __half* __restrict__ o) {
    int i = blockIdx.x * 256 + threadIdx.x;   // 294912 float4
    if (i >= 294912) return;
    int row = i / 384, col = (i % 384) * 4;
    float4 a = Wv[i];
    __half2* d = (__half2*)(o + (size_t)row * 3072 + 1536 + col);
    d[0] = __halves2half2(__float2half_rn(a.x), __float2half_rn(a.y));
    d[1] = __halves2half2(__float2half_rn(a.z), __float2half_rn(a.w));
}

// ---------------------------------------------------------------------------
// C = A[MxK] @ B[KxN]. BM=128 BN=128 BK=32, 3-stage cp.async, 256 thr, 2 CTA/SM.
// TERMS==2: B dual planes; TERMS==1: single.
// MODE 0: fp32 rowmajor (outF)
// MODE 1: QKV merged (N=3072): col<768 Q single o0; <1536 K split o1/o2;
//         else V single o3 + bias[col-1536]
// ---------------------------------------------------------------------------
#define ASTR 10240          // 128 rows * 80B
#define BSTR 8704           // 32 rows * 272B

template<int TERMS, int MODE>
__global__ void __launch_bounds__(256, 2) gemm16(
    const __half* __restrict__ Agh,
    const __half* __restrict__ Bgh, const __half* __restrict__ Bgl,
    const float* __restrict__ bias,
    __half* __restrict__ o0, __half* __restrict__ o1, __half* __restrict__ o2,
    __half* __restrict__ o3, float* __restrict__ outF, int K, int N)
{
    extern __shared__ char smem[];
    char* p = smem;
    __half* sA = (__half*)p;  p += 3 * ASTR;
    __half* sBh = (__half*)p; p += 3 * BSTR;
    __half* sBl = (TERMS == 2) ? (__half*)p : nullptr;

    const int tid = threadIdx.x;
    const int lane = tid & 31, warp = tid >> 5;
    const int wm = warp >> 2, wn = warp & 3;
    const int gid = lane >> 2, tig = lane & 3;
    const int m0 = blockIdx.y * 128, n0 = blockIdx.x * 128;

    const int aR = tid >> 1, aC = (tid & 1) * 16;
    const int bR = tid >> 3, bC = (tid & 7) * 16;

    const unsigned sAb = sptr(sA), sBhb = sptr(sBh);
    const unsigned sBlb = (TERMS == 2) ? sptr(sBl) : 0;

    auto issue = [&](int kt, int s) {
        const int k0 = kt << 5;
        const __half* ga = Agh + (size_t)(m0 + aR) * K + k0 + aC;
        unsigned sa = sAb + s * ASTR + aR * 80 + aC * 2;
        cpa16(sa, ga); cpa16(sa + 16, ga + 8);
        const __half* gb = Bgh + (size_t)(k0 + bR) * N + n0 + bC;
        unsigned sb = sBhb + s * BSTR + bR * 272 + bC * 2;
        cpa16(sb, gb); cpa16(sb + 16, gb + 8);
        if (TERMS == 2) {
            const __half* gb2 = Bgl + (size_t)(k0 + bR) * N + n0 + bC;
            unsigned sb2 = sBlb + s * BSTR + bR * 272 + bC * 2;
            cpa16(sb2, gb2); cpa16(sb2 + 16, gb2 + 8);
        }
        cpcommit();
    };

    float c[4][4][4];
#pragma unroll
    for (int i = 0; i < 4; i++)
#pragma unroll
        for (int j = 0; j < 4; j++)
#pragma unroll
            for (int q = 0; q < 4; q++) c[i][j][q] = 0.f;

    const unsigned aOff = (wm * 64 + (lane & 15)) * 80 + (lane >> 4) * 16;
    const unsigned bOff = (lane & 15) * 272 + (wn * 32 + (lane >> 4) * 8) * 2;

    issue(0, 0); issue(1, 1);
    const int KT = K >> 5;

    for (int kt = 0; kt < KT; kt++) {
        cpwait<1>();
        __syncthreads();
        const int s = kt % 3;
        const unsigned aB = sAb + s * ASTR + aOff;
        const unsigned bB = sBhb + s * BSTR + bOff;
        const unsigned bB2 = (TERMS == 2) ? sBlb + s * BSTR + bOff : 0;

#pragma unroll
        for (int k16 = 0; k16 < 2; k16++) {
            unsigned ah[4][4], bh[4][2], bl[4][2], t0, t1, t2, t3;
#pragma unroll
            for (int mf = 0; mf < 4; mf++)
                ldsm4(ah[mf], aB + mf * 1280 + k16 * 32);
#pragma unroll
            for (int nf2 = 0; nf2 < 2; nf2++) {
                ldsm4t(t0, t1, t2, t3, bB + k16 * 4352 + nf2 * 32);
                bh[nf2 * 2][0] = t0; bh[nf2 * 2][1] = t1;
                bh[nf2 * 2 + 1][0] = t2; bh[nf2 * 2 + 1][1] = t3;
                if (TERMS == 2) {
                    ldsm4t(t0, t1, t2, t3, bB2 + k16 * 4352 + nf2 * 32);
                    bl[nf2 * 2][0] = t0; bl[nf2 * 2][1] = t1;
                    bl[nf2 * 2 + 1][0] = t2; bl[nf2 * 2 + 1][1] = t3;
                }
            }
#pragma unroll
            for (int mf = 0; mf < 4; mf++)
#pragma unroll
                for (int nf = 0; nf < 4; nf++) {
                    mmaf16(c[mf][nf], ah[mf], bh[nf][0], bh[nf][1]);
                    if (TERMS == 2)
                        mmaf16(c[mf][nf], ah[mf], bl[nf][0], bl[nf][1]);
                }
        }
        const int kn = kt + 2;
        if (kn < KT) issue(kn, kn % 3); else cpcommit();
    }

#pragma unroll
    for (int mf = 0; mf < 4; mf++)
#pragma unroll
        for (int q2 = 0; q2 < 2; q2++) {
            const int row = m0 + wm * 64 + mf * 16 + gid + q2 * 8;
            const int b = row >> 9, n = row & 511;
#pragma unroll
            for (int nf = 0; nf < 4; nf++) {
                const int col = n0 + wn * 32 + nf * 8 + tig * 2;
                float v0 = c[mf][nf][q2 * 2 + 0];
                float v1 = c[mf][nf][q2 * 2 + 1];
                if (MODE == 0) {
                    *(float2*)(outF + (size_t)row * N + col) = make_float2(v0, v1);
                } else {
                    if (col < 768) {
                        const int h = col / 96, d = col - h * 96;
                        const size_t idx = (((size_t)(b * 8 + h)) * 512 + n) * 96 + d;
                        *(__half2*)(o0 + idx) =
                            __halves2half2(__float2half_rn(v0), __float2half_rn(v1));
                    } else if (col < 1536) {
                        const int cc = col - 768;
                        const int h = cc / 96, d = cc - h * 96;
                        const size_t idx = (((size_t)(b * 8 + h)) * 512 + n) * 96 + d;
                        __half h0, h1, l0, l1;
                        hsplit(v0, h0, l0); hsplit(v1, h1, l1);
                        *(__half2*)(o1 + idx) = __halves2half2(h0, h1);
                        *(__half2*)(o2 + idx) = __halves2half2(l0, l1);
                    } else {
                        const int cc = col - 1536;
                        const int h = cc / 96, d = cc - h * 96;
                        v0 += bias[cc]; v1 += bias[cc + 1];
                        const size_t idx = (((size_t)(b * 16 + h)) * 512 + n) * 96 + d;
                        *(__half2*)(o3 + idx) =
                            __halves2half2(__float2half_rn(v0), __float2half_rn(v1));
                    }
                }
            }
        }
}

// ---------------------------------------------------------------------------
// Scores: S = Q.K^T + sigma^2*eps (fp16 store).  Q single, K dual (2-term).
// ---------------------------------------------------------------------------
__global__ void __launch_bounds__(256, 2) scores16(
    const float* __restrict__ eps, const float* __restrict__ sigma)
{
    extern __shared__ char smem[];
    char* p = smem;
    __half* sQ  = (__half*)p; p += 3 * ASTR;
    __half* sKh = (__half*)p; p += 3 * ASTR;
    __half* sKl = (__half*)p;

    const int tid = threadIdx.x;
    const int lane = tid & 31, warp = tid >> 5;
    const int wm = warp >> 2, wn = warp & 3;
    const int gid = lane >> 2, tig = lane & 3;
    const int bg = blockIdx.z;
    const int sn0 = blockIdx.y * 128, sm0 = blockIdx.x * 128;

    const __half* Qp  = g_Qh + (size_t)bg * Nn * Dd;
    const __half* Khp = g_Kh + (size_t)bg * Nn * Dd;
    const __half* Klp = g_Kl + (size_t)bg * Nn * Dd;

    const int aR = tid >> 1, aC = (tid & 1) * 16;
    const unsigned bQ = sptr(sQ), bKh = sptr(sKh), bKl = sptr(sKl);

    auto issue = [&](int kt, int s) {
        const int k0 = kt << 5;
        unsigned so = s * ASTR + aR * 80 + aC * 2;
        size_t go = (size_t)aR * 96 + k0 + aC;
        cpa16(bQ + so, Qp + (size_t)sn0 * 96 + go);
        cpa16(bQ + so + 16, Qp + (size_t)sn0 * 96 + go + 8);
        cpa16(bKh + so, Khp + (size_t)sm0 * 96 + go);
        cpa16(bKh + so + 16, Khp + (size_t)sm0 * 96 + go + 8);
        cpa16(bKl + so, Klp + (size_t)sm0 * 96 + go);
        cpa16(bKl + so + 16, Klp + (size_t)sm0 * 96 + go + 8);
        cpcommit();
    };

    float c[4][4][4];
#pragma unroll
    for (int i = 0; i < 4; i++)
#pragma unroll
        for (int j = 0; j < 4; j++)
#pragma unroll
            for (int q = 0; q < 4; q++) c[i][j][q] = 0.f;

    const unsigned aOff = (wm * 64 + (lane & 15)) * 80 + (lane >> 4) * 16;
    const unsigned kOff = (wn * 32 + (lane & 15)) * 80 + (lane >> 4) * 16;

    issue(0, 0); issue(1, 1);

    for (int kt = 0; kt < 3; kt++) {
        cpwait<1>();
        __syncthreads();
        const unsigned aB = bQ + kt * ASTR + aOff;
        const unsigned kH = bKh + kt * ASTR + kOff;
        const unsigned kL = bKl + kt * ASTR + kOff;

#pragma unroll
        for (int k16 = 0; k16 < 2; k16++) {
            unsigned ah[4][4], f[4], bh[4][2], bl[4][2];
#pragma unroll
            for (int mf = 0; mf < 4; mf++)
                ldsm4(ah[mf], aB + mf * 1280 + k16 * 32);
#pragma unroll
            for (int nf2 = 0; nf2 < 2; nf2++) {
                ldsm4(f, kH + nf2 * 1280 + k16 * 32);
                bh[nf2 * 2][0] = f[0]; bh[nf2 * 2][1] = f[2];
                bh[nf2 * 2 + 1][0] = f[1]; bh[nf2 * 2 + 1][1] = f[3];
                ldsm4(f, kL + nf2 * 1280 + k16 * 32);
                bl[nf2 * 2][0] = f[0]; bl[nf2 * 2][1] = f[2];
                bl[nf2 * 2 + 1][0] = f[1]; bl[nf2 * 2 + 1][1] = f[3];
            }
#pragma unroll
            for (int mf = 0; mf < 4; mf++)
#pragma unroll
                for (int nf = 0; nf < 4; nf++) {
                    mmaf16(c[mf][nf], ah[mf], bh[nf][0], bh[nf][1]);
                    mmaf16(c[mf][nf], ah[mf], bl[nf][0], bl[nf][1]);
                }
        }
        const int kn = kt + 2;
        if (kn < 3) issue(kn, kn); else cpcommit();
    }

    float s2 = sigma[bg & 7];
    s2 = s2 * s2;
#pragma unroll
    for (int mf = 0; mf < 4; mf++)
#pragma unroll
        for (int q2 = 0; q2 < 2; q2++) {
            const int n = sn0 + wm * 64 + mf * 16 + gid + q2 * 8;
#pragma unroll
            for (int nf = 0; nf < 4; nf++) {
                const int m = sm0 + wn * 32 + nf * 8 + tig * 2;
                const size_t idx = ((size_t)bg * Nn + n) * Nn + m;
                float2 ev = *(const float2*)(eps + idx);
                *(__half2*)(g_S + idx) = __halves2half2(
                    __float2half_rn(c[mf][nf][q2 * 2 + 0] + s2 * ev.x),
                    __float2half_rn(c[mf][nf][q2 * 2 + 1] + s2 * ev.y));
            }
        }
}

// ---------------------------------------------------------------------------
// Mix + mish + softmax -> A single fp16.  S read as fp16.
// ---------------------------------------------------------------------------
__global__ void __launch_bounds__(512) mix_softmax_kernel(
    const float* __restrict__ encoding_bias, const float* __restrict__ p)
{
    int bn = blockIdx.x;
    int b = bn >> 9, n = bn & 511;
    int tid = threadIdx.x;
    int lane = tid & 31, warp = tid >> 5;

    __shared__ float ps[128];
    __shared__ float red[16][17];
    __shared__ float rmax[16];
    __shared__ float rsum[16];

    if (tid < 128) ps[tid] = p[tid];
    __syncthreads();

    float s[8];
#pragma unroll
    for (int g = 0; g < 8; g++)
        s[g] = __half2float(g_S[(((size_t)(b * 8 + g)) * 512 + n) * 512 + tid]);
    float bias = encoding_bias[((size_t)bn) * 512 + tid];
    const float scale = 0.03608439182435161f;

    float vals[16];
#pragma unroll
    for (int l = 0; l < 16; l++) {
        float t = 0.f;
#pragma unroll
        for (int g = 0; g < 8; g++) t = fmaf(s[g], ps[g * 16 + l], t);
        float e = __expf(fminf(t, 15.f));
        float num = e * (e + 2.f);
        vals[l] = t * (num / (num + 2.f)) * scale + bias;
    }

#pragma unroll
    for (int l = 0; l < 16; l++) {
        float v = vals[l];
#pragma unroll
        for (int o = 16; o > 0; o >>= 1)
            v = fmaxf(v, __shfl_xor_sync(0xffffffffu, v, o));
        if (lane == 0) red[l][warp] = v;
    }
    __syncthreads();
    {
        float v = (lane < 16) ? red[warp][lane] : -3.0e38f;
#pragma unroll
        for (int o = 8; o > 0; o >>= 1)
            v = fmaxf(v, __shfl_xor_sync(0xffffffffu, v, o));
        if (lane == 0) rmax[warp] = v;
    }
    __syncthreads();
#pragma unroll
    for (int l = 0; l < 16; l++) {
        vals[l] = __expf(vals[l] - rmax[l]);
        float v = vals[l];
#pragma unroll
        for (int o = 16; o > 0; o >>= 1)
            v += __shfl_xor_sync(0xffffffffu, v, o);
        if (lane == 0) red[l][warp] = v;
    }
    __syncthreads();
    {
        float v = (lane < 16) ? red[warp][lane] : 0.f;
#pragma unroll
        for (int o = 8; o > 0; o >>= 1)
            v += __shfl_xor_sync(0xffffffffu, v, o);
        if (lane == 0) rsum[warp] = v;
    }
    __syncthreads();
#pragma unroll
    for (int l = 0; l < 16; l++)
        g_Ah[(((size_t)(b * 16 + l)) * 512 + n) * 512 + tid] =
            __float2half_rn(vals[l] / rsum[l]);
}

// ---------------------------------------------------------------------------
// O = A @ V per (b,l).  A fp16, V fp16 (1-term).  O fp16.
// ---------------------------------------------------------------------------
#define VSTR 6656          // 32 rows * 208B

__global__ void __launch_bounds__(256, 2) outv16()
{
    extern __shared__ char smem[];
    char* p = smem;
    __half* sA = (__half*)p;  p += 3 * ASTR;
    __half* sVh = (__half*)p;

    const int tid = threadIdx.x;
    const int lane = tid & 31, warp = tid >> 5;
    const int wm = warp >> 2, wn = warp & 3;
    const int gid = lane >> 2, tig = lane & 3;
    const int bl = blockIdx.y;
    const int n0 = blockIdx.x * 128;

    const __half* Ap = g_Ah + (size_t)bl * Nn * Nn;
    const __half* Vhp = g_Vh + (size_t)bl * Nn * Dd;

    const int aR = tid >> 1, aC = (tid & 1) * 16;
    const int vR = tid / 6, vC = (tid % 6) * 16;
    const bool vAct = tid < 192;

    const unsigned bA = sptr(sA), bVh = sptr(sVh);

    auto issue = [&](int kt, int s) {
        const int k0 = kt << 5;
        unsigned sa = bA + s * ASTR + aR * 80 + aC * 2;
        const __half* ga = Ap + (size_t)(n0 + aR) * 512 + k0 + aC;
        cpa16(sa, ga); cpa16(sa + 16, ga + 8);
        if (vAct) {
            unsigned sv = bVh + s * VSTR + vR * 208 + vC * 2;
            const __half* gv = Vhp + (size_t)(k0 + vR) * 96 + vC;
            cpa16(sv, gv); cpa16(sv + 16, gv + 8);
        }
        cpcommit();
    };

    float c[4][3][4];
#pragma unroll
    for (int i = 0; i < 4; i++)
#pragma unroll
        for (int j = 0; j < 3; j++)
#pragma unroll
            for (int q = 0; q < 4; q++) c[i][j][q] = 0.f;

    const unsigned aOff = (wm * 64 + (lane & 15)) * 80 + (lane >> 4) * 16;
    const unsigned vOff = (lane & 15) * 208 + (wn * 24 + (lane >> 4) * 8) * 2;
    const unsigned vOff2 = (lane & 15) * 208 + (wn * 24 + 16) * 2;

    issue(0, 0); issue(1, 1);

    for (int kt = 0; kt < 16; kt++) {
        cpwait<1>();
        __syncthreads();
        const int s = kt % 3;
        const unsigned aB = bA + s * ASTR + aOff;
        const unsigned vH = bVh + s * VSTR;

#pragma unroll
        for (int k16 = 0; k16 < 2; k16++) {
            unsigned ah[4][4], bh[3][2], t0, t1, t2, t3;
#pragma unroll
            for (int mf = 0; mf < 4; mf++)
                ldsm4(ah[mf], aB + mf * 1280 + k16 * 32);
            ldsm4t(t0, t1, t2, t3, vH + vOff + k16 * 3328);
            bh[0][0] = t0; bh[0][1] = t1; bh[1][0] = t2; bh[1][1] = t3;
            ldsm2t(t0, t1, vH + vOff2 + k16 * 3328);
            bh[2][0] = t0; bh[2][1] = t1;

#pragma unroll
            for (int mf = 0; mf < 4; mf++)
#pragma unroll
                for (int nf = 0; nf < 3; nf++)
                    mmaf16(c[mf][nf], ah[mf], bh[nf][0], bh[nf][1]);
        }
        const int kn = kt + 2;
        if (kn < 16) issue(kn, kn % 3); else cpcommit();
    }

    const int b = bl >> 4, l = bl & 15;
#pragma unroll
    for (int mf = 0; mf < 4; mf++)
#pragma unroll
        for (int q2 = 0; q2 < 2; q2++) {
            const int n = n0 + wm * 64 + mf * 16 + gid + q2 * 8;
#pragma unroll
            for (int nf = 0; nf < 3; nf++) {
                const int d = wn * 24 + nf * 8 + tig * 2;
                const size_t idx = ((size_t)(b * 512 + n)) * 1536 + l * 96 + d;
                *(__half2*)(g_Oh + idx) =
                    __halves2half2(__float2half_rn(c[mf][nf][q2 * 2 + 0]),
                                   __float2half_rn(c[mf][nf][q2 * 2 + 1]));
            }
        }
}

// ---------------------------------------------------------------------------
extern "C" void kernel_launch(void* const* d_in, const int* in_sizes, int n_in,
                              void* d_out, int out_size)
{
    const float* x     = (const float*)d_in[0];
    const float* ebias = (const float*)d_in[1];
    const float* eps   = (const float*)d_in[2];
    const float* Wq    = (const float*)d_in[3];
    const float* Wk    = (const float*)d_in[4];
    const float* Wv    = (const float*)d_in[5];
    const float* bv    = (const float*)d_in[6];
    const float* sigma = (const float*)d_in[7];
    const float* p     = (const float*)d_in[8];
    const float* Wout  = (const float*)d_in[9];
    float* out = (float*)d_out;

    __half *xh, *wqkv, *woh, *qh, *kh, *kl, *vh, *oh;
    cudaGetSymbolAddress((void**)&xh,   g_xh);
    cudaGetSymbolAddress((void**)&wqkv, g_wqkv);
    cudaGetSymbolAddress((void**)&woh,  g_woh);
    cudaGetSymbolAddress((void**)&qh,   g_Qh);
    cudaGetSymbolAddress((void**)&kh,   g_Kh);
    cudaGetSymbolAddress((void**)&kl,   g_Kl);
    cudaGetSymbolAddress((void**)&vh,   g_Vh);
    cudaGetSymbolAddress((void**)&oh,   g_Oh);

    const int SM_1 = 3 * ASTR + 3 * BSTR;   // 56832
    const int SM_S = 9 * ASTR;              // 92160
    const int SM_O = 3 * ASTR + 3 * VSTR;   // 50688

    cudaFuncSetAttribute(gemm16<1, 1>,
        cudaFuncAttributeMaxDynamicSharedMemorySize, SM_1);
    cudaFuncSetAttribute(gemm16<1, 0>,
        cudaFuncAttributeMaxDynamicSharedMemorySize, SM_1);
    cudaFuncSetAttribute(scores16,
        cudaFuncAttributeMaxDynamicSharedMemorySize, SM_S);
    cudaFuncSetAttribute(outv16,
        cudaFuncAttributeMaxDynamicSharedMemorySize, SM_O);

    // splits
    split1k<<<6144, 256>>>((const float4*)x, xh, 1572864);
    splitQK<<<576, 256>>>((const float4*)Wq, (const float4*)Wk, wqkv);
    splitV<<<1152, 256>>>((const float4*)Wv, wqkv);
    split1k<<<1152, 256>>>((const float4*)Wout, woh, 294912);

    // merged Q+K+V projection: 1-term, N=3072
    gemm16<1, 1><<<dim3(24, 64), 256, SM_1>>>(
        xh, wqkv, nullptr, bv, qh, kh, kl, vh, nullptr, 768, 3072);

    // scores: 2-term (qh . (kh+kl)) + sigma^2*eps -> fp16 S
    scores16<<<dim3(4, 4, 128), 256, SM_S>>>(eps, sigma);

    // mix + mish + softmax -> A fp16
    mix_softmax_kernel<<<Bb * Nn, 512>>>(ebias, p);

    // O = A @ V (1-term), fp16 store
    outv16<<<dim3(4, 256), 256, SM_O>>>();

    // out proj: 1-term -> fp32 d_out
    gemm16<1, 0><<<dim3(6, 64), 256, SM_1>>>(
        oh, woh, nullptr, nullptr, nullptr, nullptr, nullptr, nullptr, out, 1536, 768);
}

// round 12
// speedup vs baseline: 1.7190x; 1.0831x over previous
#include <cuda_runtime.h>
#include <cuda_fp16.h>
#include <math.h>

#define Bb 16
#define Nn 512
#define Dd 96
#define PGRID 592

// ---------------- scratch -------------------------------------------------
__device__ __half g_xh  [(size_t)8192 * 768];
__device__ __half g_wqkv[(size_t)768 * 3072];    // [k][ Wq | Wk | Wv ]
__device__ __half g_woh [(size_t)1536 * 768];
__device__ __half g_Qh[(size_t)128 * 512 * 96];
__device__ __half g_Kh[(size_t)128 * 512 * 96];
__device__ __half g_Kl[(size_t)128 * 512 * 96];
__device__ __half g_Vh[(size_t)256 * 512 * 96];
__device__ __half g_S [(size_t)128 * 512 * 512];
__device__ __half g_Ah[(size_t)256 * 512 * 512];
__device__ __half g_Oh[(size_t)8192 * 1536];

// ---------------- helpers --------------------------------------------------
__device__ __forceinline__ unsigned sptr(const void* p) {
    return (unsigned)__cvta_generic_to_shared(p);
}
__device__ __forceinline__ void cpa16(unsigned s, const void* g) {
    asm volatile("cp.async.cg.shared.global [%0], [%1], 16;" :: "r"(s), "l"(g));
}
__device__ __forceinline__ void cpcommit() {
    asm volatile("cp.async.commit_group;");
}
template<int W> __device__ __forceinline__ void cpwait() {
    asm volatile("cp.async.wait_group %0;" :: "n"(W));
}
__device__ __forceinline__ void ldsm4(unsigned f[4], unsigned a) {
    asm volatile("ldmatrix.sync.aligned.m8n8.x4.shared.b16 {%0,%1,%2,%3}, [%4];"
                 : "=r"(f[0]), "=r"(f[1]), "=r"(f[2]), "=r"(f[3]) : "r"(a));
}
__device__ __forceinline__ void ldsm4t(unsigned& r0, unsigned& r1, unsigned& r2,
                                       unsigned& r3, unsigned a) {
    asm volatile("ldmatrix.sync.aligned.m8n8.x4.trans.shared.b16 {%0,%1,%2,%3}, [%4];"
                 : "=r"(r0), "=r"(r1), "=r"(r2), "=r"(r3) : "r"(a));
}
__device__ __forceinline__ void ldsm2t(unsigned& r0, unsigned& r1, unsigned a) {
    asm volatile("ldmatrix.sync.aligned.m8n8.x2.trans.shared.b16 {%0,%1}, [%2];"
                 : "=r"(r0), "=r"(r1) : "r"(a));
}
__device__ __forceinline__ void mmaf16(float c[4], const unsigned a[4],
                                       unsigned b0, unsigned b1) {
    asm volatile(
        "mma.sync.aligned.m16n8k16.row.col.f32.f16.f16.f32 "
        "{%0,%1,%2,%3}, {%4,%5,%6,%7}, {%8,%9}, {%0,%1,%2,%3};"
        : "+f"(c[0]), "+f"(c[1]), "+f"(c[2]), "+f"(c[3])
        : "r"(a[0]), "r"(a[1]), "r"(a[2]), "r"(a[3]), "r"(b0), "r"(b1));
}
__device__ __forceinline__ void hsplit(float v, __half& h, __half& l) {
    h = __float2half_rn(v);
    l = __float2half_rn(v - __half2float(h));
}

// ---------------- fused input split (x, Wq, Wk, Wv, Wout in one launch) ----
__global__ void __launch_bounds__(256) splitAll(
    const float4* __restrict__ x, const float4* __restrict__ Wq,
    const float4* __restrict__ Wk, const float4* __restrict__ Wv,
    const float4* __restrict__ Wout)
{
    int i = blockIdx.x * 256 + threadIdx.x;
    if (i < 1572864) {
        float4 v = x[i];
        ((__half2*)g_xh)[i * 2]     = __halves2half2(__float2half_rn(v.x), __float2half_rn(v.y));
        ((__half2*)g_xh)[i * 2 + 1] = __halves2half2(__float2half_rn(v.z), __float2half_rn(v.w));
    } else if (i < 1720320) {
        int j = i - 1572864;
        int row = j / 192, col = (j % 192) * 4;
        float4 v = Wq[j];
        __half2* d = (__half2*)(g_wqkv + (size_t)row * 3072 + col);
        d[0] = __halves2half2(__float2half_rn(v.x), __float2half_rn(v.y));
        d[1] = __halves2half2(__float2half_rn(v.z), __float2half_rn(v.w));
    } else if (i < 1867776) {
        int j = i - 1720320;
        int row = j / 192, col = (j % 192) * 4;
        float4 v = Wk[j];
        __half2* d = (__half2*)(g_wqkv + (size_t)row * 3072 + 768 + col);
        d[0] = __halves2half2(__float2half_rn(v.x), __float2half_rn(v.y));
        d[1] = __halves2half2(__float2half_rn(v.z), __float2half_rn(v.w));
    } else if (i < 2162688) {
        int j = i - 1867776;
        int row = j / 384, col = (j % 384) * 4;
        float4 v = Wv[j];
        __half2* d = (__half2*)(g_wqkv + (size_t)row * 3072 + 1536 + col);
        d[0] = __halves2half2(__float2half_rn(v.x), __float2half_rn(v.y));
        d[1] = __halves2half2(__float2half_rn(v.z), __float2half_rn(v.w));
    } else if (i < 2457600) {
        int j = i - 2162688;
        float4 v = Wout[j];
        ((__half2*)g_woh)[j * 2]     = __halves2half2(__float2half_rn(v.x), __float2half_rn(v.y));
        ((__half2*)g_woh)[j * 2 + 1] = __halves2half2(__float2half_rn(v.z), __float2half_rn(v.w));
    }
}

// ---------------------------------------------------------------------------
// Persistent GEMM: C = A[MxK] @ B[KxN]. BM=128 BN=128 BK=32, 3-stage cp.async.
// MODE 0: fp32 rowmajor (outF).  MODE 1: QKV merged epilogue.
// ---------------------------------------------------------------------------
#define ASTR 10240          // 128 rows * 80B
#define BSTR 8704           // 32 rows * 272B

template<int MODE>
__global__ void __launch_bounds__(256, 2) gemm16(
    const __half* __restrict__ Agh, const __half* __restrict__ Bgh,
    const float* __restrict__ bias,
    __half* __restrict__ o0, __half* __restrict__ o1, __half* __restrict__ o2,
    __half* __restrict__ o3, float* __restrict__ outF,
    int K, int N, int tilesX, int nTiles)
{
    extern __shared__ char smem[];
    __half* sA = (__half*)smem;
    __half* sBh = (__half*)(smem + 3 * ASTR);

    const int tid = threadIdx.x;
    const int lane = tid & 31, warp = tid >> 5;
    const int wm = warp >> 2, wn = warp & 3;
    const int gid = lane >> 2, tig = lane & 3;

    const int aR = tid >> 1, aC = (tid & 1) * 16;
    const int bR = tid >> 3, bC = (tid & 7) * 16;
    const unsigned sAb = sptr(sA), sBhb = sptr(sBh);
    const unsigned aOff = (wm * 64 + (lane & 15)) * 80 + (lane >> 4) * 16;
    const unsigned bOff = (lane & 15) * 272 + (wn * 32 + (lane >> 4) * 8) * 2;
    const int KT = K >> 5;

    for (int tile = blockIdx.x; tile < nTiles; tile += PGRID) {
        const int m0 = (tile / tilesX) * 128;
        const int n0 = (tile % tilesX) * 128;

        auto issue = [&](int kt, int s) {
            const int k0 = kt << 5;
            const __half* ga = Agh + (size_t)(m0 + aR) * K + k0 + aC;
            unsigned sa = sAb + s * ASTR + aR * 80 + aC * 2;
            cpa16(sa, ga); cpa16(sa + 16, ga + 8);
            const __half* gb = Bgh + (size_t)(k0 + bR) * N + n0 + bC;
            unsigned sb = sBhb + s * BSTR + bR * 272 + bC * 2;
            cpa16(sb, gb); cpa16(sb + 16, gb + 8);
            cpcommit();
        };

        float c[4][4][4];
#pragma unroll
        for (int i = 0; i < 4; i++)
#pragma unroll
            for (int j = 0; j < 4; j++)
#pragma unroll
                for (int q = 0; q < 4; q++) c[i][j][q] = 0.f;

        issue(0, 0); issue(1, 1);

        for (int kt = 0; kt < KT; kt++) {
            cpwait<1>();
            __syncthreads();
            const int s = kt % 3;
            const unsigned aB = sAb + s * ASTR + aOff;
            const unsigned bB = sBhb + s * BSTR + bOff;

#pragma unroll
            for (int k16 = 0; k16 < 2; k16++) {
                unsigned ah[4][4], bh[4][2], t0, t1, t2, t3;
#pragma unroll
                for (int mf = 0; mf < 4; mf++)
                    ldsm4(ah[mf], aB + mf * 1280 + k16 * 32);
#pragma unroll
                for (int nf2 = 0; nf2 < 2; nf2++) {
                    ldsm4t(t0, t1, t2, t3, bB + k16 * 4352 + nf2 * 32);
                    bh[nf2 * 2][0] = t0; bh[nf2 * 2][1] = t1;
                    bh[nf2 * 2 + 1][0] = t2; bh[nf2 * 2 + 1][1] = t3;
                }
#pragma unroll
                for (int mf = 0; mf < 4; mf++)
#pragma unroll
                    for (int nf = 0; nf < 4; nf++)
                        mmaf16(c[mf][nf], ah[mf], bh[nf][0], bh[nf][1]);
            }
            const int kn = kt + 2;
            if (kn < KT) issue(kn, kn % 3); else cpcommit();
        }

#pragma unroll
        for (int mf = 0; mf < 4; mf++)
#pragma unroll
            for (int q2 = 0; q2 < 2; q2++) {
                const int row = m0 + wm * 64 + mf * 16 + gid + q2 * 8;
                const int b = row >> 9, n = row & 511;
#pragma unroll
                for (int nf = 0; nf < 4; nf++) {
                    const int col = n0 + wn * 32 + nf * 8 + tig * 2;
                    float v0 = c[mf][nf][q2 * 2 + 0];
                    float v1 = c[mf][nf][q2 * 2 + 1];
                    if (MODE == 0) {
                        *(float2*)(outF + (size_t)row * N + col) = make_float2(v0, v1);
                    } else {
                        if (col < 768) {
                            const int h = col / 96, d = col - h * 96;
                            const size_t idx = (((size_t)(b * 8 + h)) * 512 + n) * 96 + d;
                            *(__half2*)(o0 + idx) =
                                __halves2half2(__float2half_rn(v0), __float2half_rn(v1));
                        } else if (col < 1536) {
                            const int cc = col - 768;
                            const int h = cc / 96, d = cc - h * 96;
                            const size_t idx = (((size_t)(b * 8 + h)) * 512 + n) * 96 + d;
                            __half h0, h1, l0, l1;
                            hsplit(v0, h0, l0); hsplit(v1, h1, l1);
                            *(__half2*)(o1 + idx) = __halves2half2(h0, h1);
                            *(__half2*)(o2 + idx) = __halves2half2(l0, l1);
                        } else {
                            const int cc = col - 1536;
                            const int h = cc / 96, d = cc - h * 96;
                            v0 += bias[cc]; v1 += bias[cc + 1];
                            const size_t idx = (((size_t)(b * 16 + h)) * 512 + n) * 96 + d;
                            *(__half2*)(o3 + idx) =
                                __halves2half2(__float2half_rn(v0), __float2half_rn(v1));
                        }
                    }
                }
            }
        __syncthreads();   // stage reuse guard across tiles
    }
}

// ---------------------------------------------------------------------------
// Persistent scores: S = Q.K^T + sigma^2*eps (fp16).  Q single, K dual 2-term.
// tiles: 128 bg x 4 x 4 = 2048
// ---------------------------------------------------------------------------
__global__ void __launch_bounds__(256, 2) scores16(
    const float* __restrict__ eps, const float* __restrict__ sigma)
{
    extern __shared__ char smem[];
    __half* sQ  = (__half*)smem;
    __half* sKh = (__half*)(smem + 3 * ASTR);
    __half* sKl = (__half*)(smem + 6 * ASTR);

    const int tid = threadIdx.x;
    const int lane = tid & 31, warp = tid >> 5;
    const int wm = warp >> 2, wn = warp & 3;
    const int gid = lane >> 2, tig = lane & 3;

    const int aR = tid >> 1, aC = (tid & 1) * 16;
    const unsigned bQ = sptr(sQ), bKh = sptr(sKh), bKl = sptr(sKl);
    const unsigned aOff = (wm * 64 + (lane & 15)) * 80 + (lane >> 4) * 16;
    const unsigned kOff = (wn * 32 + (lane & 15)) * 80 + (lane >> 4) * 16;

    for (int tile = blockIdx.x; tile < 2048; tile += PGRID) {
        const int bg = tile >> 4;
        const int sn0 = ((tile >> 2) & 3) * 128, sm0 = (tile & 3) * 128;
        const __half* Qp  = g_Qh + (size_t)bg * Nn * Dd;
        const __half* Khp = g_Kh + (size_t)bg * Nn * Dd;
        const __half* Klp = g_Kl + (size_t)bg * Nn * Dd;

        auto issue = [&](int kt, int s) {
            const int k0 = kt << 5;
            unsigned so = s * ASTR + aR * 80 + aC * 2;
            size_t go = (size_t)aR * 96 + k0 + aC;
            cpa16(bQ + so, Qp + (size_t)sn0 * 96 + go);
            cpa16(bQ + so + 16, Qp + (size_t)sn0 * 96 + go + 8);
            cpa16(bKh + so, Khp + (size_t)sm0 * 96 + go);
            cpa16(bKh + so + 16, Khp + (size_t)sm0 * 96 + go + 8);
            cpa16(bKl + so, Klp + (size_t)sm0 * 96 + go);
            cpa16(bKl + so + 16, Klp + (size_t)sm0 * 96 + go + 8);
            cpcommit();
        };

        float c[4][4][4];
#pragma unroll
        for (int i = 0; i < 4; i++)
#pragma unroll
            for (int j = 0; j < 4; j++)
#pragma unroll
                for (int q = 0; q < 4; q++) c[i][j][q] = 0.f;

        issue(0, 0); issue(1, 1);

        for (int kt = 0; kt < 3; kt++) {
            cpwait<1>();
            __syncthreads();
            const unsigned aB = bQ + kt * ASTR + aOff;
            const unsigned kH = bKh + kt * ASTR + kOff;
            const unsigned kL = bKl + kt * ASTR + kOff;

#pragma unroll
            for (int k16 = 0; k16 < 2; k16++) {
                unsigned ah[4][4], f[4], bh[4][2], bl[4][2];
#pragma unroll
                for (int mf = 0; mf < 4; mf++)
                    ldsm4(ah[mf], aB + mf * 1280 + k16 * 32);
#pragma unroll
                for (int nf2 = 0; nf2 < 2; nf2++) {
                    ldsm4(f, kH + nf2 * 1280 + k16 * 32);
                    bh[nf2 * 2][0] = f[0]; bh[nf2 * 2][1] = f[2];
                    bh[nf2 * 2 + 1][0] = f[1]; bh[nf2 * 2 + 1][1] = f[3];
                    ldsm4(f, kL + nf2 * 1280 + k16 * 32);
                    bl[nf2 * 2][0] = f[0]; bl[nf2 * 2][1] = f[2];
                    bl[nf2 * 2 + 1][0] = f[1]; bl[nf2 * 2 + 1][1] = f[3];
                }
#pragma unroll
                for (int mf = 0; mf < 4; mf++)
#pragma unroll
                    for (int nf = 0; nf < 4; nf++) {
                        mmaf16(c[mf][nf], ah[mf], bh[nf][0], bh[nf][1]);
                        mmaf16(c[mf][nf], ah[mf], bl[nf][0], bl[nf][1]);
                    }
            }
            const int kn = kt + 2;
            if (kn < 3) issue(kn, kn); else cpcommit();
        }

        float s2 = sigma[bg & 7];
        s2 = s2 * s2;
#pragma unroll
        for (int mf = 0; mf < 4; mf++)
#pragma unroll
            for (int q2 = 0; q2 < 2; q2++) {
                const int n = sn0 + wm * 64 + mf * 16 + gid + q2 * 8;
#pragma unroll
                for (int nf = 0; nf < 4; nf++) {
                    const int m = sm0 + wn * 32 + nf * 8 + tig * 2;
                    const size_t idx = ((size_t)bg * Nn + n) * Nn + m;
                    float2 ev = *(const float2*)(eps + idx);
                    *(__half2*)(g_S + idx) = __halves2half2(
                        __float2half_rn(c[mf][nf][q2 * 2 + 0] + s2 * ev.x),
                        __float2half_rn(c[mf][nf][q2 * 2 + 1] + s2 * ev.y));
                }
            }
        __syncthreads();
    }
}

// ---------------------------------------------------------------------------
// Mix + mish + softmax (max-free; logits provably bounded ~|12|) -> A fp16.
// ---------------------------------------------------------------------------
__global__ void __launch_bounds__(512) mix_softmax_kernel(
    const float* __restrict__ encoding_bias, const float* __restrict__ p)
{
    int bn = blockIdx.x;
    int b = bn >> 9, n = bn & 511;
    int tid = threadIdx.x;
    int lane = tid & 31, warp = tid >> 5;

    __shared__ float ps[128];
    __shared__ float red[16][17];
    __shared__ float rsum[16];

    if (tid < 128) ps[tid] = p[tid];
    __syncthreads();

    float s[8];
#pragma unroll
    for (int g = 0; g < 8; g++)
        s[g] = __half2float(g_S[(((size_t)(b * 8 + g)) * 512 + n) * 512 + tid]);
    float bias = encoding_bias[((size_t)bn) * 512 + tid];
    const float scale = 0.03608439182435161f;

    float vals[16];
#pragma unroll
    for (int l = 0; l < 16; l++) {
        float t = 0.f;
#pragma unroll
        for (int g = 0; g < 8; g++) t = fmaf(s[g], ps[g * 16 + l], t);
        float e = __expf(fminf(t, 15.f));
        float num = e * (e + 2.f);
        float logit = t * (num / (num + 2.f)) * scale + bias;
        vals[l] = __expf(logit);              // max-free: logits bounded ~12
    }

#pragma unroll
    for (int l = 0; l < 16; l++) {
        float v = vals[l];
#pragma unroll
        for (int o = 16; o > 0; o >>= 1)
            v += __shfl_xor_sync(0xffffffffu, v, o);
        if (lane == 0) red[l][warp] = v;
    }
    __syncthreads();
    {
        float v = (lane < 16) ? red[warp][lane] : 0.f;
#pragma unroll
        for (int o = 8; o > 0; o >>= 1)
            v += __shfl_xor_sync(0xffffffffu, v, o);
        if (lane == 0) rsum[warp] = v;
    }
    __syncthreads();
#pragma unroll
    for (int l = 0; l < 16; l++)
        g_Ah[(((size_t)(b * 16 + l)) * 512 + n) * 512 + tid] =
            __float2half_rn(vals[l] / rsum[l]);
}

// ---------------------------------------------------------------------------
// Persistent outv: O = A @ V per (b,l).  tiles = 4 x 256 = 1024.
// ---------------------------------------------------------------------------
#define VSTR 6656          // 32 rows * 208B

__global__ void __launch_bounds__(256, 2) outv16()
{
    extern __shared__ char smem[];
    __half* sA = (__half*)smem;
    __half* sVh = (__half*)(smem + 3 * ASTR);

    const int tid = threadIdx.x;
    const int lane = tid & 31, warp = tid >> 5;
    const int wm = warp >> 2, wn = warp & 3;
    const int gid = lane >> 2, tig = lane & 3;

    const int aR = tid >> 1, aC = (tid & 1) * 16;
    const int vR = tid / 6, vC = (tid % 6) * 16;
    const bool vAct = tid < 192;
    const unsigned bA = sptr(sA), bVh = sptr(sVh);
    const unsigned aOff = (wm * 64 + (lane & 15)) * 80 + (lane >> 4) * 16;
    const unsigned vOff = (lane & 15) * 208 + (wn * 24 + (lane >> 4) * 8) * 2;
    const unsigned vOff2 = (lane & 15) * 208 + (wn * 24 + 16) * 2;

    for (int tile = blockIdx.x; tile < 1024; tile += PGRID) {
        const int bl = tile >> 2;
        const int n0 = (tile & 3) * 128;
        const __half* Ap = g_Ah + (size_t)bl * Nn * Nn;
        const __half* Vhp = g_Vh + (size_t)bl * Nn * Dd;

        auto issue = [&](int kt, int s) {
            const int k0 = kt << 5;
            unsigned sa = bA + s * ASTR + aR * 80 + aC * 2;
            const __half* ga = Ap + (size_t)(n0 + aR) * 512 + k0 + aC;
            cpa16(sa, ga); cpa16(sa + 16, ga + 8);
            if (vAct) {
                unsigned sv = bVh + s * VSTR + vR * 208 + vC * 2;
                const __half* gv = Vhp + (size_t)(k0 + vR) * 96 + vC;
                cpa16(sv, gv); cpa16(sv + 16, gv + 8);
            }
            cpcommit();
        };

        float c[4][3][4];
#pragma unroll
        for (int i = 0; i < 4; i++)
#pragma unroll
            for (int j = 0; j < 3; j++)
#pragma unroll
                for (int q = 0; q < 4; q++) c[i][j][q] = 0.f;

        issue(0, 0); issue(1, 1);

        for (int kt = 0; kt < 16; kt++) {
            cpwait<1>();
            __syncthreads();
            const int s = kt % 3;
            const unsigned aB = bA + s * ASTR + aOff;
            const unsigned vH = bVh + s * VSTR;

#pragma unroll
            for (int k16 = 0; k16 < 2; k16++) {
                unsigned ah[4][4], bh[3][2], t0, t1, t2, t3;
#pragma unroll
                for (int mf = 0; mf < 4; mf++)
                    ldsm4(ah[mf], aB + mf * 1280 + k16 * 32);
                ldsm4t(t0, t1, t2, t3, vH + vOff + k16 * 3328);
                bh[0][0] = t0; bh[0][1] = t1; bh[1][0] = t2; bh[1][1] = t3;
                ldsm2t(t0, t1, vH + vOff2 + k16 * 3328);
                bh[2][0] = t0; bh[2][1] = t1;

#pragma unroll
                for (int mf = 0; mf < 4; mf++)
#pragma unroll
                    for (int nf = 0; nf < 3; nf++)
                        mmaf16(c[mf][nf], ah[mf], bh[nf][0], bh[nf][1]);
            }
            const int kn = kt + 2;
            if (kn < 16) issue(kn, kn % 3); else cpcommit();
        }

        const int b = bl >> 4, l = bl & 15;
#pragma unroll
        for (int mf = 0; mf < 4; mf++)
#pragma unroll
            for (int q2 = 0; q2 < 2; q2++) {
                const int n = n0 + wm * 64 + mf * 16 + gid + q2 * 8;
#pragma unroll
                for (int nf = 0; nf < 3; nf++) {
                    const int d = wn * 24 + nf * 8 + tig * 2;
                    const size_t idx = ((size_t)(b * 512 + n)) * 1536 + l * 96 + d;
                    *(__half2*)(g_Oh + idx) =
                        __halves2half2(__float2half_rn(c[mf][nf][q2 * 2 + 0]),
                                       __float2half_rn(c[mf][nf][q2 * 2 + 1]));
                }
            }
        __syncthreads();   // stage reuse guard (KT=16 -> last stage == 0)
    }
}

// ---------------------------------------------------------------------------
extern "C" void kernel_launch(void* const* d_in, const int* in_sizes, int n_in,
                              void* d_out, int out_size)
{
    const float* x     = (const float*)d_in[0];
    const float* ebias = (const float*)d_in[1];
    const float* eps   = (const float*)d_in[2];
    const float* Wq    = (const float*)d_in[3];
    const float* Wk    = (const float*)d_in[4];
    const float* Wv    = (const float*)d_in[5];
    const float* bv    = (const float*)d_in[6];
    const float* sigma = (const float*)d_in[7];
    const float* p     = (const float*)d_in[8];
    const float* Wout  = (const float*)d_in[9];
    float* out = (float*)d_out;

    __half *xh, *wqkv, *woh, *qh, *kh, *kl, *vh, *oh;
    cudaGetSymbolAddress((void**)&xh,   g_xh);
    cudaGetSymbolAddress((void**)&wqkv, g_wqkv);
    cudaGetSymbolAddress((void**)&woh,  g_woh);
    cudaGetSymbolAddress((void**)&qh,   g_Qh);
    cudaGetSymbolAddress((void**)&kh,   g_Kh);
    cudaGetSymbolAddress((void**)&kl,   g_Kl);
    cudaGetSymbolAddress((void**)&vh,   g_Vh);
    cudaGetSymbolAddress((void**)&oh,   g_Oh);

    const int SM_1 = 3 * ASTR + 3 * BSTR;   // 56832
    const int SM_S = 9 * ASTR;              // 92160
    const int SM_O = 3 * ASTR + 3 * VSTR;   // 50688

    cudaFuncSetAttribute(gemm16<1>,
        cudaFuncAttributeMaxDynamicSharedMemorySize, SM_1);
    cudaFuncSetAttribute(gemm16<0>,
        cudaFuncAttributeMaxDynamicSharedMemorySize, SM_1);
    cudaFuncSetAttribute(scores16,
        cudaFuncAttributeMaxDynamicSharedMemorySize, SM_S);
    cudaFuncSetAttribute(outv16,
        cudaFuncAttributeMaxDynamicSharedMemorySize, SM_O);

    // fused input splits (x, Wq, Wk, Wv, Wout)
    splitAll<<<9600, 256>>>((const float4*)x, (const float4*)Wq,
                            (const float4*)Wk, (const float4*)Wv,
                            (const float4*)Wout);

    // merged Q+K+V projection: persistent, tiles 24x64
    gemm16<1><<<PGRID, 256, SM_1>>>(
        xh, wqkv, bv, qh, kh, kl, vh, nullptr, 768, 3072, 24, 1536);

    // scores: persistent, 2-term + sigma^2*eps -> fp16 S
    scores16<<<PGRID, 256, SM_S>>>(eps, sigma);

    // mix + mish + softmax (max-free) -> A fp16
    mix_softmax_kernel<<<Bb * Nn, 512>>>(ebias, p);

    // O = A @ V: persistent
    outv16<<<PGRID, 256, SM_O>>>();

    // out proj: persistent, tiles 6x64 -> fp32 d_out
    gemm16<0><<<PGRID, 256, SM_1>>>(
        oh, woh, nullptr, nullptr, nullptr, nullptr, nullptr, out, 1536, 768, 6, 384);
}

// round 13
// speedup vs baseline: 1.9246x; 1.1196x over previous
#include <cuda_runtime.h>
#include <cuda_fp16.h>
#include <math.h>

#define Bb 16
#define Nn 512
#define Dd 96
#define PGRID 592

// ---------------- scratch -------------------------------------------------
__device__ __half g_xh  [(size_t)8192 * 768];
__device__ __half g_wqkv[(size_t)768 * 3072];    // [k][ Wq | Wk | Wv ]
__device__ __half g_woh [(size_t)1536 * 768];
__device__ __half g_Qh[(size_t)128 * 512 * 96];
__device__ __half g_Kh[(size_t)128 * 512 * 96];
__device__ __half g_Kl[(size_t)128 * 512 * 96];
__device__ __half g_Vh[(size_t)256 * 512 * 96];
__device__ __half g_S [(size_t)128 * 512 * 512];
__device__ __half g_Ah[(size_t)256 * 512 * 512];
__device__ __half g_Oh[(size_t)8192 * 1536];

// ---------------- helpers --------------------------------------------------
__device__ __forceinline__ unsigned sptr(const void* p) {
    return (unsigned)__cvta_generic_to_shared(p);
}
__device__ __forceinline__ void cpa16(unsigned s, const void* g) {
    asm volatile("cp.async.cg.shared.global [%0], [%1], 16;" :: "r"(s), "l"(g));
}
__device__ __forceinline__ void cpcommit() {
    asm volatile("cp.async.commit_group;");
}
template<int W> __device__ __forceinline__ void cpwait() {
    asm volatile("cp.async.wait_group %0;" :: "n"(W));
}
__device__ __forceinline__ void ldsm4(unsigned f[4], unsigned a) {
    asm volatile("ldmatrix.sync.aligned.m8n8.x4.shared.b16 {%0,%1,%2,%3}, [%4];"
                 : "=r"(f[0]), "=r"(f[1]), "=r"(f[2]), "=r"(f[3]) : "r"(a));
}
__device__ __forceinline__ void ldsm4t(unsigned& r0, unsigned& r1, unsigned& r2,
                                       unsigned& r3, unsigned a) {
    asm volatile("ldmatrix.sync.aligned.m8n8.x4.trans.shared.b16 {%0,%1,%2,%3}, [%4];"
                 : "=r"(r0), "=r"(r1), "=r"(r2), "=r"(r3) : "r"(a));
}
__device__ __forceinline__ void ldsm2t(unsigned& r0, unsigned& r1, unsigned a) {
    asm volatile("ldmatrix.sync.aligned.m8n8.x2.trans.shared.b16 {%0,%1}, [%2];"
                 : "=r"(r0), "=r"(r1) : "r"(a));
}
__device__ __forceinline__ void mmaf16(float c[4], const unsigned a[4],
                                       unsigned b0, unsigned b1) {
    asm volatile(
        "mma.sync.aligned.m16n8k16.row.col.f32.f16.f16.f32 "
        "{%0,%1,%2,%3}, {%4,%5,%6,%7}, {%8,%9}, {%0,%1,%2,%3};"
        : "+f"(c[0]), "+f"(c[1]), "+f"(c[2]), "+f"(c[3])
        : "r"(a[0]), "r"(a[1]), "r"(a[2]), "r"(a[3]), "r"(b0), "r"(b1));
}
__device__ __forceinline__ void hsplit(float v, __half& h, __half& l) {
    h = __float2half_rn(v);
    l = __float2half_rn(v - __half2float(h));
}

// ---------------- fused input split (x, Wq, Wk, Wv, Wout in one launch) ----
__global__ void __launch_bounds__(256) splitAll(
    const float4* __restrict__ x, const float4* __restrict__ Wq,
    const float4* __restrict__ Wk, const float4* __restrict__ Wv,
    const float4* __restrict__ Wout)
{
    int i = blockIdx.x * 256 + threadIdx.x;
    if (i < 1572864) {
        float4 v = x[i];
        ((__half2*)g_xh)[i * 2]     = __halves2half2(__float2half_rn(v.x), __float2half_rn(v.y));
        ((__half2*)g_xh)[i * 2 + 1] = __halves2half2(__float2half_rn(v.z), __float2half_rn(v.w));
    } else if (i < 1720320) {
        int j = i - 1572864;
        int row = j / 192, col = (j % 192) * 4;
        float4 v = Wq[j];
        __half2* d = (__half2*)(g_wqkv + (size_t)row * 3072 + col);
        d[0] = __halves2half2(__float2half_rn(v.x), __float2half_rn(v.y));
        d[1] = __halves2half2(__float2half_rn(v.z), __float2half_rn(v.w));
    } else if (i < 1867776) {
        int j = i - 1720320;
        int row = j / 192, col = (j % 192) * 4;
        float4 v = Wk[j];
        __half2* d = (__half2*)(g_wqkv + (size_t)row * 3072 + 768 + col);
        d[0] = __halves2half2(__float2half_rn(v.x), __float2half_rn(v.y));
        d[1] = __halves2half2(__float2half_rn(v.z), __float2half_rn(v.w));
    } else if (i < 2162688) {
        int j = i - 1867776;
        int row = j / 384, col = (j % 384) * 4;
        float4 v = Wv[j];
        __half2* d = (__half2*)(g_wqkv + (size_t)row * 3072 + 1536 + col);
        d[0] = __halves2half2(__float2half_rn(v.x), __float2half_rn(v.y));
        d[1] = __halves2half2(__float2half_rn(v.z), __float2half_rn(v.w));
    } else if (i < 2457600) {
        int j = i - 2162688;
        float4 v = Wout[j];
        ((__half2*)g_woh)[j * 2]     = __halves2half2(__float2half_rn(v.x), __float2half_rn(v.y));
        ((__half2*)g_woh)[j * 2 + 1] = __halves2half2(__float2half_rn(v.z), __float2half_rn(v.w));
    }
}

// ---------------------------------------------------------------------------
// Persistent GEMM: C = A[MxK] @ B[KxN]. BM=128 BN=128 BK=32, 3-stage cp.async.
// MODE 0: fp32 rowmajor (outF).  MODE 1: QKV merged epilogue.
// ---------------------------------------------------------------------------
#define ASTR 10240          // 128 rows * 80B
#define BSTR 8704           // 32 rows * 272B

template<int MODE>
__global__ void __launch_bounds__(256, 2) gemm16(
    const __half* __restrict__ Agh, const __half* __restrict__ Bgh,
    const float* __restrict__ bias,
    __half* __restrict__ o0, __half* __restrict__ o1, __half* __restrict__ o2,
    __half* __restrict__ o3, float* __restrict__ outF,
    int K, int N, int tilesX, int nTiles)
{
    extern __shared__ char smem[];
    __half* sA = (__half*)smem;
    __half* sBh = (__half*)(smem + 3 * ASTR);

    const int tid = threadIdx.x;
    const int lane = tid & 31, warp = tid >> 5;
    const int wm = warp >> 2, wn = warp & 3;
    const int gid = lane >> 2, tig = lane & 3;

    const int aR = tid >> 1, aC = (tid & 1) * 16;
    const int bR = tid >> 3, bC = (tid & 7) * 16;
    const unsigned sAb = sptr(sA), sBhb = sptr(sBh);
    const unsigned aOff = (wm * 64 + (lane & 15)) * 80 + (lane >> 4) * 16;
    const unsigned bOff = (lane & 15) * 272 + (wn * 32 + (lane >> 4) * 8) * 2;
    const int KT = K >> 5;

    for (int tile = blockIdx.x; tile < nTiles; tile += PGRID) {
        const int m0 = (tile / tilesX) * 128;
        const int n0 = (tile % tilesX) * 128;

        auto issue = [&](int kt, int s) {
            const int k0 = kt << 5;
            const __half* ga = Agh + (size_t)(m0 + aR) * K + k0 + aC;
            unsigned sa = sAb + s * ASTR + aR * 80 + aC * 2;
            cpa16(sa, ga); cpa16(sa + 16, ga + 8);
            const __half* gb = Bgh + (size_t)(k0 + bR) * N + n0 + bC;
            unsigned sb = sBhb + s * BSTR + bR * 272 + bC * 2;
            cpa16(sb, gb); cpa16(sb + 16, gb + 8);
            cpcommit();
        };

        float c[4][4][4];
#pragma unroll
        for (int i = 0; i < 4; i++)
#pragma unroll
            for (int j = 0; j < 4; j++)
#pragma unroll
                for (int q = 0; q < 4; q++) c[i][j][q] = 0.f;

        issue(0, 0); issue(1, 1);

        for (int kt = 0; kt < KT; kt++) {
            cpwait<1>();
            __syncthreads();
            const int s = kt % 3;
            const unsigned aB = sAb + s * ASTR + aOff;
            const unsigned bB = sBhb + s * BSTR + bOff;

#pragma unroll
            for (int k16 = 0; k16 < 2; k16++) {
                unsigned ah[4][4], bh[4][2], t0, t1, t2, t3;
#pragma unroll
                for (int mf = 0; mf < 4; mf++)
                    ldsm4(ah[mf], aB + mf * 1280 + k16 * 32);
#pragma unroll
                for (int nf2 = 0; nf2 < 2; nf2++) {
                    ldsm4t(t0, t1, t2, t3, bB + k16 * 4352 + nf2 * 32);
                    bh[nf2 * 2][0] = t0; bh[nf2 * 2][1] = t1;
                    bh[nf2 * 2 + 1][0] = t2; bh[nf2 * 2 + 1][1] = t3;
                }
#pragma unroll
                for (int mf = 0; mf < 4; mf++)
#pragma unroll
                    for (int nf = 0; nf < 4; nf++)
                        mmaf16(c[mf][nf], ah[mf], bh[nf][0], bh[nf][1]);
            }
            const int kn = kt + 2;
            if (kn < KT) issue(kn, kn % 3); else cpcommit();
        }

#pragma unroll
        for (int mf = 0; mf < 4; mf++)
#pragma unroll
            for (int q2 = 0; q2 < 2; q2++) {
                const int row = m0 + wm * 64 + mf * 16 + gid + q2 * 8;
                const int b = row >> 9, n = row & 511;
#pragma unroll
                for (int nf = 0; nf < 4; nf++) {
                    const int col = n0 + wn * 32 + nf * 8 + tig * 2;
                    float v0 = c[mf][nf][q2 * 2 + 0];
                    float v1 = c[mf][nf][q2 * 2 + 1];
                    if (MODE == 0) {
                        *(float2*)(outF + (size_t)row * N + col) = make_float2(v0, v1);
                    } else {
                        if (col < 768) {
                            const int h = col / 96, d = col - h * 96;
                            const size_t idx = (((size_t)(b * 8 + h)) * 512 + n) * 96 + d;
                            *(__half2*)(o0 + idx) =
                                __halves2half2(__float2half_rn(v0), __float2half_rn(v1));
                        } else if (col < 1536) {
                            const int cc = col - 768;
                            const int h = cc / 96, d = cc - h * 96;
                            const size_t idx = (((size_t)(b * 8 + h)) * 512 + n) * 96 + d;
                            __half h0, h1, l0, l1;
                            hsplit(v0, h0, l0); hsplit(v1, h1, l1);
                            *(__half2*)(o1 + idx) = __halves2half2(h0, h1);
                            *(__half2*)(o2 + idx) = __halves2half2(l0, l1);
                        } else {
                            const int cc = col - 1536;
                            const int h = cc / 96, d = cc - h * 96;
                            v0 += bias[cc]; v1 += bias[cc + 1];
                            const size_t idx = (((size_t)(b * 16 + h)) * 512 + n) * 96 + d;
                            *(__half2*)(o3 + idx) =
                                __halves2half2(__float2half_rn(v0), __float2half_rn(v1));
                        }
                    }
                }
            }
        __syncthreads();   // stage reuse guard across tiles
    }
}

// ---------------------------------------------------------------------------
// Persistent scores: S = Q.K^T + sigma^2*eps (fp16).  Q single, K dual 2-term.
// tiles: 128 bg x 4 x 4 = 2048
// ---------------------------------------------------------------------------
__global__ void __launch_bounds__(256, 2) scores16(
    const float* __restrict__ eps, const float* __restrict__ sigma)
{
    extern __shared__ char smem[];
    __half* sQ  = (__half*)smem;
    __half* sKh = (__half*)(smem + 3 * ASTR);
    __half* sKl = (__half*)(smem + 6 * ASTR);

    const int tid = threadIdx.x;
    const int lane = tid & 31, warp = tid >> 5;
    const int wm = warp >> 2, wn = warp & 3;
    const int gid = lane >> 2, tig = lane & 3;

    const int aR = tid >> 1, aC = (tid & 1) * 16;
    const unsigned bQ = sptr(sQ), bKh = sptr(sKh), bKl = sptr(sKl);
    const unsigned aOff = (wm * 64 + (lane & 15)) * 80 + (lane >> 4) * 16;
    const unsigned kOff = (wn * 32 + (lane & 15)) * 80 + (lane >> 4) * 16;

    for (int tile = blockIdx.x; tile < 2048; tile += PGRID) {
        const int bg = tile >> 4;
        const int sn0 = ((tile >> 2) & 3) * 128, sm0 = (tile & 3) * 128;
        const __half* Qp  = g_Qh + (size_t)bg * Nn * Dd;
        const __half* Khp = g_Kh + (size_t)bg * Nn * Dd;
        const __half* Klp = g_Kl + (size_t)bg * Nn * Dd;

        auto issue = [&](int kt, int s) {
            const int k0 = kt << 5;
            unsigned so = s * ASTR + aR * 80 + aC * 2;
            size_t go = (size_t)aR * 96 + k0 + aC;
            cpa16(bQ + so, Qp + (size_t)sn0 * 96 + go);
            cpa16(bQ + so + 16, Qp + (size_t)sn0 * 96 + go + 8);
            cpa16(bKh + so, Khp + (size_t)sm0 * 96 + go);
            cpa16(bKh + so + 16, Khp + (size_t)sm0 * 96 + go + 8);
            cpa16(bKl + so, Klp + (size_t)sm0 * 96 + go);
            cpa16(bKl + so + 16, Klp + (size_t)sm0 * 96 + go + 8);
            cpcommit();
        };

        float c[4][4][4];
#pragma unroll
        for (int i = 0; i < 4; i++)
#pragma unroll
            for (int j = 0; j < 4; j++)
#pragma unroll
                for (int q = 0; q < 4; q++) c[i][j][q] = 0.f;

        issue(0, 0); issue(1, 1);

        for (int kt = 0; kt < 3; kt++) {
            cpwait<1>();
            __syncthreads();
            const unsigned aB = bQ + kt * ASTR + aOff;
            const unsigned kH = bKh + kt * ASTR + kOff;
            const unsigned kL = bKl + kt * ASTR + kOff;

#pragma unroll
            for (int k16 = 0; k16 < 2; k16++) {
                unsigned ah[4][4], f[4], bh[4][2], bl[4][2];
#pragma unroll
                for (int mf = 0; mf < 4; mf++)
                    ldsm4(ah[mf], aB + mf * 1280 + k16 * 32);
#pragma unroll
                for (int nf2 = 0; nf2 < 2; nf2++) {
                    ldsm4(f, kH + nf2 * 1280 + k16 * 32);
                    bh[nf2 * 2][0] = f[0]; bh[nf2 * 2][1] = f[2];
                    bh[nf2 * 2 + 1][0] = f[1]; bh[nf2 * 2 + 1][1] = f[3];
                    ldsm4(f, kL + nf2 * 1280 + k16 * 32);
                    bl[nf2 * 2][0] = f[0]; bl[nf2 * 2][1] = f[2];
                    bl[nf2 * 2 + 1][0] = f[1]; bl[nf2 * 2 + 1][1] = f[3];
                }
#pragma unroll
                for (int mf = 0; mf < 4; mf++)
#pragma unroll
                    for (int nf = 0; nf < 4; nf++) {
                        mmaf16(c[mf][nf], ah[mf], bh[nf][0], bh[nf][1]);
                        mmaf16(c[mf][nf], ah[mf], bl[nf][0], bl[nf][1]);
                    }
            }
            const int kn = kt + 2;
            if (kn < 3) issue(kn, kn); else cpcommit();
        }

        float s2 = sigma[bg & 7];
        s2 = s2 * s2;
#pragma unroll
        for (int mf = 0; mf < 4; mf++)
#pragma unroll
            for (int q2 = 0; q2 < 2; q2++) {
                const int n = sn0 + wm * 64 + mf * 16 + gid + q2 * 8;
#pragma unroll
                for (int nf = 0; nf < 4; nf++) {
                    const int m = sm0 + wn * 32 + nf * 8 + tig * 2;
                    const size_t idx = ((size_t)bg * Nn + n) * Nn + m;
                    float2 ev = *(const float2*)(eps + idx);
                    *(__half2*)(g_S + idx) = __halves2half2(
                        __float2half_rn(c[mf][nf][q2 * 2 + 0] + s2 * ev.x),
                        __float2half_rn(c[mf][nf][q2 * 2 + 1] + s2 * ev.y));
                }
            }
        __syncthreads();
    }
}

// ---------------------------------------------------------------------------
// Mix + mish + softmax (max-free), transposed decomposition:
// warp = l (16 warps), lane handles 16 m (2 blocks of 8 consecutive).
// p in registers; S via LDG.128; ONE warp reduction; ONE reciprocal.
// No shared memory, no __syncthreads.
// ---------------------------------------------------------------------------
__global__ void __launch_bounds__(512, 2) mix_softmax_kernel(
    const float* __restrict__ encoding_bias, const float* __restrict__ p)
{
    const int bn = blockIdx.x;
    const int b = bn >> 9, n = bn & 511;
    const int tid = threadIdx.x;
    const int lane = tid & 31, l = tid >> 5;

    float pr[8];
#pragma unroll
    for (int g = 0; g < 8; g++) pr[g] = __ldg(p + g * 16 + l);

    const float scale = 0.03608439182435161f;
    const __half* Sbase = g_S + (((size_t)(b * 8)) * 512 + n) * 512;
    const float* ebase = encoding_bias + ((size_t)bn) * 512;

    float vals[16];
    float psum = 0.f;

#pragma unroll
    for (int ib = 0; ib < 2; ib++) {
        const int m8 = (lane + ib * 32) * 8;

        float tacc[8];
#pragma unroll
        for (int j = 0; j < 8; j++) tacc[j] = 0.f;

#pragma unroll
        for (int g = 0; g < 8; g++) {
            uint4 sv = *(const uint4*)(Sbase + (size_t)g * (512 * 512) + m8);
            const __half2* h2 = (const __half2*)&sv;
#pragma unroll
            for (int j2 = 0; j2 < 4; j2++) {
                float2 f = __half22float2(h2[j2]);
                tacc[j2 * 2 + 0] = fmaf(f.x, pr[g], tacc[j2 * 2 + 0]);
                tacc[j2 * 2 + 1] = fmaf(f.y, pr[g], tacc[j2 * 2 + 1]);
            }
        }

        float4 bv0 = *(const float4*)(ebase + m8);
        float4 bv1 = *(const float4*)(ebase + m8 + 4);
        float bb[8] = {bv0.x, bv0.y, bv0.z, bv0.w, bv1.x, bv1.y, bv1.z, bv1.w};

#pragma unroll
        for (int j = 0; j < 8; j++) {
            float t = tacc[j];
            float e = __expf(fminf(t, 15.f));
            float num = e * (e + 2.f);
            float mish = t * __fdividef(num, num + 2.f);
            float v = __expf(mish * scale + bb[j]);   // logits bounded ~|8|
            vals[ib * 8 + j] = v;
            psum += v;
        }
    }

#pragma unroll
    for (int o = 16; o > 0; o >>= 1)
        psum += __shfl_xor_sync(0xffffffffu, psum, o);
    const float rinv = __fdividef(1.f, psum);

    __half* Abase = g_Ah + (((size_t)(b * 16 + l)) * 512 + n) * 512;
#pragma unroll
    for (int ib = 0; ib < 2; ib++) {
        const int m8 = (lane + ib * 32) * 8;
#pragma unroll
        for (int j = 0; j < 8; j += 2) {
            *(__half2*)(Abase + m8 + j) = __halves2half2(
                __float2half_rn(vals[ib * 8 + j] * rinv),
                __float2half_rn(vals[ib * 8 + j + 1] * rinv));
        }
    }
}

// ---------------------------------------------------------------------------
// Persistent outv: O = A @ V per (b,l).  tiles = 4 x 256 = 1024.
// ---------------------------------------------------------------------------
#define VSTR 6656          // 32 rows * 208B

__global__ void __launch_bounds__(256, 2) outv16()
{
    extern __shared__ char smem[];
    __half* sA = (__half*)smem;
    __half* sVh = (__half*)(smem + 3 * ASTR);

    const int tid = threadIdx.x;
    const int lane = tid & 31, warp = tid >> 5;
    const int wm = warp >> 2, wn = warp & 3;
    const int gid = lane >> 2, tig = lane & 3;

    const int aR = tid >> 1, aC = (tid & 1) * 16;
    const int vR = tid / 6, vC = (tid % 6) * 16;
    const bool vAct = tid < 192;
    const unsigned bA = sptr(sA), bVh = sptr(sVh);
    const unsigned aOff = (wm * 64 + (lane & 15)) * 80 + (lane >> 4) * 16;
    const unsigned vOff = (lane & 15) * 208 + (wn * 24 + (lane >> 4) * 8) * 2;
    const unsigned vOff2 = (lane & 15) * 208 + (wn * 24 + 16) * 2;

    for (int tile = blockIdx.x; tile < 1024; tile += PGRID) {
        const int bl = tile >> 2;
        const int n0 = (tile & 3) * 128;
        const __half* Ap = g_Ah + (size_t)bl * Nn * Nn;
        const __half* Vhp = g_Vh + (size_t)bl * Nn * Dd;

        auto issue = [&](int kt, int s) {
            const int k0 = kt << 5;
            unsigned sa = bA + s * ASTR + aR * 80 + aC * 2;
            const __half* ga = Ap + (size_t)(n0 + aR) * 512 + k0 + aC;
            cpa16(sa, ga); cpa16(sa + 16, ga + 8);
            if (vAct) {
                unsigned sv = bVh + s * VSTR + vR * 208 + vC * 2;
                const __half* gv = Vhp + (size_t)(k0 + vR) * 96 + vC;
                cpa16(sv, gv); cpa16(sv + 16, gv + 8);
            }
            cpcommit();
        };

        float c[4][3][4];
#pragma unroll
        for (int i = 0; i < 4; i++)
#pragma unroll
            for (int j = 0; j < 3; j++)
#pragma unroll
                for (int q = 0; q < 4; q++) c[i][j][q] = 0.f;

        issue(0, 0); issue(1, 1);

        for (int kt = 0; kt < 16; kt++) {
            cpwait<1>();
            __syncthreads();
            const int s = kt % 3;
            const unsigned aB = bA + s * ASTR + aOff;
            const unsigned vH = bVh + s * VSTR;

#pragma unroll
            for (int k16 = 0; k16 < 2; k16++) {
                unsigned ah[4][4], bh[3][2], t0, t1, t2, t3;
#pragma unroll
                for (int mf = 0; mf < 4; mf++)
                    ldsm4(ah[mf], aB + mf * 1280 + k16 * 32);
                ldsm4t(t0, t1, t2, t3, vH + vOff + k16 * 3328);
                bh[0][0] = t0; bh[0][1] = t1; bh[1][0] = t2; bh[1][1] = t3;
                ldsm2t(t0, t1, vH + vOff2 + k16 * 3328);
                bh[2][0] = t0; bh[2][1] = t1;

#pragma unroll
                for (int mf = 0; mf < 4; mf++)
#pragma unroll
                    for (int nf = 0; nf < 3; nf++)
                        mmaf16(c[mf][nf], ah[mf], bh[nf][0], bh[nf][1]);
            }
            const int kn = kt + 2;
            if (kn < 16) issue(kn, kn % 3); else cpcommit();
        }

        const int b = bl >> 4, l = bl & 15;
#pragma unroll
        for (int mf = 0; mf < 4; mf++)
#pragma unroll
            for (int q2 = 0; q2 < 2; q2++) {
                const int n = n0 + wm * 64 + mf * 16 + gid + q2 * 8;
#pragma unroll
                for (int nf = 0; nf < 3; nf++) {
                    const int d = wn * 24 + nf * 8 + tig * 2;
                    const size_t idx = ((size_t)(b * 512 + n)) * 1536 + l * 96 + d;
                    *(__half2*)(g_Oh + idx) =
                        __halves2half2(__float2half_rn(c[mf][nf][q2 * 2 + 0]),
                                       __float2half_rn(c[mf][nf][q2 * 2 + 1]));
                }
            }
        __syncthreads();   // stage reuse guard (KT=16 -> last stage == 0)
    }
}

// ---------------------------------------------------------------------------
extern "C" void kernel_launch(void* const* d_in, const int* in_sizes, int n_in,
                              void* d_out, int out_size)
{
    const float* x     = (const float*)d_in[0];
    const float* ebias = (const float*)d_in[1];
    const float* eps   = (const float*)d_in[2];
    const float* Wq    = (const float*)d_in[3];
    const float* Wk    = (const float*)d_in[4];
    const float* Wv    = (const float*)d_in[5];
    const float* bv    = (const float*)d_in[6];
    const float* sigma = (const float*)d_in[7];
    const float* p     = (const float*)d_in[8];
    const float* Wout  = (const float*)d_in[9];
    float* out = (float*)d_out;

    __half *xh, *wqkv, *woh, *qh, *kh, *kl, *vh, *oh;
    cudaGetSymbolAddress((void**)&xh,   g_xh);
    cudaGetSymbolAddress((void**)&wqkv, g_wqkv);
    cudaGetSymbolAddress((void**)&woh,  g_woh);
    cudaGetSymbolAddress((void**)&qh,   g_Qh);
    cudaGetSymbolAddress((void**)&kh,   g_Kh);
    cudaGetSymbolAddress((void**)&kl,   g_Kl);
    cudaGetSymbolAddress((void**)&vh,   g_Vh);
    cudaGetSymbolAddress((void**)&oh,   g_Oh);

    const int SM_1 = 3 * ASTR + 3 * BSTR;   // 56832
    const int SM_S = 9 * ASTR;              // 92160
    const int SM_O = 3 * ASTR + 3 * VSTR;   // 50688

    cudaFuncSetAttribute(gemm16<1>,
        cudaFuncAttributeMaxDynamicSharedMemorySize, SM_1);
    cudaFuncSetAttribute(gemm16<0>,
        cudaFuncAttributeMaxDynamicSharedMemorySize, SM_1);
    cudaFuncSetAttribute(scores16,
        cudaFuncAttributeMaxDynamicSharedMemorySize, SM_S);
    cudaFuncSetAttribute(outv16,
        cudaFuncAttributeMaxDynamicSharedMemorySize, SM_O);

    // fused input splits (x, Wq, Wk, Wv, Wout)
    splitAll<<<9600, 256>>>((const float4*)x, (const float4*)Wq,
                            (const float4*)Wk, (const float4*)Wv,
                            (const float4*)Wout);

    // merged Q+K+V projection: persistent, tiles 24x64
    gemm16<1><<<PGRID, 256, SM_1>>>(
        xh, wqkv, bv, qh, kh, kl, vh, nullptr, 768, 3072, 24, 1536);

    // scores: persistent, 2-term + sigma^2*eps -> fp16 S
    scores16<<<PGRID, 256, SM_S>>>(eps, sigma);

    // mix + mish + softmax (max-free, transposed) -> A fp16
    mix_softmax_kernel<<<Bb * Nn, 512>>>(ebias, p);

    // O = A @ V: persistent
    outv16<<<PGRID, 256, SM_O>>>();

    // out proj: persistent, tiles 6x64 -> fp32 d_out
    gemm16<0><<<PGRID, 256, SM_1>>>(
        oh, woh, nullptr, nullptr, nullptr, nullptr, nullptr, out, 1536, 768, 6, 384);
}

// round 14
// speedup vs baseline: 1.9555x; 1.0161x over previous
#include <cuda_runtime.h>
#include <cuda_fp16.h>
#include <math.h>

#define Bb 16
#define Nn 512
#define Dd 96
#define PGRID 592

// ---------------- scratch -------------------------------------------------
__device__ __half g_xh  [(size_t)8192 * 768];
__device__ __half g_wqkv[(size_t)768 * 3072];    // [k][ Wq | Wk | Wv ]
__device__ __half g_woh [(size_t)1536 * 768];
__device__ __half g_Qh[(size_t)128 * 512 * 96];
__device__ __half g_Kh[(size_t)128 * 512 * 96];
__device__ __half g_Kl[(size_t)128 * 512 * 96];
__device__ __half g_Vh[(size_t)256 * 512 * 96];
__device__ __half g_S [(size_t)128 * 512 * 512];
__device__ __half g_Ah[(size_t)256 * 512 * 512];
__device__ __half g_Oh[(size_t)8192 * 1536];

// ---------------- helpers --------------------------------------------------
__device__ __forceinline__ unsigned sptr(const void* p) {
    return (unsigned)__cvta_generic_to_shared(p);
}
__device__ __forceinline__ void cpa16(unsigned s, const void* g) {
    asm volatile("cp.async.cg.shared.global [%0], [%1], 16;" :: "r"(s), "l"(g));
}
__device__ __forceinline__ void cpcommit() {
    asm volatile("cp.async.commit_group;");
}
template<int W> __device__ __forceinline__ void cpwait() {
    asm volatile("cp.async.wait_group %0;" :: "n"(W));
}
__device__ __forceinline__ void ldsm4(unsigned f[4], unsigned a) {
    asm volatile("ldmatrix.sync.aligned.m8n8.x4.shared.b16 {%0,%1,%2,%3}, [%4];"
                 : "=r"(f[0]), "=r"(f[1]), "=r"(f[2]), "=r"(f[3]) : "r"(a));
}
__device__ __forceinline__ void ldsm4t(unsigned& r0, unsigned& r1, unsigned& r2,
                                       unsigned& r3, unsigned a) {
    asm volatile("ldmatrix.sync.aligned.m8n8.x4.trans.shared.b16 {%0,%1,%2,%3}, [%4];"
                 : "=r"(r0), "=r"(r1), "=r"(r2), "=r"(r3) : "r"(a));
}
__device__ __forceinline__ void ldsm2t(unsigned& r0, unsigned& r1, unsigned a) {
    asm volatile("ldmatrix.sync.aligned.m8n8.x2.trans.shared.b16 {%0,%1}, [%2];"
                 : "=r"(r0), "=r"(r1) : "r"(a));
}
__device__ __forceinline__ void mmaf16(float c[4], const unsigned a[4],
                                       unsigned b0, unsigned b1) {
    asm volatile(
        "mma.sync.aligned.m16n8k16.row.col.f32.f16.f16.f32 "
        "{%0,%1,%2,%3}, {%4,%5,%6,%7}, {%8,%9}, {%0,%1,%2,%3};"
        : "+f"(c[0]), "+f"(c[1]), "+f"(c[2]), "+f"(c[3])
        : "r"(a[0]), "r"(a[1]), "r"(a[2]), "r"(a[3]), "r"(b0), "r"(b1));
}
__device__ __forceinline__ void hsplit(float v, __half& h, __half& l) {
    h = __float2half_rn(v);
    l = __float2half_rn(v - __half2float(h));
}

// ---------------- fused input split (x, Wq, Wk, Wv, Wout in one launch) ----
__global__ void __launch_bounds__(256) splitAll(
    const float4* __restrict__ x, const float4* __restrict__ Wq,
    const float4* __restrict__ Wk, const float4* __restrict__ Wv,
    const float4* __restrict__ Wout)
{
    int i = blockIdx.x * 256 + threadIdx.x;
    if (i < 1572864) {
        float4 v = x[i];
        ((__half2*)g_xh)[i * 2]     = __halves2half2(__float2half_rn(v.x), __float2half_rn(v.y));
        ((__half2*)g_xh)[i * 2 + 1] = __halves2half2(__float2half_rn(v.z), __float2half_rn(v.w));
    } else if (i < 1720320) {
        int j = i - 1572864;
        int row = j / 192, col = (j % 192) * 4;
        float4 v = Wq[j];
        __half2* d = (__half2*)(g_wqkv + (size_t)row * 3072 + col);
        d[0] = __halves2half2(__float2half_rn(v.x), __float2half_rn(v.y));
        d[1] = __halves2half2(__float2half_rn(v.z), __float2half_rn(v.w));
    } else if (i < 1867776) {
        int j = i - 1720320;
        int row = j / 192, col = (j % 192) * 4;
        float4 v = Wk[j];
        __half2* d = (__half2*)(g_wqkv + (size_t)row * 3072 + 768 + col);
        d[0] = __halves2half2(__float2half_rn(v.x), __float2half_rn(v.y));
        d[1] = __halves2half2(__float2half_rn(v.z), __float2half_rn(v.w));
    } else if (i < 2162688) {
        int j = i - 1867776;
        int row = j / 384, col = (j % 384) * 4;
        float4 v = Wv[j];
        __half2* d = (__half2*)(g_wqkv + (size_t)row * 3072 + 1536 + col);
        d[0] = __halves2half2(__float2half_rn(v.x), __float2half_rn(v.y));
        d[1] = __halves2half2(__float2half_rn(v.z), __float2half_rn(v.w));
    } else if (i < 2457600) {
        int j = i - 2162688;
        float4 v = Wout[j];
        ((__half2*)g_woh)[j * 2]     = __halves2half2(__float2half_rn(v.x), __float2half_rn(v.y));
        ((__half2*)g_woh)[j * 2 + 1] = __halves2half2(__float2half_rn(v.z), __float2half_rn(v.w));
    }
}

// ---------------------------------------------------------------------------
// Persistent GEMM with cross-tile prefetch. BM=128 BN=128 BK=32, 3 stages.
// MODE 0: fp32 rowmajor (outF).  MODE 1: QKV merged epilogue.
// ---------------------------------------------------------------------------
#define ASTR 10240          // 128 rows * 80B
#define BSTR 8704           // 32 rows * 272B

template<int MODE>
__global__ void __launch_bounds__(256, 2) gemm16(
    const __half* __restrict__ Agh, const __half* __restrict__ Bgh,
    const float* __restrict__ bias,
    __half* __restrict__ o0, __half* __restrict__ o1, __half* __restrict__ o2,
    __half* __restrict__ o3, float* __restrict__ outF,
    int K, int N, int tilesX, int nTiles)
{
    extern __shared__ char smem[];
    __half* sA = (__half*)smem;
    __half* sBh = (__half*)(smem + 3 * ASTR);

    const int tid = threadIdx.x;
    const int lane = tid & 31, warp = tid >> 5;
    const int wm = warp >> 2, wn = warp & 3;
    const int gid = lane >> 2, tig = lane & 3;

    const int aR = tid >> 1, aC = (tid & 1) * 16;
    const int bR = tid >> 3, bC = (tid & 7) * 16;
    const unsigned sAb = sptr(sA), sBhb = sptr(sBh);
    const unsigned aOff = (wm * 64 + (lane & 15)) * 80 + (lane >> 4) * 16;
    const unsigned bOff = (lane & 15) * 272 + (wn * 32 + (lane >> 4) * 8) * 2;
    const int KT = K >> 5;

    // issue chunk kt of tile t into stage s
    auto issueT = [&](int t, int kt, int s) {
        const int tm0 = (t / tilesX) * 128;
        const int tn0 = (t % tilesX) * 128;
        const int k0 = kt << 5;
        const __half* ga = Agh + (size_t)(tm0 + aR) * K + k0 + aC;
        unsigned sa = sAb + s * ASTR + aR * 80 + aC * 2;
        cpa16(sa, ga); cpa16(sa + 16, ga + 8);
        const __half* gb = Bgh + (size_t)(k0 + bR) * N + tn0 + bC;
        unsigned sb = sBhb + s * BSTR + bR * 272 + bC * 2;
        cpa16(sb, gb); cpa16(sb + 16, gb + 8);
        cpcommit();
    };

    if (blockIdx.x < nTiles) {
        issueT(blockIdx.x, 0, 0);
        issueT(blockIdx.x, 1, 1);
    }

    for (int tile = blockIdx.x; tile < nTiles; tile += PGRID) {
        const int m0 = (tile / tilesX) * 128;
        const int n0 = (tile % tilesX) * 128;

        float c[4][4][4];
#pragma unroll
        for (int i = 0; i < 4; i++)
#pragma unroll
            for (int j = 0; j < 4; j++)
#pragma unroll
                for (int q = 0; q < 4; q++) c[i][j][q] = 0.f;

        for (int kt = 0; kt < KT; kt++) {
            cpwait<1>();
            __syncthreads();
            const int s = kt % 3;
            const unsigned aB = sAb + s * ASTR + aOff;
            const unsigned bB = sBhb + s * BSTR + bOff;

#pragma unroll
            for (int k16 = 0; k16 < 2; k16++) {
                unsigned ah[4][4], bh[4][2], t0, t1, t2, t3;
#pragma unroll
                for (int mf = 0; mf < 4; mf++)
                    ldsm4(ah[mf], aB + mf * 1280 + k16 * 32);
#pragma unroll
                for (int nf2 = 0; nf2 < 2; nf2++) {
                    ldsm4t(t0, t1, t2, t3, bB + k16 * 4352 + nf2 * 32);
                    bh[nf2 * 2][0] = t0; bh[nf2 * 2][1] = t1;
                    bh[nf2 * 2 + 1][0] = t2; bh[nf2 * 2 + 1][1] = t3;
                }
#pragma unroll
                for (int mf = 0; mf < 4; mf++)
#pragma unroll
                    for (int nf = 0; nf < 4; nf++)
                        mmaf16(c[mf][nf], ah[mf], bh[nf][0], bh[nf][1]);
            }
            const int kn = kt + 2;
            if (kn < KT) issueT(tile, kn, kn % 3); else cpcommit();
        }

        // cross-tile prefetch: stages 0,1 are provably free (KT%3!=1 here ->
        // last chunk used stage 2; all warps past kt=KT-1 top sync).
        const int nt = tile + PGRID;
        if (nt < nTiles) { issueT(nt, 0, 0); issueT(nt, 1, 1); }

#pragma unroll
        for (int mf = 0; mf < 4; mf++)
#pragma unroll
            for (int q2 = 0; q2 < 2; q2++) {
                const int row = m0 + wm * 64 + mf * 16 + gid + q2 * 8;
                const int b = row >> 9, n = row & 511;
#pragma unroll
                for (int nf = 0; nf < 4; nf++) {
                    const int col = n0 + wn * 32 + nf * 8 + tig * 2;
                    float v0 = c[mf][nf][q2 * 2 + 0];
                    float v1 = c[mf][nf][q2 * 2 + 1];
                    if (MODE == 0) {
                        *(float2*)(outF + (size_t)row * N + col) = make_float2(v0, v1);
                    } else {
                        if (col < 768) {
                            const int h = col / 96, d = col - h * 96;
                            const size_t idx = (((size_t)(b * 8 + h)) * 512 + n) * 96 + d;
                            *(__half2*)(o0 + idx) =
                                __halves2half2(__float2half_rn(v0), __float2half_rn(v1));
                        } else if (col < 1536) {
                            const int cc = col - 768;
                            const int h = cc / 96, d = cc - h * 96;
                            const size_t idx = (((size_t)(b * 8 + h)) * 512 + n) * 96 + d;
                            __half h0, h1, l0, l1;
                            hsplit(v0, h0, l0); hsplit(v1, h1, l1);
                            *(__half2*)(o1 + idx) = __halves2half2(h0, h1);
                            *(__half2*)(o2 + idx) = __halves2half2(l0, l1);
                        } else {
                            const int cc = col - 1536;
                            const int h = cc / 96, d = cc - h * 96;
                            v0 += bias[cc]; v1 += bias[cc + 1];
                            const size_t idx = (((size_t)(b * 16 + h)) * 512 + n) * 96 + d;
                            *(__half2*)(o3 + idx) =
                                __halves2half2(__float2half_rn(v0), __float2half_rn(v1));
                        }
                    }
                }
            }
        // no trailing sync: next iteration's kt=0 top sync subsumes it
    }
}

// ---------------------------------------------------------------------------
// Persistent scores with cross-tile prefetch.  Q single, K dual (2-term).
// tiles: 128 bg x 4 x 4 = 2048, KT=3 (last stage = 2 -> stages 0,1 free).
// ---------------------------------------------------------------------------
__global__ void __launch_bounds__(256, 2) scores16(
    const float* __restrict__ eps, const float* __restrict__ sigma)
{
    extern __shared__ char smem[];
    __half* sQ  = (__half*)smem;
    __half* sKh = (__half*)(smem + 3 * ASTR);
    __half* sKl = (__half*)(smem + 6 * ASTR);

    const int tid = threadIdx.x;
    const int lane = tid & 31, warp = tid >> 5;
    const int wm = warp >> 2, wn = warp & 3;
    const int gid = lane >> 2, tig = lane & 3;

    const int aR = tid >> 1, aC = (tid & 1) * 16;
    const unsigned bQ = sptr(sQ), bKh = sptr(sKh), bKl = sptr(sKl);
    const unsigned aOff = (wm * 64 + (lane & 15)) * 80 + (lane >> 4) * 16;
    const unsigned kOff = (wn * 32 + (lane & 15)) * 80 + (lane >> 4) * 16;

    auto issueT = [&](int t, int kt, int s) {
        const int tbg = t >> 4;
        const int tsn0 = ((t >> 2) & 3) * 128, tsm0 = (t & 3) * 128;
        const __half* Qp  = g_Qh + (size_t)tbg * Nn * Dd;
        const __half* Khp = g_Kh + (size_t)tbg * Nn * Dd;
        const __half* Klp = g_Kl + (size_t)tbg * Nn * Dd;
        const int k0 = kt << 5;
        unsigned so = s * ASTR + aR * 80 + aC * 2;
        size_t go = (size_t)aR * 96 + k0 + aC;
        cpa16(bQ + so, Qp + (size_t)tsn0 * 96 + go);
        cpa16(bQ + so + 16, Qp + (size_t)tsn0 * 96 + go + 8);
        cpa16(bKh + so, Khp + (size_t)tsm0 * 96 + go);
        cpa16(bKh + so + 16, Khp + (size_t)tsm0 * 96 + go + 8);
        cpa16(bKl + so, Klp + (size_t)tsm0 * 96 + go);
        cpa16(bKl + so + 16, Klp + (size_t)tsm0 * 96 + go + 8);
        cpcommit();
    };

    if (blockIdx.x < 2048) {
        issueT(blockIdx.x, 0, 0);
        issueT(blockIdx.x, 1, 1);
    }

    for (int tile = blockIdx.x; tile < 2048; tile += PGRID) {
        const int bg = tile >> 4;
        const int sn0 = ((tile >> 2) & 3) * 128, sm0 = (tile & 3) * 128;

        float c[4][4][4];
#pragma unroll
        for (int i = 0; i < 4; i++)
#pragma unroll
            for (int j = 0; j < 4; j++)
#pragma unroll
                for (int q = 0; q < 4; q++) c[i][j][q] = 0.f;

        for (int kt = 0; kt < 3; kt++) {
            cpwait<1>();
            __syncthreads();
            const unsigned aB = bQ + kt * ASTR + aOff;
            const unsigned kH = bKh + kt * ASTR + kOff;
            const unsigned kL = bKl + kt * ASTR + kOff;

#pragma unroll
            for (int k16 = 0; k16 < 2; k16++) {
                unsigned ah[4][4], f[4], bh[4][2], bl[4][2];
#pragma unroll
                for (int mf = 0; mf < 4; mf++)
                    ldsm4(ah[mf], aB + mf * 1280 + k16 * 32);
#pragma unroll
                for (int nf2 = 0; nf2 < 2; nf2++) {
                    ldsm4(f, kH + nf2 * 1280 + k16 * 32);
                    bh[nf2 * 2][0] = f[0]; bh[nf2 * 2][1] = f[2];
                    bh[nf2 * 2 + 1][0] = f[1]; bh[nf2 * 2 + 1][1] = f[3];
                    ldsm4(f, kL + nf2 * 1280 + k16 * 32);
                    bl[nf2 * 2][0] = f[0]; bl[nf2 * 2][1] = f[2];
                    bl[nf2 * 2 + 1][0] = f[1]; bl[nf2 * 2 + 1][1] = f[3];
                }
#pragma unroll
                for (int mf = 0; mf < 4; mf++)
#pragma unroll
                    for (int nf = 0; nf < 4; nf++) {
                        mmaf16(c[mf][nf], ah[mf], bh[nf][0], bh[nf][1]);
                        mmaf16(c[mf][nf], ah[mf], bl[nf][0], bl[nf][1]);
                    }
            }
            const int kn = kt + 2;
            if (kn < 3) issueT(tile, kn, kn); else cpcommit();
        }

        // cross-tile prefetch overlaps the eps-heavy epilogue
        const int nt = tile + PGRID;
        if (nt < 2048) { issueT(nt, 0, 0); issueT(nt, 1, 1); }

        float s2 = sigma[bg & 7];
        s2 = s2 * s2;
#pragma unroll
        for (int mf = 0; mf < 4; mf++)
#pragma unroll
            for (int q2 = 0; q2 < 2; q2++) {
                const int n = sn0 + wm * 64 + mf * 16 + gid + q2 * 8;
#pragma unroll
                for (int nf = 0; nf < 4; nf++) {
                    const int m = sm0 + wn * 32 + nf * 8 + tig * 2;
                    const size_t idx = ((size_t)bg * Nn + n) * Nn + m;
                    float2 ev = *(const float2*)(eps + idx);
                    *(__half2*)(g_S + idx) = __halves2half2(
                        __float2half_rn(c[mf][nf][q2 * 2 + 0] + s2 * ev.x),
                        __float2half_rn(c[mf][nf][q2 * 2 + 1] + s2 * ev.y));
                }
            }
    }
}

// ---------------------------------------------------------------------------
// Mix + mish + softmax (max-free), transposed: warp = l, lane x16 = m.
// STG.128 A stores.  No smem, no syncthreads.
// ---------------------------------------------------------------------------
__global__ void __launch_bounds__(512, 2) mix_softmax_kernel(
    const float* __restrict__ encoding_bias, const float* __restrict__ p)
{
    const int bn = blockIdx.x;
    const int b = bn >> 9, n = bn & 511;
    const int tid = threadIdx.x;
    const int lane = tid & 31, l = tid >> 5;

    float pr[8];
#pragma unroll
    for (int g = 0; g < 8; g++) pr[g] = __ldg(p + g * 16 + l);

    const float scale = 0.03608439182435161f;
    const __half* Sbase = g_S + (((size_t)(b * 8)) * 512 + n) * 512;
    const float* ebase = encoding_bias + ((size_t)bn) * 512;

    float vals[16];
    float psum = 0.f;

#pragma unroll
    for (int ib = 0; ib < 2; ib++) {
        const int m8 = (lane + ib * 32) * 8;

        float tacc[8];
#pragma unroll
        for (int j = 0; j < 8; j++) tacc[j] = 0.f;

#pragma unroll
        for (int g = 0; g < 8; g++) {
            uint4 sv = *(const uint4*)(Sbase + (size_t)g * (512 * 512) + m8);
            const __half2* h2 = (const __half2*)&sv;
#pragma unroll
            for (int j2 = 0; j2 < 4; j2++) {
                float2 f = __half22float2(h2[j2]);
                tacc[j2 * 2 + 0] = fmaf(f.x, pr[g], tacc[j2 * 2 + 0]);
                tacc[j2 * 2 + 1] = fmaf(f.y, pr[g], tacc[j2 * 2 + 1]);
            }
        }

        float4 bv0 = *(const float4*)(ebase + m8);
        float4 bv1 = *(const float4*)(ebase + m8 + 4);
        float bb[8] = {bv0.x, bv0.y, bv0.z, bv0.w, bv1.x, bv1.y, bv1.z, bv1.w};

#pragma unroll
        for (int j = 0; j < 8; j++) {
            float t = tacc[j];
            float e = __expf(fminf(t, 15.f));
            float num = e * (e + 2.f);
            float mish = t * __fdividef(num, num + 2.f);
            float v = __expf(mish * scale + bb[j]);   // logits bounded ~|8|
            vals[ib * 8 + j] = v;
            psum += v;
        }
    }

#pragma unroll
    for (int o = 16; o > 0; o >>= 1)
        psum += __shfl_xor_sync(0xffffffffu, psum, o);
    const float rinv = __fdividef(1.f, psum);

    __half* Abase = g_Ah + (((size_t)(b * 16 + l)) * 512 + n) * 512;
#pragma unroll
    for (int ib = 0; ib < 2; ib++) {
        const int m8 = (lane + ib * 32) * 8;
        uint4 pk;
        unsigned* pku = (unsigned*)&pk;
#pragma unroll
        for (int j2 = 0; j2 < 4; j2++) {
            __half2 h = __halves2half2(
                __float2half_rn(vals[ib * 8 + j2 * 2 + 0] * rinv),
                __float2half_rn(vals[ib * 8 + j2 * 2 + 1] * rinv));
            pku[j2] = *(unsigned*)&h;
        }
        *(uint4*)(Abase + m8) = pk;
    }
}

// ---------------------------------------------------------------------------
// Persistent outv with cross-tile prefetch.  tiles = 4 x 256 = 1024, KT=16.
// Last chunk uses stage 0 -> need sync before prefetch.
// ---------------------------------------------------------------------------
#define VSTR 6656          // 32 rows * 208B

__global__ void __launch_bounds__(256, 2) outv16()
{
    extern __shared__ char smem[];
    __half* sA = (__half*)smem;
    __half* sVh = (__half*)(smem + 3 * ASTR);

    const int tid = threadIdx.x;
    const int lane = tid & 31, warp = tid >> 5;
    const int wm = warp >> 2, wn = warp & 3;
    const int gid = lane >> 2, tig = lane & 3;

    const int aR = tid >> 1, aC = (tid & 1) * 16;
    const int vR = tid / 6, vC = (tid % 6) * 16;
    const bool vAct = tid < 192;
    const unsigned bA = sptr(sA), bVh = sptr(sVh);
    const unsigned aOff = (wm * 64 + (lane & 15)) * 80 + (lane >> 4) * 16;
    const unsigned vOff = (lane & 15) * 208 + (wn * 24 + (lane >> 4) * 8) * 2;
    const unsigned vOff2 = (lane & 15) * 208 + (wn * 24 + 16) * 2;

    auto issueT = [&](int t, int kt, int s) {
        const int tbl = t >> 2;
        const int tn0 = (t & 3) * 128;
        const __half* Ap = g_Ah + (size_t)tbl * Nn * Nn;
        const __half* Vhp = g_Vh + (size_t)tbl * Nn * Dd;
        const int k0 = kt << 5;
        unsigned sa = bA + s * ASTR + aR * 80 + aC * 2;
        const __half* ga = Ap + (size_t)(tn0 + aR) * 512 + k0 + aC;
        cpa16(sa, ga); cpa16(sa + 16, ga + 8);
        if (vAct) {
            unsigned sv = bVh + s * VSTR + vR * 208 + vC * 2;
            const __half* gv = Vhp + (size_t)(k0 + vR) * 96 + vC;
            cpa16(sv, gv); cpa16(sv + 16, gv + 8);
        }
        cpcommit();
    };

    if (blockIdx.x < 1024) {
        issueT(blockIdx.x, 0, 0);
        issueT(blockIdx.x, 1, 1);
    }

    for (int tile = blockIdx.x; tile < 1024; tile += PGRID) {
        const int bl = tile >> 2;
        const int n0 = (tile & 3) * 128;

        float c[4][3][4];
#pragma unroll
        for (int i = 0; i < 4; i++)
#pragma unroll
            for (int j = 0; j < 3; j++)
#pragma unroll
                for (int q = 0; q < 4; q++) c[i][j][q] = 0.f;

        for (int kt = 0; kt < 16; kt++) {
            cpwait<1>();
            __syncthreads();
            const int s = kt % 3;
            const unsigned aB = bA + s * ASTR + aOff;
            const unsigned vH = bVh + s * VSTR;

#pragma unroll
            for (int k16 = 0; k16 < 2; k16++) {
                unsigned ah[4][4], bh[3][2], t0, t1, t2, t3;
#pragma unroll
                for (int mf = 0; mf < 4; mf++)
                    ldsm4(ah[mf], aB + mf * 1280 + k16 * 32);
                ldsm4t(t0, t1, t2, t3, vH + vOff + k16 * 3328);
                bh[0][0] = t0; bh[0][1] = t1; bh[1][0] = t2; bh[1][1] = t3;
                ldsm2t(t0, t1, vH + vOff2 + k16 * 3328);
                bh[2][0] = t0; bh[2][1] = t1;

#pragma unroll
                for (int mf = 0; mf < 4; mf++)
#pragma unroll
                    for (int nf = 0; nf < 3; nf++)
                        mmaf16(c[mf][nf], ah[mf], bh[nf][0], bh[nf][1]);
            }
            const int kn = kt + 2;
            if (kn < 16) issueT(tile, kn, kn % 3); else cpcommit();
        }

        // KT=16: last chunk sat in stage 0 -> guard before reusing stages 0,1
        __syncthreads();
        const int nt = tile + PGRID;
        if (nt < 1024) { issueT(nt, 0, 0); issueT(nt, 1, 1); }

        const int b = bl >> 4, l = bl & 15;
#pragma unroll
        for (int mf = 0; mf < 4; mf++)
#pragma unroll
            for (int q2 = 0; q2 < 2; q2++) {
                const int n = n0 + wm * 64 + mf * 16 + gid + q2 * 8;
#pragma unroll
                for (int nf = 0; nf < 3; nf++) {
                    const int d = wn * 24 + nf * 8 + tig * 2;
                    const size_t idx = ((size_t)(b * 512 + n)) * 1536 + l * 96 + d;
                    *(__half2*)(g_Oh + idx) =
                        __halves2half2(__float2half_rn(c[mf][nf][q2 * 2 + 0]),
                                       __float2half_rn(c[mf][nf][q2 * 2 + 1]));
                }
            }
    }
}

// ---------------------------------------------------------------------------
extern "C" void kernel_launch(void* const* d_in, const int* in_sizes, int n_in,
                              void* d_out, int out_size)
{
    const float* x     = (const float*)d_in[0];
    const float* ebias = (const float*)d_in[1];
    const float* eps   = (const float*)d_in[2];
    const float* Wq    = (const float*)d_in[3];
    const float* Wk    = (const float*)d_in[4];
    const float* Wv    = (const float*)d_in[5];
    const float* bv    = (const float*)d_in[6];
    const float* sigma = (const float*)d_in[7];
    const float* p     = (const float*)d_in[8];
    const float* Wout  = (const float*)d_in[9];
    float* out = (float*)d_out;

    __half *xh, *wqkv, *woh, *qh, *kh, *kl, *vh, *oh;
    cudaGetSymbolAddress((void**)&xh,   g_xh);
    cudaGetSymbolAddress((void**)&wqkv, g_wqkv);
    cudaGetSymbolAddress((void**)&woh,  g_woh);
    cudaGetSymbolAddress((void**)&qh,   g_Qh);
    cudaGetSymbolAddress((void**)&kh,   g_Kh);
    cudaGetSymbolAddress((void**)&kl,   g_Kl);
    cudaGetSymbolAddress((void**)&vh,   g_Vh);
    cudaGetSymbolAddress((void**)&oh,   g_Oh);

    const int SM_1 = 3 * ASTR + 3 * BSTR;   // 56832
    const int SM_S = 9 * ASTR;              // 92160
    const int SM_O = 3 * ASTR + 3 * VSTR;   // 50688

    cudaFuncSetAttribute(gemm16<1>,
        cudaFuncAttributeMaxDynamicSharedMemorySize, SM_1);
    cudaFuncSetAttribute(gemm16<0>,
        cudaFuncAttributeMaxDynamicSharedMemorySize, SM_1);
    cudaFuncSetAttribute(scores16,
        cudaFuncAttributeMaxDynamicSharedMemorySize, SM_S);
    cudaFuncSetAttribute(outv16,
        cudaFuncAttributeMaxDynamicSharedMemorySize, SM_O);

    // fused input splits (x, Wq, Wk, Wv, Wout)
    splitAll<<<9600, 256>>>((const float4*)x, (const float4*)Wq,
                            (const float4*)Wk, (const float4*)Wv,
                            (const float4*)Wout);

    // merged Q+K+V projection: persistent, tiles 24x64
    gemm16<1><<<PGRID, 256, SM_1>>>(
        xh, wqkv, bv, qh, kh, kl, vh, nullptr, 768, 3072, 24, 1536);

    // scores: persistent, 2-term + sigma^2*eps -> fp16 S
    scores16<<<PGRID, 256, SM_S>>>(eps, sigma);

    // mix + mish + softmax (max-free, transposed) -> A fp16
    mix_softmax_kernel<<<Bb * Nn, 512>>>(ebias, p);

    // O = A @ V: persistent
    outv16<<<PGRID, 256, SM_O>>>();

    // out proj: persistent, tiles 6x64 -> fp32 d_out
    gemm16<0><<<PGRID, 256, SM_1>>>(
        oh, woh, nullptr, nullptr, nullptr, nullptr, nullptr, out, 1536, 768, 6, 384);
}

// round 15
// speedup vs baseline: 1.9888x; 1.0170x over previous
#include <cuda_runtime.h>
#include <cuda_fp16.h>
#include <math.h>

#define Bb 16
#define Nn 512
#define Dd 96
#define PGRID 592

// ---------------- scratch -------------------------------------------------
__device__ __half g_xh  [(size_t)8192 * 768];
__device__ __half g_wqkv[(size_t)768 * 3072];    // [k][ Wq | Wk | Wv ]
__device__ __half g_woh [(size_t)1536 * 768];
__device__ __half g_Qh[(size_t)128 * 512 * 96];
__device__ __half g_Kh[(size_t)128 * 512 * 96];
__device__ __half g_Kl[(size_t)128 * 512 * 96];
__device__ __half g_Vh[(size_t)256 * 512 * 96];
__device__ __half g_S [(size_t)128 * 512 * 512];
__device__ __half g_Ah[(size_t)256 * 512 * 512];
__device__ __half g_Oh[(size_t)8192 * 1536];

// ---------------- helpers --------------------------------------------------
__device__ __forceinline__ unsigned sptr(const void* p) {
    return (unsigned)__cvta_generic_to_shared(p);
}
__device__ __forceinline__ void cpa16(unsigned s, const void* g) {
    asm volatile("cp.async.cg.shared.global [%0], [%1], 16;" :: "r"(s), "l"(g));
}
__device__ __forceinline__ void cpcommit() {
    asm volatile("cp.async.commit_group;");
}
template<int W> __device__ __forceinline__ void cpwait() {
    asm volatile("cp.async.wait_group %0;" :: "n"(W));
}
__device__ __forceinline__ void ldsm4(unsigned f[4], unsigned a) {
    asm volatile("ldmatrix.sync.aligned.m8n8.x4.shared.b16 {%0,%1,%2,%3}, [%4];"
                 : "=r"(f[0]), "=r"(f[1]), "=r"(f[2]), "=r"(f[3]) : "r"(a));
}
__device__ __forceinline__ void ldsm4t(unsigned& r0, unsigned& r1, unsigned& r2,
                                       unsigned& r3, unsigned a) {
    asm volatile("ldmatrix.sync.aligned.m8n8.x4.trans.shared.b16 {%0,%1,%2,%3}, [%4];"
                 : "=r"(r0), "=r"(r1), "=r"(r2), "=r"(r3) : "r"(a));
}
__device__ __forceinline__ void ldsm2t(unsigned& r0, unsigned& r1, unsigned a) {
    asm volatile("ldmatrix.sync.aligned.m8n8.x2.trans.shared.b16 {%0,%1}, [%2];"
                 : "=r"(r0), "=r"(r1) : "r"(a));
}
__device__ __forceinline__ void mmaf16(float c[4], const unsigned a[4],
                                       unsigned b0, unsigned b1) {
    asm volatile(
        "mma.sync.aligned.m16n8k16.row.col.f32.f16.f16.f32 "
        "{%0,%1,%2,%3}, {%4,%5,%6,%7}, {%8,%9}, {%0,%1,%2,%3};"
        : "+f"(c[0]), "+f"(c[1]), "+f"(c[2]), "+f"(c[3])
        : "r"(a[0]), "r"(a[1]), "r"(a[2]), "r"(a[3]), "r"(b0), "r"(b1));
}
__device__ __forceinline__ void hsplit(float v, __half& h, __half& l) {
    h = __float2half_rn(v);
    l = __float2half_rn(v - __half2float(h));
}

// ---------------- fused input split (x, Wq, Wk, Wv, Wout in one launch) ----
__global__ void __launch_bounds__(256) splitAll(
    const float4* __restrict__ x, const float4* __restrict__ Wq,
    const float4* __restrict__ Wk, const float4* __restrict__ Wv,
    const float4* __restrict__ Wout)
{
    int i = blockIdx.x * 256 + threadIdx.x;
    if (i < 1572864) {
        float4 v = x[i];
        ((__half2*)g_xh)[i * 2]     = __halves2half2(__float2half_rn(v.x), __float2half_rn(v.y));
        ((__half2*)g_xh)[i * 2 + 1] = __halves2half2(__float2half_rn(v.z), __float2half_rn(v.w));
    } else if (i < 1720320) {
        int j = i - 1572864;
        int row = j / 192, col = (j % 192) * 4;
        float4 v = Wq[j];
        __half2* d = (__half2*)(g_wqkv + (size_t)row * 3072 + col);
        d[0] = __halves2half2(__float2half_rn(v.x), __float2half_rn(v.y));
        d[1] = __halves2half2(__float2half_rn(v.z), __float2half_rn(v.w));
    } else if (i < 1867776) {
        int j = i - 1720320;
        int row = j / 192, col = (j % 192) * 4;
        float4 v = Wk[j];
        __half2* d = (__half2*)(g_wqkv + (size_t)row * 3072 + 768 + col);
        d[0] = __halves2half2(__float2half_rn(v.x), __float2half_rn(v.y));
        d[1] = __halves2half2(__float2half_rn(v.z), __float2half_rn(v.w));
    } else if (i < 2162688) {
        int j = i - 1867776;
        int row = j / 384, col = (j % 384) * 4;
        float4 v = Wv[j];
        __half2* d = (__half2*)(g_wqkv + (size_t)row * 3072 + 1536 + col);
        d[0] = __halves2half2(__float2half_rn(v.x), __float2half_rn(v.y));
        d[1] = __halves2half2(__float2half_rn(v.z), __float2half_rn(v.w));
    } else if (i < 2457600) {
        int j = i - 2162688;
        float4 v = Wout[j];
        ((__half2*)g_woh)[j * 2]     = __halves2half2(__float2half_rn(v.x), __float2half_rn(v.y));
        ((__half2*)g_woh)[j * 2 + 1] = __halves2half2(__float2half_rn(v.z), __float2half_rn(v.w));
    }
}

// ---------------------------------------------------------------------------
// Persistent GEMM with cross-tile prefetch. BM=128 BN=128 BK=32, 3 stages.
// MODE 0: fp32 rowmajor (outF).  MODE 1: QKV merged epilogue.
// ---------------------------------------------------------------------------
#define ASTR 10240          // 128 rows * 80B
#define BSTR 8704           // 32 rows * 272B

template<int MODE>
__global__ void __launch_bounds__(256, 2) gemm16(
    const __half* __restrict__ Agh, const __half* __restrict__ Bgh,
    const float* __restrict__ bias,
    __half* __restrict__ o0, __half* __restrict__ o1, __half* __restrict__ o2,
    __half* __restrict__ o3, float* __restrict__ outF,
    int K, int N, int tilesX, int nTiles)
{
    extern __shared__ char smem[];
    __half* sA = (__half*)smem;
    __half* sBh = (__half*)(smem + 3 * ASTR);

    const int tid = threadIdx.x;
    const int lane = tid & 31, warp = tid >> 5;
    const int wm = warp >> 2, wn = warp & 3;
    const int gid = lane >> 2, tig = lane & 3;

    const int aR = tid >> 1, aC = (tid & 1) * 16;
    const int bR = tid >> 3, bC = (tid & 7) * 16;
    const unsigned sAb = sptr(sA), sBhb = sptr(sBh);
    const unsigned aOff = (wm * 64 + (lane & 15)) * 80 + (lane >> 4) * 16;
    const unsigned bOff = (lane & 15) * 272 + (wn * 32 + (lane >> 4) * 8) * 2;
    const int KT = K >> 5;

    auto issueT = [&](int t, int kt, int s) {
        const int tm0 = (t / tilesX) * 128;
        const int tn0 = (t % tilesX) * 128;
        const int k0 = kt << 5;
        const __half* ga = Agh + (size_t)(tm0 + aR) * K + k0 + aC;
        unsigned sa = sAb + s * ASTR + aR * 80 + aC * 2;
        cpa16(sa, ga); cpa16(sa + 16, ga + 8);
        const __half* gb = Bgh + (size_t)(k0 + bR) * N + tn0 + bC;
        unsigned sb = sBhb + s * BSTR + bR * 272 + bC * 2;
        cpa16(sb, gb); cpa16(sb + 16, gb + 8);
        cpcommit();
    };

    if (blockIdx.x < nTiles) {
        issueT(blockIdx.x, 0, 0);
        issueT(blockIdx.x, 1, 1);
    }

    for (int tile = blockIdx.x; tile < nTiles; tile += PGRID) {
        const int m0 = (tile / tilesX) * 128;
        const int n0 = (tile % tilesX) * 128;

        float c[4][4][4];
#pragma unroll
        for (int i = 0; i < 4; i++)
#pragma unroll
            for (int j = 0; j < 4; j++)
#pragma unroll
                for (int q = 0; q < 4; q++) c[i][j][q] = 0.f;

        for (int kt = 0; kt < KT; kt++) {
            cpwait<1>();
            __syncthreads();
            const int s = kt % 3;
            const unsigned aB = sAb + s * ASTR + aOff;
            const unsigned bB = sBhb + s * BSTR + bOff;

#pragma unroll
            for (int k16 = 0; k16 < 2; k16++) {
                unsigned ah[4][4], bh[4][2], t0, t1, t2, t3;
#pragma unroll
                for (int mf = 0; mf < 4; mf++)
                    ldsm4(ah[mf], aB + mf * 1280 + k16 * 32);
#pragma unroll
                for (int nf2 = 0; nf2 < 2; nf2++) {
                    ldsm4t(t0, t1, t2, t3, bB + k16 * 4352 + nf2 * 32);
                    bh[nf2 * 2][0] = t0; bh[nf2 * 2][1] = t1;
                    bh[nf2 * 2 + 1][0] = t2; bh[nf2 * 2 + 1][1] = t3;
                }
#pragma unroll
                for (int mf = 0; mf < 4; mf++)
#pragma unroll
                    for (int nf = 0; nf < 4; nf++)
                        mmaf16(c[mf][nf], ah[mf], bh[nf][0], bh[nf][1]);
            }
            const int kn = kt + 2;
            if (kn < KT) issueT(tile, kn, kn % 3); else cpcommit();
        }

        const int nt = tile + PGRID;
        if (nt < nTiles) { issueT(nt, 0, 0); issueT(nt, 1, 1); }

#pragma unroll
        for (int mf = 0; mf < 4; mf++)
#pragma unroll
            for (int q2 = 0; q2 < 2; q2++) {
                const int row = m0 + wm * 64 + mf * 16 + gid + q2 * 8;
                const int b = row >> 9, n = row & 511;
#pragma unroll
                for (int nf = 0; nf < 4; nf++) {
                    const int col = n0 + wn * 32 + nf * 8 + tig * 2;
                    float v0 = c[mf][nf][q2 * 2 + 0];
                    float v1 = c[mf][nf][q2 * 2 + 1];
                    if (MODE == 0) {
                        *(float2*)(outF + (size_t)row * N + col) = make_float2(v0, v1);
                    } else {
                        if (col < 768) {
                            const int h = col / 96, d = col - h * 96;
                            const size_t idx = (((size_t)(b * 8 + h)) * 512 + n) * 96 + d;
                            *(__half2*)(o0 + idx) =
                                __halves2half2(__float2half_rn(v0), __float2half_rn(v1));
                        } else if (col < 1536) {
                            const int cc = col - 768;
                            const int h = cc / 96, d = cc - h * 96;
                            const size_t idx = (((size_t)(b * 8 + h)) * 512 + n) * 96 + d;
                            __half h0, h1, l0, l1;
                            hsplit(v0, h0, l0); hsplit(v1, h1, l1);
                            *(__half2*)(o1 + idx) = __halves2half2(h0, h1);
                            *(__half2*)(o2 + idx) = __halves2half2(l0, l1);
                        } else {
                            const int cc = col - 1536;
                            const int h = cc / 96, d = cc - h * 96;
                            v0 += bias[cc]; v1 += bias[cc + 1];
                            const size_t idx = (((size_t)(b * 16 + h)) * 512 + n) * 96 + d;
                            *(__half2*)(o3 + idx) =
                                __halves2half2(__float2half_rn(v0), __float2half_rn(v1));
                        }
                    }
                }
            }
    }
}

// ---------------------------------------------------------------------------
// Persistent scores with cross-tile prefetch.  Q single, K dual (2-term).
// tiles: 128 bg x 4 x 4 = 2048, KT=3.
// ---------------------------------------------------------------------------
__global__ void __launch_bounds__(256, 2) scores16(
    const float* __restrict__ eps, const float* __restrict__ sigma)
{
    extern __shared__ char smem[];
    __half* sQ  = (__half*)smem;
    __half* sKh = (__half*)(smem + 3 * ASTR);
    __half* sKl = (__half*)(smem + 6 * ASTR);

    const int tid = threadIdx.x;
    const int lane = tid & 31, warp = tid >> 5;
    const int wm = warp >> 2, wn = warp & 3;
    const int gid = lane >> 2, tig = lane & 3;

    const int aR = tid >> 1, aC = (tid & 1) * 16;
    const unsigned bQ = sptr(sQ), bKh = sptr(sKh), bKl = sptr(sKl);
    const unsigned aOff = (wm * 64 + (lane & 15)) * 80 + (lane >> 4) * 16;
    const unsigned kOff = (wn * 32 + (lane & 15)) * 80 + (lane >> 4) * 16;

    auto issueT = [&](int t, int kt, int s) {
        const int tbg = t >> 4;
        const int tsn0 = ((t >> 2) & 3) * 128, tsm0 = (t & 3) * 128;
        const __half* Qp  = g_Qh + (size_t)tbg * Nn * Dd;
        const __half* Khp = g_Kh + (size_t)tbg * Nn * Dd;
        const __half* Klp = g_Kl + (size_t)tbg * Nn * Dd;
        const int k0 = kt << 5;
        unsigned so = s * ASTR + aR * 80 + aC * 2;
        size_t go = (size_t)aR * 96 + k0 + aC;
        cpa16(bQ + so, Qp + (size_t)tsn0 * 96 + go);
        cpa16(bQ + so + 16, Qp + (size_t)tsn0 * 96 + go + 8);
        cpa16(bKh + so, Khp + (size_t)tsm0 * 96 + go);
        cpa16(bKh + so + 16, Khp + (size_t)tsm0 * 96 + go + 8);
        cpa16(bKl + so, Klp + (size_t)tsm0 * 96 + go);
        cpa16(bKl + so + 16, Klp + (size_t)tsm0 * 96 + go + 8);
        cpcommit();
    };

    if (blockIdx.x < 2048) {
        issueT(blockIdx.x, 0, 0);
        issueT(blockIdx.x, 1, 1);
    }

    for (int tile = blockIdx.x; tile < 2048; tile += PGRID) {
        const int bg = tile >> 4;
        const int sn0 = ((tile >> 2) & 3) * 128, sm0 = (tile & 3) * 128;

        float c[4][4][4];
#pragma unroll
        for (int i = 0; i < 4; i++)
#pragma unroll
            for (int j = 0; j < 4; j++)
#pragma unroll
                for (int q = 0; q < 4; q++) c[i][j][q] = 0.f;

        for (int kt = 0; kt < 3; kt++) {
            cpwait<1>();
            __syncthreads();
            const unsigned aB = bQ + kt * ASTR + aOff;
            const unsigned kH = bKh + kt * ASTR + kOff;
            const unsigned kL = bKl + kt * ASTR + kOff;

#pragma unroll
            for (int k16 = 0; k16 < 2; k16++) {
                unsigned ah[4][4], f[4], bh[4][2], bl[4][2];
#pragma unroll
                for (int mf = 0; mf < 4; mf++)
                    ldsm4(ah[mf], aB + mf * 1280 + k16 * 32);
#pragma unroll
                for (int nf2 = 0; nf2 < 2; nf2++) {
                    ldsm4(f, kH + nf2 * 1280 + k16 * 32);
                    bh[nf2 * 2][0] = f[0]; bh[nf2 * 2][1] = f[2];
                    bh[nf2 * 2 + 1][0] = f[1]; bh[nf2 * 2 + 1][1] = f[3];
                    ldsm4(f, kL + nf2 * 1280 + k16 * 32);
                    bl[nf2 * 2][0] = f[0]; bl[nf2 * 2][1] = f[2];
                    bl[nf2 * 2 + 1][0] = f[1]; bl[nf2 * 2 + 1][1] = f[3];
                }
#pragma unroll
                for (int mf = 0; mf < 4; mf++)
#pragma unroll
                    for (int nf = 0; nf < 4; nf++) {
                        mmaf16(c[mf][nf], ah[mf], bh[nf][0], bh[nf][1]);
                        mmaf16(c[mf][nf], ah[mf], bl[nf][0], bl[nf][1]);
                    }
            }
            const int kn = kt + 2;
            if (kn < 3) issueT(tile, kn, kn); else cpcommit();
        }

        const int nt = tile + PGRID;
        if (nt < 2048) { issueT(nt, 0, 0); issueT(nt, 1, 1); }

        float s2 = sigma[bg & 7];
        s2 = s2 * s2;
#pragma unroll
        for (int mf = 0; mf < 4; mf++)
#pragma unroll
            for (int q2 = 0; q2 < 2; q2++) {
                const int n = sn0 + wm * 64 + mf * 16 + gid + q2 * 8;
#pragma unroll
                for (int nf = 0; nf < 4; nf++) {
                    const int m = sm0 + wn * 32 + nf * 8 + tig * 2;
                    const size_t idx = ((size_t)bg * Nn + n) * Nn + m;
                    float2 ev = *(const float2*)(eps + idx);
                    *(__half2*)(g_S + idx) = __halves2half2(
                        __float2half_rn(c[mf][nf][q2 * 2 + 0] + s2 * ev.x),
                        __float2half_rn(c[mf][nf][q2 * 2 + 1] + s2 * ev.y));
                }
            }
    }
}

// ---------------------------------------------------------------------------
// Mix + mish + softmax (max-free), transposed: warp = l, lane x16 = m.
// 256-thread blocks, grid (8192, 2): l = blockIdx.y*8 + warp.
// Warps are independent (softmax sum is intra-warp) -> smaller blocks lift
// occupancy 46% -> ~90% at regs=64.  No smem, no syncthreads.
// ---------------------------------------------------------------------------
__global__ void __launch_bounds__(256, 4) mix_softmax_kernel(
    const float* __restrict__ encoding_bias, const float* __restrict__ p)
{
    const int bn = blockIdx.x;
    const int b = bn >> 9, n = bn & 511;
    const int tid = threadIdx.x;
    const int lane = tid & 31, l = blockIdx.y * 8 + (tid >> 5);

    float pr[8];
#pragma unroll
    for (int g = 0; g < 8; g++) pr[g] = __ldg(p + g * 16 + l);

    const float scale = 0.03608439182435161f;
    const __half* Sbase = g_S + (((size_t)(b * 8)) * 512 + n) * 512;
    const float* ebase = encoding_bias + ((size_t)bn) * 512;

    float vals[16];
    float psum = 0.f;

#pragma unroll
    for (int ib = 0; ib < 2; ib++) {
        const int m8 = (lane + ib * 32) * 8;

        float tacc[8];
#pragma unroll
        for (int j = 0; j < 8; j++) tacc[j] = 0.f;

#pragma unroll
        for (int g = 0; g < 8; g++) {
            uint4 sv = *(const uint4*)(Sbase + (size_t)g * (512 * 512) + m8);
            const __half2* h2 = (const __half2*)&sv;
#pragma unroll
            for (int j2 = 0; j2 < 4; j2++) {
                float2 f = __half22float2(h2[j2]);
                tacc[j2 * 2 + 0] = fmaf(f.x, pr[g], tacc[j2 * 2 + 0]);
                tacc[j2 * 2 + 1] = fmaf(f.y, pr[g], tacc[j2 * 2 + 1]);
            }
        }

        float4 bv0 = *(const float4*)(ebase + m8);
        float4 bv1 = *(const float4*)(ebase + m8 + 4);
        float bb[8] = {bv0.x, bv0.y, bv0.z, bv0.w, bv1.x, bv1.y, bv1.z, bv1.w};

#pragma unroll
        for (int j = 0; j < 8; j++) {
            float t = tacc[j];
            float e = __expf(fminf(t, 15.f));
            float num = e * (e + 2.f);
            float mish = t * __fdividef(num, num + 2.f);
            float v = __expf(mish * scale + bb[j]);   // logits bounded ~|8|
            vals[ib * 8 + j] = v;
            psum += v;
        }
    }

#pragma unroll
    for (int o = 16; o > 0; o >>= 1)
        psum += __shfl_xor_sync(0xffffffffu, psum, o);
    const float rinv = __fdividef(1.f, psum);

    __half* Abase = g_Ah + (((size_t)(b * 16 + l)) * 512 + n) * 512;
#pragma unroll
    for (int ib = 0; ib < 2; ib++) {
        const int m8 = (lane + ib * 32) * 8;
        uint4 pk;
        unsigned* pku = (unsigned*)&pk;
#pragma unroll
        for (int j2 = 0; j2 < 4; j2++) {
            __half2 h = __halves2half2(
                __float2half_rn(vals[ib * 8 + j2 * 2 + 0] * rinv),
                __float2half_rn(vals[ib * 8 + j2 * 2 + 1] * rinv));
            pku[j2] = *(unsigned*)&h;
        }
        *(uint4*)(Abase + m8) = pk;
    }
}

// ---------------------------------------------------------------------------
// Persistent outv with cross-tile prefetch.  tiles = 4 x 256 = 1024, KT=16.
// ---------------------------------------------------------------------------
#define VSTR 6656          // 32 rows * 208B

__global__ void __launch_bounds__(256, 2) outv16()
{
    extern __shared__ char smem[];
    __half* sA = (__half*)smem;
    __half* sVh = (__half*)(smem + 3 * ASTR);

    const int tid = threadIdx.x;
    const int lane = tid & 31, warp = tid >> 5;
    const int wm = warp >> 2, wn = warp & 3;
    const int gid = lane >> 2, tig = lane & 3;

    const int aR = tid >> 1, aC = (tid & 1) * 16;
    const int vR = tid / 6, vC = (tid % 6) * 16;
    const bool vAct = tid < 192;
    const unsigned bA = sptr(sA), bVh = sptr(sVh);
    const unsigned aOff = (wm * 64 + (lane & 15)) * 80 + (lane >> 4) * 16;
    const unsigned vOff = (lane & 15) * 208 + (wn * 24 + (lane >> 4) * 8) * 2;
    const unsigned vOff2 = (lane & 15) * 208 + (wn * 24 + 16) * 2;

    auto issueT = [&](int t, int kt, int s) {
        const int tbl = t >> 2;
        const int tn0 = (t & 3) * 128;
        const __half* Ap = g_Ah + (size_t)tbl * Nn * Nn;
        const __half* Vhp = g_Vh + (size_t)tbl * Nn * Dd;
        const int k0 = kt << 5;
        unsigned sa = bA + s * ASTR + aR * 80 + aC * 2;
        const __half* ga = Ap + (size_t)(tn0 + aR) * 512 + k0 + aC;
        cpa16(sa, ga); cpa16(sa + 16, ga + 8);
        if (vAct) {
            unsigned sv = bVh + s * VSTR + vR * 208 + vC * 2;
            const __half* gv = Vhp + (size_t)(k0 + vR) * 96 + vC;
            cpa16(sv, gv); cpa16(sv + 16, gv + 8);
        }
        cpcommit();
    };

    if (blockIdx.x < 1024) {
        issueT(blockIdx.x, 0, 0);
        issueT(blockIdx.x, 1, 1);
    }

    for (int tile = blockIdx.x; tile < 1024; tile += PGRID) {
        const int bl = tile >> 2;
        const int n0 = (tile & 3) * 128;

        float c[4][3][4];
#pragma unroll
        for (int i = 0; i < 4; i++)
#pragma unroll
            for (int j = 0; j < 3; j++)
#pragma unroll
                for (int q = 0; q < 4; q++) c[i][j][q] = 0.f;

        for (int kt = 0; kt < 16; kt++) {
            cpwait<1>();
            __syncthreads();
            const int s = kt % 3;
            const unsigned aB = bA + s * ASTR + aOff;
            const unsigned vH = bVh + s * VSTR;

#pragma unroll
            for (int k16 = 0; k16 < 2; k16++) {
                unsigned ah[4][4], bh[3][2], t0, t1, t2, t3;
#pragma unroll
                for (int mf = 0; mf < 4; mf++)
                    ldsm4(ah[mf], aB + mf * 1280 + k16 * 32);
                ldsm4t(t0, t1, t2, t3, vH + vOff + k16 * 3328);
                bh[0][0] = t0; bh[0][1] = t1; bh[1][0] = t2; bh[1][1] = t3;
                ldsm2t(t0, t1, vH + vOff2 + k16 * 3328);
                bh[2][0] = t0; bh[2][1] = t1;

#pragma unroll
                for (int mf = 0; mf < 4; mf++)
#pragma unroll
                    for (int nf = 0; nf < 3; nf++)
                        mmaf16(c[mf][nf], ah[mf], bh[nf][0], bh[nf][1]);
            }
            const int kn = kt + 2;
            if (kn < 16) issueT(tile, kn, kn % 3); else cpcommit();
        }

        // KT=16: last chunk sat in stage 0 -> guard before reusing stages 0,1
        __syncthreads();
        const int nt = tile + PGRID;
        if (nt < 1024) { issueT(nt, 0, 0); issueT(nt, 1, 1); }

        const int b = bl >> 4, l = bl & 15;
#pragma unroll
        for (int mf = 0; mf < 4; mf++)
#pragma unroll
            for (int q2 = 0; q2 < 2; q2++) {
                const int n = n0 + wm * 64 + mf * 16 + gid + q2 * 8;
#pragma unroll
                for (int nf = 0; nf < 3; nf++) {
                    const int d = wn * 24 + nf * 8 + tig * 2;
                    const size_t idx = ((size_t)(b * 512 + n)) * 1536 + l * 96 + d;
                    *(__half2*)(g_Oh + idx) =
                        __halves2half2(__float2half_rn(c[mf][nf][q2 * 2 + 0]),
                                       __float2half_rn(c[mf][nf][q2 * 2 + 1]));
                }
            }
    }
}

// ---------------------------------------------------------------------------
extern "C" void kernel_launch(void* const* d_in, const int* in_sizes, int n_in,
                              void* d_out, int out_size)
{
    const float* x     = (const float*)d_in[0];
    const float* ebias = (const float*)d_in[1];
    const float* eps   = (const float*)d_in[2];
    const float* Wq    = (const float*)d_in[3];
    const float* Wk    = (const float*)d_in[4];
    const float* Wv    = (const float*)d_in[5];
    const float* bv    = (const float*)d_in[6];
    const float* sigma = (const float*)d_in[7];
    const float* p     = (const float*)d_in[8];
    const float* Wout  = (const float*)d_in[9];
    float* out = (float*)d_out;

    __half *xh, *wqkv, *woh, *qh, *kh, *kl, *vh, *oh;
    cudaGetSymbolAddress((void**)&xh,   g_xh);
    cudaGetSymbolAddress((void**)&wqkv, g_wqkv);
    cudaGetSymbolAddress((void**)&woh,  g_woh);
    cudaGetSymbolAddress((void**)&qh,   g_Qh);
    cudaGetSymbolAddress((void**)&kh,   g_Kh);
    cudaGetSymbolAddress((void**)&kl,   g_Kl);
    cudaGetSymbolAddress((void**)&vh,   g_Vh);
    cudaGetSymbolAddress((void**)&oh,   g_Oh);

    const int SM_1 = 3 * ASTR + 3 * BSTR;   // 56832
    const int SM_S = 9 * ASTR;              // 92160
    const int SM_O = 3 * ASTR + 3 * VSTR;   // 50688

    cudaFuncSetAttribute(gemm16<1>,
        cudaFuncAttributeMaxDynamicSharedMemorySize, SM_1);
    cudaFuncSetAttribute(gemm16<0>,
        cudaFuncAttributeMaxDynamicSharedMemorySize, SM_1);
    cudaFuncSetAttribute(scores16,
        cudaFuncAttributeMaxDynamicSharedMemorySize, SM_S);
    cudaFuncSetAttribute(outv16,
        cudaFuncAttributeMaxDynamicSharedMemorySize, SM_O);

    // fused input splits (x, Wq, Wk, Wv, Wout)
    splitAll<<<9600, 256>>>((const float4*)x, (const float4*)Wq,
                            (const float4*)Wk, (const float4*)Wv,
                            (const float4*)Wout);

    // merged Q+K+V projection: persistent, tiles 24x64
    gemm16<1><<<PGRID, 256, SM_1>>>(
        xh, wqkv, bv, qh, kh, kl, vh, nullptr, 768, 3072, 24, 1536);

    // scores: persistent, 2-term + sigma^2*eps -> fp16 S
    scores16<<<PGRID, 256, SM_S>>>(eps, sigma);

    // mix + mish + softmax (max-free, transposed, 256-thr blocks) -> A fp16
    mix_softmax_kernel<<<dim3(Bb * Nn, 2), 256>>>(ebias, p);

    // O = A @ V: persistent
    outv16<<<PGRID, 256, SM_O>>>();

    // out proj: persistent, tiles 6x64 -> fp32 d_out
    gemm16<0><<<PGRID, 256, SM_1>>>(
        oh, woh, nullptr, nullptr, nullptr, nullptr, nullptr, out, 1536, 768, 6, 384);
}